// round 2
// baseline (speedup 1.0000x reference)
#include <cuda_runtime.h>
#include <cstdint>

#define N_NODES 50000
#define N_EDGES 1600000
#define DIM 128
#define HID2 256
#define BN_EPS 1e-5f

// ---------------- scratch (static device globals; no runtime alloc) ----------------
__device__ float g_agg[(size_t)N_NODES * DIM];      // aggregation buffer (layer1 then layer2)
__device__ float g_hid[(size_t)N_NODES * HID2];     // MLP hidden (256)
__device__ float g_pre[(size_t)N_NODES * DIM];      // pre-BN layer1 output
__device__ float g_h1 [(size_t)N_NODES * DIM];      // post-BN layer1 output
__device__ float g_out2[(size_t)N_NODES * 2];       // pre-BN layer2 output

__device__ __align__(16) float g_sum1[DIM];
__device__ __align__(16) float g_sq1[DIM];
__device__ __align__(16) float g_scale1[DIM];
__device__ __align__(16) float g_shift1[DIM];
__device__ float g_bn2[4];    // sum0,sum1,sq0,sq1
__device__ float g_ss2[4];    // scale0,scale1,shift0,shift1

// ---------------- init: agg = x, zero stats ----------------
__global__ void k_init(const float* __restrict__ x) {
    int i = blockIdx.x * blockDim.x + threadIdx.x;       // float4 index
    const int n4 = N_NODES * (DIM / 4);
    if (i < n4) {
        ((float4*)g_agg)[i] = ((const float4*)x)[i];
    }
    if (i < DIM) { g_sum1[i] = 0.f; g_sq1[i] = 0.f; }
    if (i < 4)   { g_bn2[i] = 0.f; }
}

// ---------------- scatter: agg[dst] += feat[src] * w, one warp per edge ----------------
__global__ void __launch_bounds__(256) k_scatter(const int* __restrict__ src,
                                                 const int* __restrict__ dst,
                                                 const float* __restrict__ wgt,
                                                 const float* __restrict__ feat,
                                                 float* __restrict__ agg,
                                                 int nEdges) {
    int lane = threadIdx.x & 31;
    int warp = (blockIdx.x * blockDim.x + threadIdx.x) >> 5;
    int nwarps = (gridDim.x * blockDim.x) >> 5;
    for (int e = warp; e < nEdges; e += nwarps) {
        int s = src[e];
        int d = dst[e];
        float w = wgt[e];
        float4 v = ((const float4*)(feat + (size_t)s * DIM))[lane];
        v.x *= w; v.y *= w; v.z *= w; v.w *= w;
        float* p = agg + (size_t)d * DIM + lane * 4;
        asm volatile("red.global.add.v4.f32 [%0], {%1, %2, %3, %4};"
                     :: "l"(p), "f"(v.x), "f"(v.y), "f"(v.z), "f"(v.w)
                     : "memory");
    }
}

// ---------------- tiled fp32 GEMM: C = relu(A @ B + bias) ----------------
// A: M x K row-major, B: K x N row-major, C: M x N. BM=BN=64, BK=16, 256 threads, 4x4/thread.
__global__ void __launch_bounds__(256) k_gemm(const float* __restrict__ A,
                                              const float* __restrict__ B,
                                              const float* __restrict__ bias,
                                              float* __restrict__ C,
                                              int M, int N, int K) {
    __shared__ float As[16][64];
    __shared__ float Bs[16][64];
    const int bm = blockIdx.x * 64;
    const int bn = blockIdx.y * 64;
    const int t = threadIdx.x;
    const int tx = t & 15, ty = t >> 4;

    const int arow = t >> 2;            // 0..63
    const int acol = (t & 3) * 4;       // 0,4,8,12
    const int brow = t >> 4;            // 0..15
    const int bcol = (t & 15) * 4;      // 0..60

    float acc[4][4] = {};

    for (int k0 = 0; k0 < K; k0 += 16) {
        float4 av = make_float4(0.f, 0.f, 0.f, 0.f);
        int gr = bm + arow;
        if (gr < M) av = *(const float4*)(A + (size_t)gr * K + k0 + acol);
        As[acol + 0][arow] = av.x;
        As[acol + 1][arow] = av.y;
        As[acol + 2][arow] = av.z;
        As[acol + 3][arow] = av.w;
        float4 bv = *(const float4*)(B + (size_t)(k0 + brow) * N + bn + bcol);
        *(float4*)&Bs[brow][bcol] = bv;
        __syncthreads();
#pragma unroll
        for (int k = 0; k < 16; k++) {
            float a[4], b[4];
#pragma unroll
            for (int i = 0; i < 4; i++) a[i] = As[k][ty * 4 + i];
#pragma unroll
            for (int j = 0; j < 4; j++) b[j] = Bs[k][tx * 4 + j];
#pragma unroll
            for (int i = 0; i < 4; i++)
#pragma unroll
                for (int j = 0; j < 4; j++) acc[i][j] = fmaf(a[i], b[j], acc[i][j]);
        }
        __syncthreads();
    }

    float4 bv = *(const float4*)(bias + bn + tx * 4);
    float bb[4] = {bv.x, bv.y, bv.z, bv.w};
#pragma unroll
    for (int i = 0; i < 4; i++) {
        int row = bm + ty * 4 + i;
        if (row < M) {
            float4 o;
            o.x = fmaxf(acc[i][0] + bb[0], 0.f);
            o.y = fmaxf(acc[i][1] + bb[1], 0.f);
            o.z = fmaxf(acc[i][2] + bb[2], 0.f);
            o.w = fmaxf(acc[i][3] + bb[3], 0.f);
            *(float4*)(C + (size_t)row * N + bn + tx * 4) = o;
        }
    }
}

// ---------------- BN1 column reduce (sum, sumsq) ----------------
__global__ void __launch_bounds__(128) k_bn1_reduce(const float* __restrict__ pre) {
    int c = threadIdx.x;   // 0..127
    float s = 0.f, q = 0.f;
    for (int r = blockIdx.x; r < N_NODES; r += gridDim.x) {
        float v = pre[(size_t)r * DIM + c];
        s += v;
        q += v * v;
    }
    atomicAdd(&g_sum1[c], s);
    atomicAdd(&g_sq1[c], q);
}

__global__ void k_bn1_fin(const float* __restrict__ gamma, const float* __restrict__ beta) {
    int c = threadIdx.x;
    if (c >= DIM) return;
    const float invN = 1.0f / (float)N_NODES;
    float mean = g_sum1[c] * invN;
    float var  = g_sq1[c] * invN - mean * mean;
    float sc   = gamma[c] * rsqrtf(var + BN_EPS);
    g_scale1[c] = sc;
    g_shift1[c] = beta[c] - mean * sc;
}

// normalize + write h1 AND init agg for layer 2
__global__ void k_bn1_norm(const float* __restrict__ pre) {
    int i = blockIdx.x * blockDim.x + threadIdx.x;   // float4 index
    const int n4 = N_NODES * (DIM / 4);
    if (i >= n4) return;
    int c4 = i & 31;
    float4 v  = ((const float4*)pre)[i];
    float4 sc = ((const float4*)g_scale1)[c4];
    float4 sh = ((const float4*)g_shift1)[c4];
    float4 o;
    o.x = fmaf(v.x, sc.x, sh.x);
    o.y = fmaf(v.y, sc.y, sh.y);
    o.z = fmaf(v.z, sc.z, sh.z);
    o.w = fmaf(v.w, sc.w, sh.w);
    ((float4*)g_h1)[i] = o;
    ((float4*)g_agg)[i] = o;
}

// ---------------- final GEMM 256->2 fused with relu + BN2 stats ----------------
__global__ void __launch_bounds__(256) k_gemm2b(const float* __restrict__ Hid,
                                                const float* __restrict__ W,   // 256x2 row-major
                                                const float* __restrict__ bias) {
    __shared__ float w0[HID2], w1[HID2];
    __shared__ float red[8][4];
    int t = threadIdx.x;
    w0[t] = W[t * 2 + 0];
    w1[t] = W[t * 2 + 1];
    __syncthreads();

    int lane = t & 31, wid = t >> 5;
    int row = blockIdx.x * 8 + wid;
    float s0 = 0.f, s1 = 0.f, q0 = 0.f, q1 = 0.f;
    if (row < N_NODES) {
        const float* h = Hid + (size_t)row * HID2;
        float a0 = 0.f, a1 = 0.f;
#pragma unroll
        for (int i = 0; i < 8; i++) {
            float v = h[lane + 32 * i];
            a0 = fmaf(v, w0[lane + 32 * i], a0);
            a1 = fmaf(v, w1[lane + 32 * i], a1);
        }
#pragma unroll
        for (int o = 16; o; o >>= 1) {
            a0 += __shfl_xor_sync(0xffffffffu, a0, o);
            a1 += __shfl_xor_sync(0xffffffffu, a1, o);
        }
        if (lane == 0) {
            a0 = fmaxf(a0 + bias[0], 0.f);
            a1 = fmaxf(a1 + bias[1], 0.f);
            g_out2[(size_t)row * 2 + 0] = a0;
            g_out2[(size_t)row * 2 + 1] = a1;
            s0 = a0; s1 = a1; q0 = a0 * a0; q1 = a1 * a1;
        }
    }
    if (lane == 0) { red[wid][0] = s0; red[wid][1] = s1; red[wid][2] = q0; red[wid][3] = q1; }
    __syncthreads();
    if (t < 4) {
        float acc = 0.f;
#pragma unroll
        for (int wI = 0; wI < 8; wI++) acc += red[wI][t];
        atomicAdd(&g_bn2[t], acc);
    }
}

__global__ void k_bn2_fin(const float* __restrict__ gamma2, const float* __restrict__ beta2) {
    int c = threadIdx.x;
    if (c >= 2) return;
    const float invN = 1.0f / (float)N_NODES;
    float mean = g_bn2[c] * invN;
    float var  = g_bn2[2 + c] * invN - mean * mean;
    float sc   = gamma2[c] * rsqrtf(var + BN_EPS);
    g_ss2[c]     = sc;
    g_ss2[2 + c] = beta2[c] - mean * sc;
}

__global__ void k_bn2_norm(float* __restrict__ out) {
    int r = blockIdx.x * blockDim.x + threadIdx.x;
    if (r >= N_NODES) return;
    float2 v = ((const float2*)g_out2)[r];
    float2 o;
    o.x = fmaf(v.x, g_ss2[0], g_ss2[2]);
    o.y = fmaf(v.y, g_ss2[1], g_ss2[3]);
    ((float2*)out)[r] = o;
}

// ---------------- launch ----------------
extern "C" void kernel_launch(void* const* d_in, const int* in_sizes, int n_in,
                              void* d_out, int out_size) {
    const float* x      = (const float*)d_in[0];
    const int*   eidx   = (const int*)d_in[1];
    const float* ew     = (const float*)d_in[3];
    const float* W1a    = (const float*)d_in[4];
    const float* b1a    = (const float*)d_in[5];
    const float* W1b    = (const float*)d_in[6];
    const float* b1b    = (const float*)d_in[7];
    const float* gamma1 = (const float*)d_in[8];
    const float* beta1  = (const float*)d_in[9];
    const float* W2a    = (const float*)d_in[10];
    const float* b2a    = (const float*)d_in[11];
    const float* W2b    = (const float*)d_in[12];
    const float* b2b    = (const float*)d_in[13];
    const float* gamma2 = (const float*)d_in[14];
    const float* beta2  = (const float*)d_in[15];

    const int nEdges = in_sizes[1] / 2;
    const int* src = eidx;
    const int* dst = eidx + nEdges;

    float *agg, *hid, *pre, *h1;
    cudaGetSymbolAddress((void**)&agg, g_agg);
    cudaGetSymbolAddress((void**)&hid, g_hid);
    cudaGetSymbolAddress((void**)&pre, g_pre);
    cudaGetSymbolAddress((void**)&h1,  g_h1);

    const int n4 = N_NODES * (DIM / 4);
    const int initBlocks = (n4 + 255) / 256;
    const int gemmMB = (N_NODES + 63) / 64;   // 782

    // ---- layer 1 ----
    k_init<<<initBlocks, 256>>>(x);
    k_scatter<<<2048, 256>>>(src, dst, ew, x, agg, nEdges);
    {
        dim3 g(gemmMB, 4);
        k_gemm<<<g, 256>>>(agg, W1a, b1a, hid, N_NODES, HID2, DIM);
    }
    {
        dim3 g(gemmMB, 2);
        k_gemm<<<g, 256>>>(hid, W1b, b1b, pre, N_NODES, DIM, HID2);
    }
    k_bn1_reduce<<<512, 128>>>(pre);
    k_bn1_fin<<<1, 128>>>(gamma1, beta1);
    k_bn1_norm<<<initBlocks, 256>>>(pre);

    // ---- layer 2 ----
    k_scatter<<<2048, 256>>>(src, dst, ew, h1, agg, nEdges);
    {
        dim3 g(gemmMB, 4);
        k_gemm<<<g, 256>>>(agg, W2a, b2a, hid, N_NODES, HID2, DIM);
    }
    k_gemm2b<<<(N_NODES + 7) / 8, 256>>>(hid, W2b, b2b);
    k_bn2_fin<<<1, 32>>>(gamma2, beta2);
    k_bn2_norm<<<(N_NODES + 255) / 256, 256>>>((float*)d_out);
}

// round 3
// speedup vs baseline: 1.0708x; 1.0708x over previous
#include <cuda_runtime.h>
#include <cstdint>

#define N_NODES 50000
#define N_EDGES 1600000
#define DIM 128
#define HID2 256
#define BN_EPS 1e-5f

// ---------------- scratch (static device globals; no runtime alloc) ----------------
__device__ float g_agg[(size_t)N_NODES * DIM];      // aggregation buffer (layer1 then layer2)
__device__ float g_hid[(size_t)N_NODES * HID2];     // MLP hidden (256)
__device__ float g_pre[(size_t)N_NODES * DIM];      // pre-BN layer1 output
__device__ float g_h1 [(size_t)N_NODES * DIM];      // post-BN layer1 output
__device__ float g_out2[(size_t)N_NODES * 2];       // pre-BN layer2 output

__device__ __align__(16) float g_sum1[DIM];
__device__ __align__(16) float g_sq1[DIM];
__device__ __align__(16) float g_scale1[DIM];
__device__ __align__(16) float g_shift1[DIM];
__device__ float g_bn2[4];    // sum0,sum1,sq0,sq1
__device__ float g_ss2[4];    // scale0,scale1,shift0,shift1

// ---------------- f32x2 packed-FMA helpers (FFMA2: 2x fp32 rate, PTX-only) ----------------
__device__ __forceinline__ unsigned long long dup_f32x2(float x) {
    unsigned long long r;
    asm("mov.b64 %0, {%1, %1};" : "=l"(r) : "f"(x));
    return r;
}
__device__ __forceinline__ void ffma2(unsigned long long& d, unsigned long long a, unsigned long long b) {
    asm("fma.rn.f32x2 %0, %1, %2, %0;" : "+l"(d) : "l"(a), "l"(b));
}
__device__ __forceinline__ float2 unpack_f32x2(unsigned long long p) {
    float lo, hi;
    asm("mov.b64 {%0, %1}, %2;" : "=f"(lo), "=f"(hi) : "l"(p));
    return make_float2(lo, hi);
}

// ---------------- init: agg = x, zero stats ----------------
__global__ void k_init(const float* __restrict__ x) {
    int i = blockIdx.x * blockDim.x + threadIdx.x;       // float4 index
    const int n4 = N_NODES * (DIM / 4);
    if (i < n4) {
        ((float4*)g_agg)[i] = ((const float4*)x)[i];
    }
    if (i < DIM) { g_sum1[i] = 0.f; g_sq1[i] = 0.f; }
    if (i < 4)   { g_bn2[i] = 0.f; }
}

// ---------------- scatter: agg[dst] += feat[src] * w, one warp per edge ----------------
__global__ void __launch_bounds__(256) k_scatter(const int* __restrict__ src,
                                                 const int* __restrict__ dst,
                                                 const float* __restrict__ wgt,
                                                 const float* __restrict__ feat,
                                                 float* __restrict__ agg,
                                                 int nEdges) {
    int lane = threadIdx.x & 31;
    int warp = (blockIdx.x * blockDim.x + threadIdx.x) >> 5;
    int nwarps = (gridDim.x * blockDim.x) >> 5;
    for (int e = warp; e < nEdges; e += nwarps) {
        int s = src[e];
        int d = dst[e];
        float w = wgt[e];
        float4 v = ((const float4*)(feat + (size_t)s * DIM))[lane];
        v.x *= w; v.y *= w; v.z *= w; v.w *= w;
        float* p = agg + (size_t)d * DIM + lane * 4;
        asm volatile("red.global.add.v4.f32 [%0], {%1, %2, %3, %4};"
                     :: "l"(p), "f"(v.x), "f"(v.y), "f"(v.z), "f"(v.w)
                     : "memory");
    }
}

// ---------------- tiled fp32 GEMM: C = relu(A @ B + bias) ----------------
// BM=BN=128, BK=16, 256 threads, 8x8 per thread, FFMA2 packed math.
// A: M x K row-major, B: K x N row-major (N multiple of 128, K multiple of 16).
__global__ void __launch_bounds__(256, 2) k_gemm(const float* __restrict__ A,
                                                 const float* __restrict__ B,
                                                 const float* __restrict__ bias,
                                                 float* __restrict__ C,
                                                 int M, int N, int K) {
    __shared__ float As[16][128];   // As[k][m]
    __shared__ float Bs[16][128];   // Bs[k][n]

    const int bm = blockIdx.x * 128;
    const int bn = blockIdx.y * 128;
    const int t = threadIdx.x;
    const int tx = t & 15;          // N-dir: 8 cols at tx*8
    const int ty = t >> 4;          // M-dir: 8 rows at ty*8

    // loader indices
    const int arow = t & 127;            // 0..127 (consecutive within warp -> conflict-free STS)
    const int acol = (t >> 7) * 8;       // 0 or 8
    const int brow = t >> 4;             // 0..15
    const int bcol = (t & 15) * 8;       // 0..120

    const float* Aptr = A + (size_t)(bm + arow) * K + acol;
    const bool arow_ok = (bm + arow) < M;

    float4 aR0, aR1, bR0, bR1;
    // prefetch tile 0
    if (arow_ok) {
        aR0 = *(const float4*)(Aptr + 0);
        aR1 = *(const float4*)(Aptr + 4);
    } else {
        aR0 = aR1 = make_float4(0.f, 0.f, 0.f, 0.f);
    }
    bR0 = *(const float4*)(B + (size_t)brow * N + bn + bcol);
    bR1 = *(const float4*)(B + (size_t)brow * N + bn + bcol + 4);

    unsigned long long acc[8][4] = {};

    const int ntiles = K >> 4;
    for (int tile = 0; tile < ntiles; tile++) {
        __syncthreads();
        // store prefetched regs -> smem (A transposed)
        As[acol + 0][arow] = aR0.x;
        As[acol + 1][arow] = aR0.y;
        As[acol + 2][arow] = aR0.z;
        As[acol + 3][arow] = aR0.w;
        As[acol + 4][arow] = aR1.x;
        As[acol + 5][arow] = aR1.y;
        As[acol + 6][arow] = aR1.z;
        As[acol + 7][arow] = aR1.w;
        *(float4*)&Bs[brow][bcol]     = bR0;
        *(float4*)&Bs[brow][bcol + 4] = bR1;
        __syncthreads();

        if (tile + 1 < ntiles) {
            int k0 = (tile + 1) * 16;
            if (arow_ok) {
                aR0 = *(const float4*)(Aptr + k0 + 0);
                aR1 = *(const float4*)(Aptr + k0 + 4);
            }
            bR0 = *(const float4*)(B + (size_t)(k0 + brow) * N + bn + bcol);
            bR1 = *(const float4*)(B + (size_t)(k0 + brow) * N + bn + bcol + 4);
        }

#pragma unroll
        for (int k = 0; k < 16; k++) {
            float4 a0 = *(const float4*)&As[k][ty * 8];       // broadcast across tx
            float4 a1 = *(const float4*)&As[k][ty * 8 + 4];
            unsigned long long ap[8];
            ap[0] = dup_f32x2(a0.x); ap[1] = dup_f32x2(a0.y);
            ap[2] = dup_f32x2(a0.z); ap[3] = dup_f32x2(a0.w);
            ap[4] = dup_f32x2(a1.x); ap[5] = dup_f32x2(a1.y);
            ap[6] = dup_f32x2(a1.z); ap[7] = dup_f32x2(a1.w);
            const unsigned long long* bsrc = (const unsigned long long*)&Bs[k][tx * 8];
            unsigned long long bp0 = bsrc[0], bp1 = bsrc[1], bp2 = bsrc[2], bp3 = bsrc[3];
#pragma unroll
            for (int i = 0; i < 8; i++) {
                ffma2(acc[i][0], ap[i], bp0);
                ffma2(acc[i][1], ap[i], bp1);
                ffma2(acc[i][2], ap[i], bp2);
                ffma2(acc[i][3], ap[i], bp3);
            }
        }
    }

    // epilogue: bias + relu + store
    float4 bv0 = *(const float4*)(bias + bn + tx * 8);
    float4 bv1 = *(const float4*)(bias + bn + tx * 8 + 4);
    float bb[8] = {bv0.x, bv0.y, bv0.z, bv0.w, bv1.x, bv1.y, bv1.z, bv1.w};
#pragma unroll
    for (int i = 0; i < 8; i++) {
        int row = bm + ty * 8 + i;
        if (row < M) {
            float o[8];
#pragma unroll
            for (int j = 0; j < 4; j++) {
                float2 v = unpack_f32x2(acc[i][j]);
                o[2 * j]     = fmaxf(v.x + bb[2 * j], 0.f);
                o[2 * j + 1] = fmaxf(v.y + bb[2 * j + 1], 0.f);
            }
            float* cp = C + (size_t)row * N + bn + tx * 8;
            *(float4*)(cp)     = make_float4(o[0], o[1], o[2], o[3]);
            *(float4*)(cp + 4) = make_float4(o[4], o[5], o[6], o[7]);
        }
    }
}

// ---------------- BN1 column reduce (sum, sumsq) ----------------
__global__ void __launch_bounds__(128) k_bn1_reduce(const float* __restrict__ pre) {
    int c = threadIdx.x;   // 0..127
    float s = 0.f, q = 0.f;
    for (int r = blockIdx.x; r < N_NODES; r += gridDim.x) {
        float v = pre[(size_t)r * DIM + c];
        s += v;
        q += v * v;
    }
    atomicAdd(&g_sum1[c], s);
    atomicAdd(&g_sq1[c], q);
}

__global__ void k_bn1_fin(const float* __restrict__ gamma, const float* __restrict__ beta) {
    int c = threadIdx.x;
    if (c >= DIM) return;
    const float invN = 1.0f / (float)N_NODES;
    float mean = g_sum1[c] * invN;
    float var  = g_sq1[c] * invN - mean * mean;
    float sc   = gamma[c] * rsqrtf(var + BN_EPS);
    g_scale1[c] = sc;
    g_shift1[c] = beta[c] - mean * sc;
}

// normalize + write h1 AND init agg for layer 2
__global__ void k_bn1_norm(const float* __restrict__ pre) {
    int i = blockIdx.x * blockDim.x + threadIdx.x;   // float4 index
    const int n4 = N_NODES * (DIM / 4);
    if (i >= n4) return;
    int c4 = i & 31;
    float4 v  = ((const float4*)pre)[i];
    float4 sc = ((const float4*)g_scale1)[c4];
    float4 sh = ((const float4*)g_shift1)[c4];
    float4 o;
    o.x = fmaf(v.x, sc.x, sh.x);
    o.y = fmaf(v.y, sc.y, sh.y);
    o.z = fmaf(v.z, sc.z, sh.z);
    o.w = fmaf(v.w, sc.w, sh.w);
    ((float4*)g_h1)[i] = o;
    ((float4*)g_agg)[i] = o;
}

// ---------------- final GEMM 256->2 fused with relu + BN2 stats ----------------
__global__ void __launch_bounds__(256) k_gemm2b(const float* __restrict__ Hid,
                                                const float* __restrict__ W,   // 256x2 row-major
                                                const float* __restrict__ bias) {
    __shared__ float w0[HID2], w1[HID2];
    __shared__ float red[8][4];
    int t = threadIdx.x;
    w0[t] = W[t * 2 + 0];
    w1[t] = W[t * 2 + 1];
    __syncthreads();

    int lane = t & 31, wid = t >> 5;
    int row = blockIdx.x * 8 + wid;
    float s0 = 0.f, s1 = 0.f, q0 = 0.f, q1 = 0.f;
    if (row < N_NODES) {
        const float* h = Hid + (size_t)row * HID2;
        float a0 = 0.f, a1 = 0.f;
#pragma unroll
        for (int i = 0; i < 8; i++) {
            float v = h[lane + 32 * i];
            a0 = fmaf(v, w0[lane + 32 * i], a0);
            a1 = fmaf(v, w1[lane + 32 * i], a1);
        }
#pragma unroll
        for (int o = 16; o; o >>= 1) {
            a0 += __shfl_xor_sync(0xffffffffu, a0, o);
            a1 += __shfl_xor_sync(0xffffffffu, a1, o);
        }
        if (lane == 0) {
            a0 = fmaxf(a0 + bias[0], 0.f);
            a1 = fmaxf(a1 + bias[1], 0.f);
            g_out2[(size_t)row * 2 + 0] = a0;
            g_out2[(size_t)row * 2 + 1] = a1;
            s0 = a0; s1 = a1; q0 = a0 * a0; q1 = a1 * a1;
        }
    }
    if (lane == 0) { red[wid][0] = s0; red[wid][1] = s1; red[wid][2] = q0; red[wid][3] = q1; }
    __syncthreads();
    if (t < 4) {
        float acc = 0.f;
#pragma unroll
        for (int wI = 0; wI < 8; wI++) acc += red[wI][t];
        atomicAdd(&g_bn2[t], acc);
    }
}

__global__ void k_bn2_fin(const float* __restrict__ gamma2, const float* __restrict__ beta2) {
    int c = threadIdx.x;
    if (c >= 2) return;
    const float invN = 1.0f / (float)N_NODES;
    float mean = g_bn2[c] * invN;
    float var  = g_bn2[2 + c] * invN - mean * mean;
    float sc   = gamma2[c] * rsqrtf(var + BN_EPS);
    g_ss2[c]     = sc;
    g_ss2[2 + c] = beta2[c] - mean * sc;
}

__global__ void k_bn2_norm(float* __restrict__ out) {
    int r = blockIdx.x * blockDim.x + threadIdx.x;
    if (r >= N_NODES) return;
    float2 v = ((const float2*)g_out2)[r];
    float2 o;
    o.x = fmaf(v.x, g_ss2[0], g_ss2[2]);
    o.y = fmaf(v.y, g_ss2[1], g_ss2[3]);
    ((float2*)out)[r] = o;
}

// ---------------- launch ----------------
extern "C" void kernel_launch(void* const* d_in, const int* in_sizes, int n_in,
                              void* d_out, int out_size) {
    const float* x      = (const float*)d_in[0];
    const int*   eidx   = (const int*)d_in[1];
    const float* ew     = (const float*)d_in[3];
    const float* W1a    = (const float*)d_in[4];
    const float* b1a    = (const float*)d_in[5];
    const float* W1b    = (const float*)d_in[6];
    const float* b1b    = (const float*)d_in[7];
    const float* gamma1 = (const float*)d_in[8];
    const float* beta1  = (const float*)d_in[9];
    const float* W2a    = (const float*)d_in[10];
    const float* b2a    = (const float*)d_in[11];
    const float* W2b    = (const float*)d_in[12];
    const float* b2b    = (const float*)d_in[13];
    const float* gamma2 = (const float*)d_in[14];
    const float* beta2  = (const float*)d_in[15];

    const int nEdges = in_sizes[1] / 2;
    const int* src = eidx;
    const int* dst = eidx + nEdges;

    float *agg, *hid, *pre, *h1;
    cudaGetSymbolAddress((void**)&agg, g_agg);
    cudaGetSymbolAddress((void**)&hid, g_hid);
    cudaGetSymbolAddress((void**)&pre, g_pre);
    cudaGetSymbolAddress((void**)&h1,  g_h1);

    const int n4 = N_NODES * (DIM / 4);
    const int initBlocks = (n4 + 255) / 256;
    const int gemmMB = (N_NODES + 127) / 128;   // 391

    // ---- layer 1 ----
    k_init<<<initBlocks, 256>>>(x);
    k_scatter<<<2048, 256>>>(src, dst, ew, x, agg, nEdges);
    {
        dim3 g(gemmMB, HID2 / 128);
        k_gemm<<<g, 256>>>(agg, W1a, b1a, hid, N_NODES, HID2, DIM);
    }
    {
        dim3 g(gemmMB, DIM / 128);
        k_gemm<<<g, 256>>>(hid, W1b, b1b, pre, N_NODES, DIM, HID2);
    }
    k_bn1_reduce<<<512, 128>>>(pre);
    k_bn1_fin<<<1, 128>>>(gamma1, beta1);
    k_bn1_norm<<<initBlocks, 256>>>(pre);

    // ---- layer 2 ----
    k_scatter<<<2048, 256>>>(src, dst, ew, h1, agg, nEdges);
    {
        dim3 g(gemmMB, HID2 / 128);
        k_gemm<<<g, 256>>>(agg, W2a, b2a, hid, N_NODES, HID2, DIM);
    }
    k_gemm2b<<<(N_NODES + 7) / 8, 256>>>(hid, W2b, b2b);
    k_bn2_fin<<<1, 32>>>(gamma2, beta2);
    k_bn2_norm<<<(N_NODES + 255) / 256, 256>>>((float*)d_out);
}

// round 6
// speedup vs baseline: 1.3331x; 1.2450x over previous
#include <cuda_runtime.h>
#include <cuda_bf16.h>
#include <cstdint>

#define N_NODES 50000
#define N_EDGES 1600000
#define DIM 128
#define HID2 256
#define BN_EPS 1e-5f

#define MPAD 50048          // 391 * 128
#define MTILES 391

// ---------------- scratch (static device globals; no runtime alloc) ----------------
__device__ float g_agg[(size_t)N_NODES * DIM];
__device__ float g_hid[(size_t)N_NODES * HID2];
__device__ float g_pre[(size_t)N_NODES * DIM];
__device__ float g_h1 [(size_t)N_NODES * DIM];
__device__ float g_out2[(size_t)N_NODES * 2];

__device__ __nv_bfloat16 g_A2[(size_t)MPAD * 512];   // [Mpad, 2K] split-bf16 A: [hi|lo], K<=256
__device__ __nv_bfloat16 g_B2[(size_t)256 * 512];    // [N, 2K] split-bf16 B: [hi|lo]

__device__ __align__(16) float g_sum1[DIM];
__device__ __align__(16) float g_sq1[DIM];
__device__ __align__(16) float g_scale1[DIM];
__device__ __align__(16) float g_shift1[DIM];
__device__ float g_bn2[4];
__device__ float g_ss2[4];

// ---------------- helpers ----------------
__device__ __forceinline__ uint32_t smem_u32(const void* p) {
    uint32_t a;
    asm("{ .reg .u64 t; cvta.to.shared.u64 t, %1; cvt.u32.u64 %0, t; }" : "=r"(a) : "l"(p));
    return a;
}
#define SWZ128(off) ((off) ^ (((off) >> 3) & 0x70))

__device__ __forceinline__ void mma16816(float* c, const uint32_t* a, const uint32_t* b) {
    asm volatile("mma.sync.aligned.m16n8k16.row.col.f32.bf16.bf16.f32 "
        "{%0,%1,%2,%3}, {%4,%5,%6,%7}, {%8,%9}, {%0,%1,%2,%3};"
        : "+f"(c[0]), "+f"(c[1]), "+f"(c[2]), "+f"(c[3])
        : "r"(a[0]), "r"(a[1]), "r"(a[2]), "r"(a[3]), "r"(b[0]), "r"(b[1]));
}
#define LDSM4(r, addr) asm volatile("ldmatrix.sync.aligned.m8n8.x4.shared.b16 {%0,%1,%2,%3}, [%4];" \
    : "=r"((r)[0]), "=r"((r)[1]), "=r"((r)[2]), "=r"((r)[3]) : "r"(addr))
#define LDSM2(r, addr) asm volatile("ldmatrix.sync.aligned.m8n8.x2.shared.b16 {%0,%1}, [%2];" \
    : "=r"((r)[0]), "=r"((r)[1]) : "r"(addr))
#define CPASYNC16(dst, src) asm volatile("cp.async.cg.shared.global [%0], [%1], 16;" :: "r"(dst), "l"(src))

// ---------------- init: agg = x, zero stats ----------------
__global__ void k_init(const float* __restrict__ x) {
    int i = blockIdx.x * blockDim.x + threadIdx.x;
    const int n4 = N_NODES * (DIM / 4);
    if (i < n4) ((float4*)g_agg)[i] = ((const float4*)x)[i];
    if (i < DIM) { g_sum1[i] = 0.f; g_sq1[i] = 0.f; }
    if (i < 4)   { g_bn2[i] = 0.f; }
}

// ---------------- scatter: agg[dst] += feat[src] * w, one warp per edge ----------------
__global__ void __launch_bounds__(256) k_scatter(const int* __restrict__ src,
                                                 const int* __restrict__ dst,
                                                 const float* __restrict__ wgt,
                                                 const float* __restrict__ feat,
                                                 float* __restrict__ agg,
                                                 int nEdges) {
    int lane = threadIdx.x & 31;
    int warp = (blockIdx.x * blockDim.x + threadIdx.x) >> 5;
    int nwarps = (gridDim.x * blockDim.x) >> 5;
    for (int e = warp; e < nEdges; e += nwarps) {
        int s = src[e];
        int d = dst[e];
        float w = wgt[e];
        float4 v = ((const float4*)(feat + (size_t)s * DIM))[lane];
        v.x *= w; v.y *= w; v.z *= w; v.w *= w;
        float* p = agg + (size_t)d * DIM + lane * 4;
        asm volatile("red.global.add.v4.f32 [%0], {%1, %2, %3, %4};"
                     :: "l"(p), "f"(v.x), "f"(v.y), "f"(v.z), "f"(v.w)
                     : "memory");
    }
}

// ---------------- split-bf16 conversions ----------------
// A [M,K] fp32 -> A2 [Mpad, 2K] bf16: [hi | lo], pad rows zero.
__global__ void k_convA(const float* __restrict__ A, int M, int K) {
    int i = blockIdx.x * blockDim.x + threadIdx.x;   // over Mpad * K/2 (uint32 pairs)
    int kh = K >> 1;
    if (i >= MPAD * kh) return;
    int m = i / kh, k2 = i % kh;
    float2 v = make_float2(0.f, 0.f);
    if (m < M) v = ((const float2*)A)[(size_t)m * kh + k2];
    __nv_bfloat16 h0 = __float2bfloat16(v.x);
    __nv_bfloat16 h1 = __float2bfloat16(v.y);
    __nv_bfloat16 l0 = __float2bfloat16(v.x - __bfloat162float(h0));
    __nv_bfloat16 l1 = __float2bfloat16(v.y - __bfloat162float(h1));
    uint32_t hi, lo;
    asm("mov.b32 %0, {%1, %2};" : "=r"(hi) : "h"(*(unsigned short*)&h0), "h"(*(unsigned short*)&h1));
    asm("mov.b32 %0, {%1, %2};" : "=r"(lo) : "h"(*(unsigned short*)&l0), "h"(*(unsigned short*)&l1));
    uint32_t* o = (uint32_t*)g_A2;
    size_t base = (size_t)m * K;   // uint32 units per row = K
    o[base + k2]      = hi;
    o[base + kh + k2] = lo;
}

// W [K,N] fp32 -> B2 [N, 2K] bf16: [hi | lo]
__global__ void k_convB(const float* __restrict__ W, int K, int N) {
    int i = blockIdx.x * blockDim.x + threadIdx.x;   // over N*K
    if (i >= N * K) return;
    int n = i / K, k = i % K;
    float v = W[(size_t)k * N + n];
    __nv_bfloat16 h = __float2bfloat16(v);
    __nv_bfloat16 l = __float2bfloat16(v - __bfloat162float(h));
    size_t base = (size_t)n * 2 * K;
    g_B2[base + k]     = h;
    g_B2[base + K + k] = l;
}

// ---------------- HMMA bf16 GEMM: C = relu(split3(A) @ split3(B)^T + bias) ----------------
// A2 [Mpad,2K] bf16 [hi|lo], B2 [Ntot,2K] bf16 [hi|lo]. 3 segments: hi*hi + lo*hi + hi*lo.
// Tile 128x128, K-chunk 64, double-buffered cp.async, 8 warps (2m x 4n), m16n8k16.
__global__ void __launch_bounds__(256, 2)
k_mma(const __nv_bfloat16* __restrict__ A2, const __nv_bfloat16* __restrict__ B2,
      const float* __restrict__ bias, float* __restrict__ C,
      int M, int Ntot, int K) {
    extern __shared__ __align__(1024) uint8_t sm[];
    const int t = threadIdx.x;
    const int lane = t & 31;
    const int wid = t >> 5;
    const int wm = wid >> 2;          // 0..1 (64 rows each)
    const int wn = wid & 3;           // 0..3 (32 cols each)
    const int bm = blockIdx.x * 128;
    const int bn = blockIdx.y * 128;
    const int K2 = K * 2;
    const uint32_t smbase = smem_u32(sm);

    const int lrow = t >> 3;          // 0..31
    const int ls16 = t & 7;           // 16B segment within 128B row
    const int cps = K >> 6;           // chunks per segment
    const int total = 3 * cps;

#define LOADCHUNK(c, buf) do {                                                        \
        int s_ = (c) / cps, ck_ = (c) % cps;                                          \
        int aoff_ = (s_ == 1 ? K : 0) + ck_ * 64;                                     \
        int boff_ = (s_ == 2 ? K : 0) + ck_ * 64;                                     \
        uint32_t sA_ = smbase + (buf) * 32768;                                        \
        uint32_t sB_ = sA_ + 16384;                                                   \
        _Pragma("unroll")                                                             \
        for (int i_ = 0; i_ < 4; i_++) {                                              \
            int row_ = lrow + 32 * i_;                                                \
            uint32_t da_ = sA_ + SWZ128(row_ * 128 + ls16 * 16);                      \
            const void* ga_ = A2 + (size_t)(bm + row_) * K2 + aoff_ + ls16 * 8;       \
            CPASYNC16(da_, ga_);                                                      \
            uint32_t db_ = sB_ + SWZ128(row_ * 128 + ls16 * 16);                      \
            const void* gb_ = B2 + (size_t)(bn + row_) * K2 + boff_ + ls16 * 8;       \
            CPASYNC16(db_, gb_);                                                      \
        }                                                                             \
        asm volatile("cp.async.commit_group;");                                       \
    } while (0)

    float acc[4][4][4] = {};

    LOADCHUNK(0, 0);
    for (int c = 0; c < total; c++) {
        if (c + 1 < total) {
            LOADCHUNK(c + 1, (c + 1) & 1);
            asm volatile("cp.async.wait_group 1;");
        } else {
            asm volatile("cp.async.wait_group 0;");
        }
        __syncthreads();
        uint32_t sA = smbase + (c & 1) * 32768;
        uint32_t sB = sA + 16384;
        const int t16 = lane & 15;
#pragma unroll
        for (int ks = 0; ks < 4; ks++) {
            uint32_t afr[4][4];
            uint32_t bfr[4][2];
#pragma unroll
            for (int mi = 0; mi < 4; mi++) {
                int row = wm * 64 + mi * 16 + (lane & 15);
                uint32_t addr = sA + SWZ128(row * 128 + ks * 32 + ((lane >> 4) << 4));
                LDSM4(afr[mi], addr);
            }
#pragma unroll
            for (int ni = 0; ni < 4; ni++) {
                int row = wn * 32 + ni * 8 + (t16 & 7);
                uint32_t addr = sB + SWZ128(row * 128 + ks * 32 + ((t16 >> 3) << 4));
                LDSM2(bfr[ni], addr);
            }
#pragma unroll
            for (int mi = 0; mi < 4; mi++)
#pragma unroll
                for (int ni = 0; ni < 4; ni++)
                    mma16816(acc[mi][ni], afr[mi], bfr[ni]);
        }
        __syncthreads();
    }

    // epilogue: bias + relu + store
#pragma unroll
    for (int mi = 0; mi < 4; mi++) {
        int r0 = bm + wm * 64 + mi * 16 + (lane >> 2);
        int r1 = r0 + 8;
#pragma unroll
        for (int ni = 0; ni < 4; ni++) {
            int col = bn + wn * 32 + ni * 8 + (lane & 3) * 2;
            float2 bv = *(const float2*)(bias + col);
            if (r0 < M) {
                float2 o;
                o.x = fmaxf(acc[mi][ni][0] + bv.x, 0.f);
                o.y = fmaxf(acc[mi][ni][1] + bv.y, 0.f);
                *(float2*)(C + (size_t)r0 * Ntot + col) = o;
            }
            if (r1 < M) {
                float2 o;
                o.x = fmaxf(acc[mi][ni][2] + bv.x, 0.f);
                o.y = fmaxf(acc[mi][ni][3] + bv.y, 0.f);
                *(float2*)(C + (size_t)r1 * Ntot + col) = o;
            }
        }
    }
#undef LOADCHUNK
}

// ---------------- BN1 ----------------
__global__ void __launch_bounds__(128) k_bn1_reduce(const float* __restrict__ pre) {
    int c = threadIdx.x;
    float s = 0.f, q = 0.f;
    for (int r = blockIdx.x; r < N_NODES; r += gridDim.x) {
        float v = pre[(size_t)r * DIM + c];
        s += v; q += v * v;
    }
    atomicAdd(&g_sum1[c], s);
    atomicAdd(&g_sq1[c], q);
}

__global__ void k_bn1_fin(const float* __restrict__ gamma, const float* __restrict__ beta) {
    int c = threadIdx.x;
    if (c >= DIM) return;
    const float invN = 1.0f / (float)N_NODES;
    float mean = g_sum1[c] * invN;
    float var  = g_sq1[c] * invN - mean * mean;
    float sc   = gamma[c] * rsqrtf(var + BN_EPS);
    g_scale1[c] = sc;
    g_shift1[c] = beta[c] - mean * sc;
}

__global__ void k_bn1_norm(const float* __restrict__ pre) {
    int i = blockIdx.x * blockDim.x + threadIdx.x;
    const int n4 = N_NODES * (DIM / 4);
    if (i >= n4) return;
    int c4 = i & 31;
    float4 v  = ((const float4*)pre)[i];
    float4 sc = ((const float4*)g_scale1)[c4];
    float4 sh = ((const float4*)g_shift1)[c4];
    float4 o;
    o.x = fmaf(v.x, sc.x, sh.x);
    o.y = fmaf(v.y, sc.y, sh.y);
    o.z = fmaf(v.z, sc.z, sh.z);
    o.w = fmaf(v.w, sc.w, sh.w);
    ((float4*)g_h1)[i] = o;
    ((float4*)g_agg)[i] = o;
}

// ---------------- final GEMM 256->2 fused with relu + BN2 stats ----------------
__global__ void __launch_bounds__(256) k_gemm2b(const float* __restrict__ Hid,
                                                const float* __restrict__ W,
                                                const float* __restrict__ bias) {
    __shared__ float w0[HID2], w1[HID2];
    __shared__ float red[8][4];
    int t = threadIdx.x;
    w0[t] = W[t * 2 + 0];
    w1[t] = W[t * 2 + 1];
    __syncthreads();

    int lane = t & 31, wid = t >> 5;
    int row = blockIdx.x * 8 + wid;
    float s0 = 0.f, s1 = 0.f, q0 = 0.f, q1 = 0.f;
    if (row < N_NODES) {
        const float* h = Hid + (size_t)row * HID2;
        float a0 = 0.f, a1 = 0.f;
#pragma unroll
        for (int i = 0; i < 8; i++) {
            float v = h[lane + 32 * i];
            a0 = fmaf(v, w0[lane + 32 * i], a0);
            a1 = fmaf(v, w1[lane + 32 * i], a1);
        }
#pragma unroll
        for (int o = 16; o; o >>= 1) {
            a0 += __shfl_xor_sync(0xffffffffu, a0, o);
            a1 += __shfl_xor_sync(0xffffffffu, a1, o);
        }
        if (lane == 0) {
            a0 = fmaxf(a0 + bias[0], 0.f);
            a1 = fmaxf(a1 + bias[1], 0.f);
            g_out2[(size_t)row * 2 + 0] = a0;
            g_out2[(size_t)row * 2 + 1] = a1;
            s0 = a0; s1 = a1; q0 = a0 * a0; q1 = a1 * a1;
        }
    }
    if (lane == 0) { red[wid][0] = s0; red[wid][1] = s1; red[wid][2] = q0; red[wid][3] = q1; }
    __syncthreads();
    if (t < 4) {
        float acc = 0.f;
#pragma unroll
        for (int wI = 0; wI < 8; wI++) acc += red[wI][t];
        atomicAdd(&g_bn2[t], acc);
    }
}

__global__ void k_bn2_fin(const float* __restrict__ gamma2, const float* __restrict__ beta2) {
    int c = threadIdx.x;
    if (c >= 2) return;
    const float invN = 1.0f / (float)N_NODES;
    float mean = g_bn2[c] * invN;
    float var  = g_bn2[2 + c] * invN - mean * mean;
    float sc   = gamma2[c] * rsqrtf(var + BN_EPS);
    g_ss2[c]     = sc;
    g_ss2[2 + c] = beta2[c] - mean * sc;
}

__global__ void k_bn2_norm(float* __restrict__ out) {
    int r = blockIdx.x * blockDim.x + threadIdx.x;
    if (r >= N_NODES) return;
    float2 v = ((const float2*)g_out2)[r];
    float2 o;
    o.x = fmaf(v.x, g_ss2[0], g_ss2[2]);
    o.y = fmaf(v.y, g_ss2[1], g_ss2[3]);
    ((float2*)out)[r] = o;
}

// ---------------- launch ----------------
extern "C" void kernel_launch(void* const* d_in, const int* in_sizes, int n_in,
                              void* d_out, int out_size) {
    const float* x      = (const float*)d_in[0];
    const int*   eidx   = (const int*)d_in[1];
    const float* ew     = (const float*)d_in[3];
    const float* W1a    = (const float*)d_in[4];
    const float* b1a    = (const float*)d_in[5];
    const float* W1b    = (const float*)d_in[6];
    const float* b1b    = (const float*)d_in[7];
    const float* gamma1 = (const float*)d_in[8];
    const float* beta1  = (const float*)d_in[9];
    const float* W2a    = (const float*)d_in[10];
    const float* b2a    = (const float*)d_in[11];
    const float* W2b    = (const float*)d_in[12];
    const float* b2b    = (const float*)d_in[13];
    const float* gamma2 = (const float*)d_in[14];
    const float* beta2  = (const float*)d_in[15];

    const int nEdges = in_sizes[1] / 2;
    const int* src = eidx;
    const int* dst = eidx + nEdges;

    float *agg, *hid, *pre, *h1;
    __nv_bfloat16 *A2, *B2;
    cudaGetSymbolAddress((void**)&agg, g_agg);
    cudaGetSymbolAddress((void**)&hid, g_hid);
    cudaGetSymbolAddress((void**)&pre, g_pre);
    cudaGetSymbolAddress((void**)&h1,  g_h1);
    cudaGetSymbolAddress((void**)&A2,  g_A2);
    cudaGetSymbolAddress((void**)&B2,  g_B2);

    cudaFuncSetAttribute(k_mma, cudaFuncAttributeMaxDynamicSharedMemorySize, 65536);

    const int n4 = N_NODES * (DIM / 4);
    const int initBlocks = (n4 + 255) / 256;

    const int convA128 = (MPAD * 64 + 255) / 256;    // K=128 -> Mpad*K/2 threads
    const int convA256 = (MPAD * 128 + 255) / 256;   // K=256

    // ---- layer 1 ----
    k_init<<<initBlocks, 256>>>(x);
    k_scatter<<<2048, 256>>>(src, dst, ew, x, agg, nEdges);

    // GEMM1: relu(agg[50000,128] @ W1a[128,256] + b1a) -> hid
    k_convA<<<convA128, 256>>>(agg, N_NODES, DIM);
    k_convB<<<(DIM * HID2 + 255) / 256, 256>>>(W1a, DIM, HID2);
    {
        dim3 g(MTILES, 2);
        k_mma<<<g, 256, 65536>>>(A2, B2, b1a, hid, N_NODES, HID2, DIM);
    }
    // GEMM2: relu(hid[50000,256] @ W1b[256,128] + b1b) -> pre
    k_convA<<<convA256, 256>>>(hid, N_NODES, HID2);
    k_convB<<<(HID2 * DIM + 255) / 256, 256>>>(W1b, HID2, DIM);
    {
        dim3 g(MTILES, 1);
        k_mma<<<g, 256, 65536>>>(A2, B2, b1b, pre, N_NODES, DIM, HID2);
    }
    k_bn1_reduce<<<512, 128>>>(pre);
    k_bn1_fin<<<1, 128>>>(gamma1, beta1);
    k_bn1_norm<<<initBlocks, 256>>>(pre);

    // ---- layer 2 ----
    k_scatter<<<2048, 256>>>(src, dst, ew, h1, agg, nEdges);
    // GEMM3: relu(agg @ W2a[128,256] + b2a) -> hid
    k_convA<<<convA128, 256>>>(agg, N_NODES, DIM);
    k_convB<<<(DIM * HID2 + 255) / 256, 256>>>(W2a, DIM, HID2);
    {
        dim3 g(MTILES, 2);
        k_mma<<<g, 256, 65536>>>(A2, B2, b2a, hid, N_NODES, HID2, DIM);
    }
    k_gemm2b<<<(N_NODES + 7) / 8, 256>>>(hid, W2b, b2b);
    k_bn2_fin<<<1, 32>>>(gamma2, beta2);
    k_bn2_norm<<<(N_NODES + 255) / 256, 256>>>((float*)d_out);
}

// round 7
// speedup vs baseline: 1.6966x; 1.2727x over previous
#include <cuda_runtime.h>
#include <cuda_bf16.h>
#include <cstdint>

#define N_NODES 50000
#define N_EDGES 1600000
#define DIM 128
#define HID2 256
#define BN_EPS 1e-5f

#define MPAD 50048          // 391 * 128
#define MTILES 391

// ---------------- scratch (static device globals; no runtime alloc) ----------------
__device__ float g_hid[(size_t)N_NODES * HID2];
__device__ float g_pre[(size_t)N_NODES * DIM];
__device__ float g_h1 [(size_t)N_NODES * DIM];
__device__ float g_out2[(size_t)N_NODES * 2];

__device__ __nv_bfloat16 g_A2[(size_t)MPAD * 512];   // [Mpad, 2K] split-bf16 A: [hi|lo], K<=256
__device__ __nv_bfloat16 g_B2[(size_t)256 * 512];    // [N, 2K] split-bf16 B: [hi|lo]

// CSR scratch
__device__ int   g_deg[N_NODES];
__device__ int   g_rowptr[N_NODES + 1];
__device__ int   g_cur[N_NODES];
__device__ uint2 g_edge[N_EDGES];                    // (src, weight bits), sorted by dst

__device__ __align__(16) float g_sum1[DIM];
__device__ __align__(16) float g_sq1[DIM];
__device__ __align__(16) float g_scale1[DIM];
__device__ __align__(16) float g_shift1[DIM];
__device__ float g_bn2[4];
__device__ float g_ss2[4];

// ---------------- helpers ----------------
__device__ __forceinline__ uint32_t smem_u32(const void* p) {
    uint32_t a;
    asm("{ .reg .u64 t; cvta.to.shared.u64 t, %1; cvt.u32.u64 %0, t; }" : "=r"(a) : "l"(p));
    return a;
}
#define SWZ128(off) ((off) ^ (((off) >> 3) & 0x70))

__device__ __forceinline__ void mma16816(float* c, const uint32_t* a, const uint32_t* b) {
    asm volatile("mma.sync.aligned.m16n8k16.row.col.f32.bf16.bf16.f32 "
        "{%0,%1,%2,%3}, {%4,%5,%6,%7}, {%8,%9}, {%0,%1,%2,%3};"
        : "+f"(c[0]), "+f"(c[1]), "+f"(c[2]), "+f"(c[3])
        : "r"(a[0]), "r"(a[1]), "r"(a[2]), "r"(a[3]), "r"(b[0]), "r"(b[1]));
}
#define LDSM4(r, addr) asm volatile("ldmatrix.sync.aligned.m8n8.x4.shared.b16 {%0,%1,%2,%3}, [%4];" \
    : "=r"((r)[0]), "=r"((r)[1]), "=r"((r)[2]), "=r"((r)[3]) : "r"(addr))
#define LDSM2(r, addr) asm volatile("ldmatrix.sync.aligned.m8n8.x2.shared.b16 {%0,%1}, [%2];" \
    : "=r"((r)[0]), "=r"((r)[1]) : "r"(addr))
#define CPASYNC16(dst, src) asm volatile("cp.async.cg.shared.global [%0], [%1], 16;" :: "r"(dst), "l"(src))

__device__ __forceinline__ uint32_t pack_hi2(float x, float y) {
    __nv_bfloat16 h0 = __float2bfloat16(x);
    __nv_bfloat16 h1 = __float2bfloat16(y);
    uint32_t r;
    asm("mov.b32 %0, {%1, %2};" : "=r"(r) : "h"(*(unsigned short*)&h0), "h"(*(unsigned short*)&h1));
    return r;
}
__device__ __forceinline__ uint32_t pack_lo2(float x, float y) {
    __nv_bfloat16 h0 = __float2bfloat16(x);
    __nv_bfloat16 h1 = __float2bfloat16(y);
    __nv_bfloat16 l0 = __float2bfloat16(x - __bfloat162float(h0));
    __nv_bfloat16 l1 = __float2bfloat16(y - __bfloat162float(h1));
    uint32_t r;
    asm("mov.b32 %0, {%1, %2};" : "=r"(r) : "h"(*(unsigned short*)&l0), "h"(*(unsigned short*)&l1));
    return r;
}

// ---------------- CSR build ----------------
__global__ void k_prep() {
    int i = blockIdx.x * blockDim.x + threadIdx.x;
    if (i < N_NODES) g_deg[i] = 0;
    if (i < DIM) { g_sum1[i] = 0.f; g_sq1[i] = 0.f; }
    if (i < 4)   { g_bn2[i] = 0.f; }
}

__global__ void __launch_bounds__(256) k_hist(const int* __restrict__ dst, int nEdges) {
    int i = blockIdx.x * blockDim.x + threadIdx.x;
    int stride = gridDim.x * blockDim.x;
    for (int e = i; e < nEdges; e += stride)
        atomicAdd(&g_deg[dst[e]], 1);
}

__global__ void __launch_bounds__(1024) k_scan() {
    __shared__ int sm[1024];
    __shared__ int carry;
    int t = threadIdx.x;
    if (t == 0) { carry = 0; g_rowptr[0] = 0; }
    __syncthreads();
    for (int base = 0; base < N_NODES; base += 1024) {
        int i = base + t;
        int v = (i < N_NODES) ? g_deg[i] : 0;
        sm[t] = v;
        __syncthreads();
#pragma unroll
        for (int off = 1; off < 1024; off <<= 1) {
            int u = (t >= off) ? sm[t - off] : 0;
            __syncthreads();
            sm[t] += u;
            __syncthreads();
        }
        int inc = sm[t] + carry;
        if (i < N_NODES) {
            g_rowptr[i + 1] = inc;
            g_cur[i] = inc - v;
        }
        int blocktotal = sm[1023];
        __syncthreads();
        if (t == 0) carry += blocktotal;
        __syncthreads();
    }
}

__global__ void __launch_bounds__(256) k_fill(const int* __restrict__ src,
                                              const int* __restrict__ dst,
                                              const float* __restrict__ wgt,
                                              int nEdges) {
    int i = blockIdx.x * blockDim.x + threadIdx.x;
    int stride = gridDim.x * blockDim.x;
    for (int e = i; e < nEdges; e += stride) {
        int d = dst[e];
        int pos = atomicAdd(&g_cur[d], 1);
        g_edge[pos] = make_uint2((uint32_t)src[e], __float_as_uint(wgt[e]));
    }
}

// ---------------- fused gather + split-bf16 convert ----------------
// One warp per node row: acc = feat[n] + sum_e w_e * feat[src_e]; write A2[n] (hi|lo).
// Rows >= N_NODES written zero (pad). A2 row stride = 2*DIM bf16 = 128 u32.
__global__ void __launch_bounds__(256) k_gather(const float* __restrict__ feat) {
    int lane = threadIdx.x & 31;
    int node = (blockIdx.x * blockDim.x + threadIdx.x) >> 5;
    if (node >= MPAD) return;
    uint32_t* o = (uint32_t*)g_A2;
    size_t base = (size_t)node * 128;
    if (node >= N_NODES) {
        ((uint2*)(o + base))[lane] = make_uint2(0u, 0u);        // covers 64 u32 (hi)
        ((uint2*)(o + base + 64))[lane] = make_uint2(0u, 0u);   // covers 64 u32 (lo)
        return;
    }
    const float4* f4 = (const float4*)feat;
    float4 acc = f4[(size_t)node * 32 + lane];
    int j = g_rowptr[node];
    int end = g_rowptr[node + 1];
    for (; j + 4 <= end; j += 4) {
        uint2 e0 = g_edge[j + 0];
        uint2 e1 = g_edge[j + 1];
        uint2 e2 = g_edge[j + 2];
        uint2 e3 = g_edge[j + 3];
        float4 v0 = f4[(size_t)e0.x * 32 + lane];
        float4 v1 = f4[(size_t)e1.x * 32 + lane];
        float4 v2 = f4[(size_t)e2.x * 32 + lane];
        float4 v3 = f4[(size_t)e3.x * 32 + lane];
        float w0 = __uint_as_float(e0.y), w1 = __uint_as_float(e1.y);
        float w2 = __uint_as_float(e2.y), w3 = __uint_as_float(e3.y);
        acc.x = fmaf(w0, v0.x, acc.x); acc.y = fmaf(w0, v0.y, acc.y);
        acc.z = fmaf(w0, v0.z, acc.z); acc.w = fmaf(w0, v0.w, acc.w);
        acc.x = fmaf(w1, v1.x, acc.x); acc.y = fmaf(w1, v1.y, acc.y);
        acc.z = fmaf(w1, v1.z, acc.z); acc.w = fmaf(w1, v1.w, acc.w);
        acc.x = fmaf(w2, v2.x, acc.x); acc.y = fmaf(w2, v2.y, acc.y);
        acc.z = fmaf(w2, v2.z, acc.z); acc.w = fmaf(w2, v2.w, acc.w);
        acc.x = fmaf(w3, v3.x, acc.x); acc.y = fmaf(w3, v3.y, acc.y);
        acc.z = fmaf(w3, v3.z, acc.z); acc.w = fmaf(w3, v3.w, acc.w);
    }
    for (; j < end; j++) {
        uint2 e = g_edge[j];
        float w = __uint_as_float(e.y);
        float4 v = f4[(size_t)e.x * 32 + lane];
        acc.x = fmaf(w, v.x, acc.x); acc.y = fmaf(w, v.y, acc.y);
        acc.z = fmaf(w, v.z, acc.z); acc.w = fmaf(w, v.w, acc.w);
    }
    uint2 hi = make_uint2(pack_hi2(acc.x, acc.y), pack_hi2(acc.z, acc.w));
    uint2 lo = make_uint2(pack_lo2(acc.x, acc.y), pack_lo2(acc.z, acc.w));
    *(uint2*)(o + base + 2 * lane) = hi;
    *(uint2*)(o + base + 64 + 2 * lane) = lo;
}

// ---------------- split-bf16 conversions (for hid, K=256) ----------------
__global__ void k_convA(const float* __restrict__ A, int M, int K) {
    int i = blockIdx.x * blockDim.x + threadIdx.x;
    int kh = K >> 1;
    if (i >= MPAD * kh) return;
    int m = i / kh, k2 = i % kh;
    float2 v = make_float2(0.f, 0.f);
    if (m < M) v = ((const float2*)A)[(size_t)m * kh + k2];
    uint32_t* o = (uint32_t*)g_A2;
    size_t base = (size_t)m * K;
    o[base + k2]      = pack_hi2(v.x, v.y);
    o[base + kh + k2] = pack_lo2(v.x, v.y);
}

// W [K,N] fp32 -> B2 [N, 2K] bf16: [hi | lo]
__global__ void k_convB(const float* __restrict__ W, int K, int N) {
    int i = blockIdx.x * blockDim.x + threadIdx.x;
    if (i >= N * K) return;
    int n = i / K, k = i % K;
    float v = W[(size_t)k * N + n];
    __nv_bfloat16 h = __float2bfloat16(v);
    __nv_bfloat16 l = __float2bfloat16(v - __bfloat162float(h));
    size_t base = (size_t)n * 2 * K;
    g_B2[base + k]     = h;
    g_B2[base + K + k] = l;
}

// ---------------- HMMA bf16 GEMM: C = relu(split3(A) @ split3(B)^T + bias) ----------------
__global__ void __launch_bounds__(256, 2)
k_mma(const __nv_bfloat16* __restrict__ A2, const __nv_bfloat16* __restrict__ B2,
      const float* __restrict__ bias, float* __restrict__ C,
      int M, int Ntot, int K) {
    extern __shared__ __align__(1024) uint8_t sm[];
    const int t = threadIdx.x;
    const int lane = t & 31;
    const int wid = t >> 5;
    const int wm = wid >> 2;
    const int wn = wid & 3;
    const int bm = blockIdx.x * 128;
    const int bn = blockIdx.y * 128;
    const int K2 = K * 2;
    const uint32_t smbase = smem_u32(sm);

    const int lrow = t >> 3;
    const int ls16 = t & 7;
    const int cps = K >> 6;
    const int total = 3 * cps;

#define LOADCHUNK(c, buf) do {                                                        \
        int s_ = (c) / cps, ck_ = (c) % cps;                                          \
        int aoff_ = (s_ == 1 ? K : 0) + ck_ * 64;                                     \
        int boff_ = (s_ == 2 ? K : 0) + ck_ * 64;                                     \
        uint32_t sA_ = smbase + (buf) * 32768;                                        \
        uint32_t sB_ = sA_ + 16384;                                                   \
        _Pragma("unroll")                                                             \
        for (int i_ = 0; i_ < 4; i_++) {                                              \
            int row_ = lrow + 32 * i_;                                                \
            uint32_t da_ = sA_ + SWZ128(row_ * 128 + ls16 * 16);                      \
            const void* ga_ = A2 + (size_t)(bm + row_) * K2 + aoff_ + ls16 * 8;       \
            CPASYNC16(da_, ga_);                                                      \
            uint32_t db_ = sB_ + SWZ128(row_ * 128 + ls16 * 16);                      \
            const void* gb_ = B2 + (size_t)(bn + row_) * K2 + boff_ + ls16 * 8;       \
            CPASYNC16(db_, gb_);                                                      \
        }                                                                             \
        asm volatile("cp.async.commit_group;");                                       \
    } while (0)

    float acc[4][4][4] = {};

    LOADCHUNK(0, 0);
    for (int c = 0; c < total; c++) {
        if (c + 1 < total) {
            LOADCHUNK(c + 1, (c + 1) & 1);
            asm volatile("cp.async.wait_group 1;");
        } else {
            asm volatile("cp.async.wait_group 0;");
        }
        __syncthreads();
        uint32_t sA = smbase + (c & 1) * 32768;
        uint32_t sB = sA + 16384;
        const int t16 = lane & 15;
#pragma unroll
        for (int ks = 0; ks < 4; ks++) {
            uint32_t afr[4][4];
            uint32_t bfr[4][2];
#pragma unroll
            for (int mi = 0; mi < 4; mi++) {
                int row = wm * 64 + mi * 16 + (lane & 15);
                uint32_t addr = sA + SWZ128(row * 128 + ks * 32 + ((lane >> 4) << 4));
                LDSM4(afr[mi], addr);
            }
#pragma unroll
            for (int ni = 0; ni < 4; ni++) {
                int row = wn * 32 + ni * 8 + (t16 & 7);
                uint32_t addr = sB + SWZ128(row * 128 + ks * 32 + ((t16 >> 3) << 4));
                LDSM2(bfr[ni], addr);
            }
#pragma unroll
            for (int mi = 0; mi < 4; mi++)
#pragma unroll
                for (int ni = 0; ni < 4; ni++)
                    mma16816(acc[mi][ni], afr[mi], bfr[ni]);
        }
        __syncthreads();
    }

#pragma unroll
    for (int mi = 0; mi < 4; mi++) {
        int r0 = bm + wm * 64 + mi * 16 + (lane >> 2);
        int r1 = r0 + 8;
#pragma unroll
        for (int ni = 0; ni < 4; ni++) {
            int col = bn + wn * 32 + ni * 8 + (lane & 3) * 2;
            float2 bv = *(const float2*)(bias + col);
            if (r0 < M) {
                float2 o;
                o.x = fmaxf(acc[mi][ni][0] + bv.x, 0.f);
                o.y = fmaxf(acc[mi][ni][1] + bv.y, 0.f);
                *(float2*)(C + (size_t)r0 * Ntot + col) = o;
            }
            if (r1 < M) {
                float2 o;
                o.x = fmaxf(acc[mi][ni][2] + bv.x, 0.f);
                o.y = fmaxf(acc[mi][ni][3] + bv.y, 0.f);
                *(float2*)(C + (size_t)r1 * Ntot + col) = o;
            }
        }
    }
#undef LOADCHUNK
}

// ---------------- BN1 ----------------
__global__ void __launch_bounds__(128) k_bn1_reduce(const float* __restrict__ pre) {
    int c = threadIdx.x;
    float s = 0.f, q = 0.f;
    for (int r = blockIdx.x; r < N_NODES; r += gridDim.x) {
        float v = pre[(size_t)r * DIM + c];
        s += v; q += v * v;
    }
    atomicAdd(&g_sum1[c], s);
    atomicAdd(&g_sq1[c], q);
}

__global__ void k_bn1_fin(const float* __restrict__ gamma, const float* __restrict__ beta) {
    int c = threadIdx.x;
    if (c >= DIM) return;
    const float invN = 1.0f / (float)N_NODES;
    float mean = g_sum1[c] * invN;
    float var  = g_sq1[c] * invN - mean * mean;
    float sc   = gamma[c] * rsqrtf(var + BN_EPS);
    g_scale1[c] = sc;
    g_shift1[c] = beta[c] - mean * sc;
}

__global__ void k_bn1_norm(const float* __restrict__ pre) {
    int i = blockIdx.x * blockDim.x + threadIdx.x;
    const int n4 = N_NODES * (DIM / 4);
    if (i >= n4) return;
    int c4 = i & 31;
    float4 v  = ((const float4*)pre)[i];
    float4 sc = ((const float4*)g_scale1)[c4];
    float4 sh = ((const float4*)g_shift1)[c4];
    float4 o;
    o.x = fmaf(v.x, sc.x, sh.x);
    o.y = fmaf(v.y, sc.y, sh.y);
    o.z = fmaf(v.z, sc.z, sh.z);
    o.w = fmaf(v.w, sc.w, sh.w);
    ((float4*)g_h1)[i] = o;
}

// ---------------- final GEMM 256->2 fused with relu + BN2 stats ----------------
__global__ void __launch_bounds__(256) k_gemm2b(const float* __restrict__ Hid,
                                                const float* __restrict__ W,
                                                const float* __restrict__ bias) {
    __shared__ float w0[HID2], w1[HID2];
    __shared__ float red[8][4];
    int t = threadIdx.x;
    w0[t] = W[t * 2 + 0];
    w1[t] = W[t * 2 + 1];
    __syncthreads();

    int lane = t & 31, wid = t >> 5;
    int row = blockIdx.x * 8 + wid;
    float s0 = 0.f, s1 = 0.f, q0 = 0.f, q1 = 0.f;
    if (row < N_NODES) {
        const float* h = Hid + (size_t)row * HID2;
        float a0 = 0.f, a1 = 0.f;
#pragma unroll
        for (int i = 0; i < 8; i++) {
            float v = h[lane + 32 * i];
            a0 = fmaf(v, w0[lane + 32 * i], a0);
            a1 = fmaf(v, w1[lane + 32 * i], a1);
        }
#pragma unroll
        for (int o = 16; o; o >>= 1) {
            a0 += __shfl_xor_sync(0xffffffffu, a0, o);
            a1 += __shfl_xor_sync(0xffffffffu, a1, o);
        }
        if (lane == 0) {
            a0 = fmaxf(a0 + bias[0], 0.f);
            a1 = fmaxf(a1 + bias[1], 0.f);
            g_out2[(size_t)row * 2 + 0] = a0;
            g_out2[(size_t)row * 2 + 1] = a1;
            s0 = a0; s1 = a1; q0 = a0 * a0; q1 = a1 * a1;
        }
    }
    if (lane == 0) { red[wid][0] = s0; red[wid][1] = s1; red[wid][2] = q0; red[wid][3] = q1; }
    __syncthreads();
    if (t < 4) {
        float acc = 0.f;
#pragma unroll
        for (int wI = 0; wI < 8; wI++) acc += red[wI][t];
        atomicAdd(&g_bn2[t], acc);
    }
}

__global__ void k_bn2_fin(const float* __restrict__ gamma2, const float* __restrict__ beta2) {
    int c = threadIdx.x;
    if (c >= 2) return;
    const float invN = 1.0f / (float)N_NODES;
    float mean = g_bn2[c] * invN;
    float var  = g_bn2[2 + c] * invN - mean * mean;
    float sc   = gamma2[c] * rsqrtf(var + BN_EPS);
    g_ss2[c]     = sc;
    g_ss2[2 + c] = beta2[c] - mean * sc;
}

__global__ void k_bn2_norm(float* __restrict__ out) {
    int r = blockIdx.x * blockDim.x + threadIdx.x;
    if (r >= N_NODES) return;
    float2 v = ((const float2*)g_out2)[r];
    float2 o;
    o.x = fmaf(v.x, g_ss2[0], g_ss2[2]);
    o.y = fmaf(v.y, g_ss2[1], g_ss2[3]);
    ((float2*)out)[r] = o;
}

// ---------------- launch ----------------
extern "C" void kernel_launch(void* const* d_in, const int* in_sizes, int n_in,
                              void* d_out, int out_size) {
    const float* x      = (const float*)d_in[0];
    const int*   eidx   = (const int*)d_in[1];
    const float* ew     = (const float*)d_in[3];
    const float* W1a    = (const float*)d_in[4];
    const float* b1a    = (const float*)d_in[5];
    const float* W1b    = (const float*)d_in[6];
    const float* b1b    = (const float*)d_in[7];
    const float* gamma1 = (const float*)d_in[8];
    const float* beta1  = (const float*)d_in[9];
    const float* W2a    = (const float*)d_in[10];
    const float* b2a    = (const float*)d_in[11];
    const float* W2b    = (const float*)d_in[12];
    const float* b2b    = (const float*)d_in[13];
    const float* gamma2 = (const float*)d_in[14];
    const float* beta2  = (const float*)d_in[15];

    const int nEdges = in_sizes[1] / 2;
    const int* src = eidx;
    const int* dst = eidx + nEdges;

    float *hid, *pre, *h1;
    __nv_bfloat16 *A2, *B2;
    cudaGetSymbolAddress((void**)&hid, g_hid);
    cudaGetSymbolAddress((void**)&pre, g_pre);
    cudaGetSymbolAddress((void**)&h1,  g_h1);
    cudaGetSymbolAddress((void**)&A2,  g_A2);
    cudaGetSymbolAddress((void**)&B2,  g_B2);

    cudaFuncSetAttribute(k_mma, cudaFuncAttributeMaxDynamicSharedMemorySize, 65536);

    const int n4 = N_NODES * (DIM / 4);
    const int normBlocks = (n4 + 255) / 256;
    const int gatherBlocks = (MPAD * 32 + 255) / 256;   // one warp per node row
    const int convA256 = (MPAD * 128 + 255) / 256;

    // ---- CSR build (reused by both layers) ----
    k_prep<<<(N_NODES + 255) / 256, 256>>>();
    k_hist<<<1024, 256>>>(dst, nEdges);
    k_scan<<<1, 1024>>>();
    k_fill<<<1024, 256>>>(src, dst, ew, nEdges);

    // ---- layer 1 ----
    k_gather<<<gatherBlocks, 256>>>(x);                       // agg + split-bf16 -> A2
    k_convB<<<(DIM * HID2 + 255) / 256, 256>>>(W1a, DIM, HID2);
    {
        dim3 g(MTILES, 2);
        k_mma<<<g, 256, 65536>>>(A2, B2, b1a, hid, N_NODES, HID2, DIM);
    }
    k_convA<<<convA256, 256>>>(hid, N_NODES, HID2);
    k_convB<<<(HID2 * DIM + 255) / 256, 256>>>(W1b, HID2, DIM);
    {
        dim3 g(MTILES, 1);
        k_mma<<<g, 256, 65536>>>(A2, B2, b1b, pre, N_NODES, DIM, HID2);
    }
    k_bn1_reduce<<<512, 128>>>(pre);
    k_bn1_fin<<<1, 128>>>(gamma1, beta1);
    k_bn1_norm<<<normBlocks, 256>>>(pre);

    // ---- layer 2 ----
    k_gather<<<gatherBlocks, 256>>>(h1);                      // agg + split-bf16 -> A2
    k_convB<<<(DIM * HID2 + 255) / 256, 256>>>(W2a, DIM, HID2);
    {
        dim3 g(MTILES, 2);
        k_mma<<<g, 256, 65536>>>(A2, B2, b2a, hid, N_NODES, HID2, DIM);
    }
    k_gemm2b<<<(N_NODES + 7) / 8, 256>>>(hid, W2b, b2b);
    k_bn2_fin<<<1, 32>>>(gamma2, beta2);
    k_bn2_norm<<<(N_NODES + 255) / 256, 256>>>((float*)d_out);
}

// round 8
// speedup vs baseline: 2.0601x; 1.2143x over previous
#include <cuda_runtime.h>
#include <cuda_bf16.h>
#include <cstdint>

#define N_NODES 50000
#define N_EDGES 1600000
#define DIM 128
#define HID2 256
#define BN_EPS 1e-5f

#define MPAD 50048          // 391 * 128
#define MTILES 391

// ---------------- scratch (static device globals; no runtime alloc) ----------------
__device__ float g_pre[(size_t)N_NODES * DIM];
__device__ float g_out2[(size_t)N_NODES * 2];

__device__ __nv_bfloat16 g_A2[(size_t)MPAD * 512];   // gather out: [Mpad, 2*128] split-bf16 [hi|lo]
__device__ __nv_bfloat16 g_A3[(size_t)MPAD * 512];   // mma1 out:   [Mpad, 2*256] split-bf16 [hi|lo]
__device__ __nv_bfloat16 g_B2[(size_t)256 * 512];    // weights: [N, 2K] split-bf16 [hi|lo]

// CSR scratch
__device__ int   g_deg[N_NODES];
__device__ int   g_rowptr[N_NODES + 1];
__device__ int   g_cur[N_NODES];
__device__ uint2 g_edge[N_EDGES];                    // (src, weight bits), sorted by dst

__device__ __align__(16) float g_sum1[DIM];
__device__ __align__(16) float g_sq1[DIM];
__device__ __align__(16) float g_scale1[DIM];
__device__ __align__(16) float g_shift1[DIM];
__device__ float g_bn2[4];
__device__ float g_ss2[4];

// ---------------- helpers ----------------
__device__ __forceinline__ uint32_t smem_u32(const void* p) {
    uint32_t a;
    asm("{ .reg .u64 t; cvta.to.shared.u64 t, %1; cvt.u32.u64 %0, t; }" : "=r"(a) : "l"(p));
    return a;
}
#define SWZ128(off) ((off) ^ (((off) >> 3) & 0x70))

__device__ __forceinline__ void mma16816(float* c, const uint32_t* a, const uint32_t* b) {
    asm volatile("mma.sync.aligned.m16n8k16.row.col.f32.bf16.bf16.f32 "
        "{%0,%1,%2,%3}, {%4,%5,%6,%7}, {%8,%9}, {%0,%1,%2,%3};"
        : "+f"(c[0]), "+f"(c[1]), "+f"(c[2]), "+f"(c[3])
        : "r"(a[0]), "r"(a[1]), "r"(a[2]), "r"(a[3]), "r"(b[0]), "r"(b[1]));
}
#define LDSM4(r, addr) asm volatile("ldmatrix.sync.aligned.m8n8.x4.shared.b16 {%0,%1,%2,%3}, [%4];" \
    : "=r"((r)[0]), "=r"((r)[1]), "=r"((r)[2]), "=r"((r)[3]) : "r"(addr))
#define LDSM2(r, addr) asm volatile("ldmatrix.sync.aligned.m8n8.x2.shared.b16 {%0,%1}, [%2];" \
    : "=r"((r)[0]), "=r"((r)[1]) : "r"(addr))
#define CPASYNC16(dst, src) asm volatile("cp.async.cg.shared.global [%0], [%1], 16;" :: "r"(dst), "l"(src))

__device__ __forceinline__ uint32_t pack_hi2(float x, float y) {
    __nv_bfloat16 h0 = __float2bfloat16(x);
    __nv_bfloat16 h1 = __float2bfloat16(y);
    uint32_t r;
    asm("mov.b32 %0, {%1, %2};" : "=r"(r) : "h"(*(unsigned short*)&h0), "h"(*(unsigned short*)&h1));
    return r;
}
__device__ __forceinline__ uint32_t pack_lo2(float x, float y) {
    __nv_bfloat16 h0 = __float2bfloat16(x);
    __nv_bfloat16 h1 = __float2bfloat16(y);
    __nv_bfloat16 l0 = __float2bfloat16(x - __bfloat162float(h0));
    __nv_bfloat16 l1 = __float2bfloat16(y - __bfloat162float(h1));
    uint32_t r;
    asm("mov.b32 %0, {%1, %2};" : "=r"(r) : "h"(*(unsigned short*)&l0), "h"(*(unsigned short*)&l1));
    return r;
}

// ---------------- CSR build ----------------
__global__ void k_prep() {
    int i = blockIdx.x * blockDim.x + threadIdx.x;
    if (i < N_NODES) g_deg[i] = 0;
    if (i < 2 * N_NODES) g_out2[i] = 0.f;
    if (i < DIM) { g_sum1[i] = 0.f; g_sq1[i] = 0.f; }
    if (i < 4)   { g_bn2[i] = 0.f; }
}

__global__ void __launch_bounds__(256) k_hist(const int* __restrict__ dst, int nEdges) {
    int e = blockIdx.x * blockDim.x + threadIdx.x;
    if (e < nEdges) atomicAdd(&g_deg[dst[e]], 1);
}

__global__ void __launch_bounds__(1024) k_scan() {
    __shared__ int wsum[32];
    __shared__ int carry;
    int t = threadIdx.x, lane = t & 31, w = t >> 5;
    if (t == 0) { carry = 0; g_rowptr[0] = 0; }
    __syncthreads();
    for (int base = 0; base < N_NODES; base += 1024) {
        int i = base + t;
        int v = (i < N_NODES) ? g_deg[i] : 0;
        int s = v;
#pragma unroll
        for (int off = 1; off < 32; off <<= 1) {
            int u = __shfl_up_sync(0xffffffffu, s, off);
            if (lane >= off) s += u;
        }
        if (lane == 31) wsum[w] = s;
        __syncthreads();
        if (w == 0) {
            int ws = wsum[lane];
#pragma unroll
            for (int off = 1; off < 32; off <<= 1) {
                int u = __shfl_up_sync(0xffffffffu, ws, off);
                if (lane >= off) ws += u;
            }
            wsum[lane] = ws;
        }
        __syncthreads();
        int prefix = carry + (w > 0 ? wsum[w - 1] : 0);
        int inc = prefix + s;
        if (i < N_NODES) { g_rowptr[i + 1] = inc; g_cur[i] = inc - v; }
        int total = wsum[31];
        __syncthreads();
        if (t == 0) carry += total;
        __syncthreads();
    }
}

__global__ void __launch_bounds__(256) k_fill(const int* __restrict__ src,
                                              const int* __restrict__ dst,
                                              const float* __restrict__ wgt,
                                              int nEdges) {
    int e = blockIdx.x * blockDim.x + threadIdx.x;
    if (e >= nEdges) return;
    int d = dst[e];
    int pos = atomicAdd(&g_cur[d], 1);
    g_edge[pos] = make_uint2((uint32_t)src[e], __float_as_uint(wgt[e]));
}

// ---------------- fused gather + (optional BN affine) + split-bf16 convert ----------------
// One warp per node row: raw = feat[n] + sum_e w_e * feat[src_e].
// BN_MODE: acc = scale * raw + shift * (1 + sum_w)   (folds h1 = pre*sc+sh through the gather)
template<bool BN_MODE>
__global__ void __launch_bounds__(256) k_gather(const float* __restrict__ feat) {
    int lane = threadIdx.x & 31;
    int node = (blockIdx.x * blockDim.x + threadIdx.x) >> 5;
    if (node >= MPAD) return;
    uint32_t* o = (uint32_t*)g_A2;
    size_t base = (size_t)node * 128;
    if (node >= N_NODES) {
        ((uint2*)(o + base))[lane] = make_uint2(0u, 0u);
        ((uint2*)(o + base + 64))[lane] = make_uint2(0u, 0u);
        return;
    }
    const float4* f4 = (const float4*)feat;
    float4 acc = f4[(size_t)node * 32 + lane];
    float sumw = 0.f;
    int j = g_rowptr[node];
    int end = g_rowptr[node + 1];
    for (; j + 4 <= end; j += 4) {
        uint2 e0 = g_edge[j + 0];
        uint2 e1 = g_edge[j + 1];
        uint2 e2 = g_edge[j + 2];
        uint2 e3 = g_edge[j + 3];
        float4 v0 = f4[(size_t)e0.x * 32 + lane];
        float4 v1 = f4[(size_t)e1.x * 32 + lane];
        float4 v2 = f4[(size_t)e2.x * 32 + lane];
        float4 v3 = f4[(size_t)e3.x * 32 + lane];
        float w0 = __uint_as_float(e0.y), w1 = __uint_as_float(e1.y);
        float w2 = __uint_as_float(e2.y), w3 = __uint_as_float(e3.y);
        if (BN_MODE) sumw += (w0 + w1) + (w2 + w3);
        acc.x = fmaf(w0, v0.x, acc.x); acc.y = fmaf(w0, v0.y, acc.y);
        acc.z = fmaf(w0, v0.z, acc.z); acc.w = fmaf(w0, v0.w, acc.w);
        acc.x = fmaf(w1, v1.x, acc.x); acc.y = fmaf(w1, v1.y, acc.y);
        acc.z = fmaf(w1, v1.z, acc.z); acc.w = fmaf(w1, v1.w, acc.w);
        acc.x = fmaf(w2, v2.x, acc.x); acc.y = fmaf(w2, v2.y, acc.y);
        acc.z = fmaf(w2, v2.z, acc.z); acc.w = fmaf(w2, v2.w, acc.w);
        acc.x = fmaf(w3, v3.x, acc.x); acc.y = fmaf(w3, v3.y, acc.y);
        acc.z = fmaf(w3, v3.z, acc.z); acc.w = fmaf(w3, v3.w, acc.w);
    }
    for (; j < end; j++) {
        uint2 e = g_edge[j];
        float w = __uint_as_float(e.y);
        if (BN_MODE) sumw += w;
        float4 v = f4[(size_t)e.x * 32 + lane];
        acc.x = fmaf(w, v.x, acc.x); acc.y = fmaf(w, v.y, acc.y);
        acc.z = fmaf(w, v.z, acc.z); acc.w = fmaf(w, v.w, acc.w);
    }
    if (BN_MODE) {
        float4 sc = ((const float4*)g_scale1)[lane];
        float4 sh = ((const float4*)g_shift1)[lane];
        float m = 1.f + sumw;
        acc.x = fmaf(sc.x, acc.x, sh.x * m);
        acc.y = fmaf(sc.y, acc.y, sh.y * m);
        acc.z = fmaf(sc.z, acc.z, sh.z * m);
        acc.w = fmaf(sc.w, acc.w, sh.w * m);
    }
    uint2 hi = make_uint2(pack_hi2(acc.x, acc.y), pack_hi2(acc.z, acc.w));
    uint2 lo = make_uint2(pack_lo2(acc.x, acc.y), pack_lo2(acc.z, acc.w));
    *(uint2*)(o + base + 2 * lane) = hi;
    *(uint2*)(o + base + 64 + 2 * lane) = lo;
}

// W [K,N] fp32 -> B2 [N, 2K] bf16: [hi | lo]
__global__ void k_convB(const float* __restrict__ W, int K, int N) {
    int i = blockIdx.x * blockDim.x + threadIdx.x;
    if (i >= N * K) return;
    int n = i / K, k = i % K;
    float v = W[(size_t)k * N + n];
    __nv_bfloat16 h = __float2bfloat16(v);
    __nv_bfloat16 l = __float2bfloat16(v - __bfloat162float(h));
    size_t base = (size_t)n * 2 * K;
    g_B2[base + k]     = h;
    g_B2[base + K + k] = l;
}

// ---------------- HMMA bf16 GEMM with fused epilogues ----------------
// MODE 0: C = relu(A@B^T + bias) fp32, stride Ntot
// MODE 1: split-bf16 [hi|lo] write into Cu32 (row stride 256 u32), Ntot must be 256
// MODE 2: fused gemv: atomicAdd partials of relu(A@B^T + bias) @ w2b[256,2] into C (g_out2)
template<int MODE>
__global__ void __launch_bounds__(256, 2)
k_mma(const __nv_bfloat16* __restrict__ A2, const __nv_bfloat16* __restrict__ B2,
      const float* __restrict__ bias, float* __restrict__ C,
      const float* __restrict__ w2b, int M, int Ntot, int K) {
    extern __shared__ __align__(1024) uint8_t sm[];
    const int t = threadIdx.x;
    const int lane = t & 31;
    const int wid = t >> 5;
    const int wm = wid >> 2;
    const int wn = wid & 3;
    const int bm = blockIdx.x * 128;
    const int bn = blockIdx.y * 128;
    const int K2 = K * 2;
    const uint32_t smbase = smem_u32(sm);

    const int lrow = t >> 3;
    const int ls16 = t & 7;
    const int cps = K >> 6;
    const int total = 3 * cps;

#define LOADCHUNK(c, buf) do {                                                        \
        int s_ = (c) / cps, ck_ = (c) % cps;                                          \
        int aoff_ = (s_ == 1 ? K : 0) + ck_ * 64;                                     \
        int boff_ = (s_ == 2 ? K : 0) + ck_ * 64;                                     \
        uint32_t sA_ = smbase + (buf) * 32768;                                        \
        uint32_t sB_ = sA_ + 16384;                                                   \
        _Pragma("unroll")                                                             \
        for (int i_ = 0; i_ < 4; i_++) {                                              \
            int row_ = lrow + 32 * i_;                                                \
            uint32_t da_ = sA_ + SWZ128(row_ * 128 + ls16 * 16);                      \
            const void* ga_ = A2 + (size_t)(bm + row_) * K2 + aoff_ + ls16 * 8;       \
            CPASYNC16(da_, ga_);                                                      \
            uint32_t db_ = sB_ + SWZ128(row_ * 128 + ls16 * 16);                      \
            const void* gb_ = B2 + (size_t)(bn + row_) * K2 + boff_ + ls16 * 8;       \
            CPASYNC16(db_, gb_);                                                      \
        }                                                                             \
        asm volatile("cp.async.commit_group;");                                       \
    } while (0)

    float acc[4][4][4] = {};

    LOADCHUNK(0, 0);
    for (int c = 0; c < total; c++) {
        if (c + 1 < total) {
            LOADCHUNK(c + 1, (c + 1) & 1);
            asm volatile("cp.async.wait_group 1;");
        } else {
            asm volatile("cp.async.wait_group 0;");
        }
        __syncthreads();
        uint32_t sA = smbase + (c & 1) * 32768;
        uint32_t sB = sA + 16384;
        const int t16 = lane & 15;
#pragma unroll
        for (int ks = 0; ks < 4; ks++) {
            uint32_t afr[4][4];
            uint32_t bfr[4][2];
#pragma unroll
            for (int mi = 0; mi < 4; mi++) {
                int row = wm * 64 + mi * 16 + (lane & 15);
                uint32_t addr = sA + SWZ128(row * 128 + ks * 32 + ((lane >> 4) << 4));
                LDSM4(afr[mi], addr);
            }
#pragma unroll
            for (int ni = 0; ni < 4; ni++) {
                int row = wn * 32 + ni * 8 + (t16 & 7);
                uint32_t addr = sB + SWZ128(row * 128 + ks * 32 + ((t16 >> 3) << 4));
                LDSM2(bfr[ni], addr);
            }
#pragma unroll
            for (int mi = 0; mi < 4; mi++)
#pragma unroll
                for (int ni = 0; ni < 4; ni++)
                    mma16816(acc[mi][ni], afr[mi], bfr[ni]);
        }
        __syncthreads();
    }

    if (MODE == 0 || MODE == 1) {
#pragma unroll
        for (int mi = 0; mi < 4; mi++) {
            int r0 = bm + wm * 64 + mi * 16 + (lane >> 2);
            int r1 = r0 + 8;
#pragma unroll
            for (int ni = 0; ni < 4; ni++) {
                int col = bn + wn * 32 + ni * 8 + (lane & 3) * 2;
                float2 bv = *(const float2*)(bias + col);
                float v00 = fmaxf(acc[mi][ni][0] + bv.x, 0.f);
                float v01 = fmaxf(acc[mi][ni][1] + bv.y, 0.f);
                float v10 = fmaxf(acc[mi][ni][2] + bv.x, 0.f);
                float v11 = fmaxf(acc[mi][ni][3] + bv.y, 0.f);
                if (MODE == 0) {
                    if (r0 < M) *(float2*)(C + (size_t)r0 * Ntot + col) = make_float2(v00, v01);
                    if (r1 < M) *(float2*)(C + (size_t)r1 * Ntot + col) = make_float2(v10, v11);
                } else {
                    // split-bf16 rows: [hi(128 u32) | lo(128 u32)], stride 256 u32
                    uint32_t* o = (uint32_t*)C;
                    int ci = col >> 1;
                    o[(size_t)r0 * 256 + ci]       = pack_hi2(v00, v01);
                    o[(size_t)r0 * 256 + 128 + ci] = pack_lo2(v00, v01);
                    o[(size_t)r1 * 256 + ci]       = pack_hi2(v10, v11);
                    o[(size_t)r1 * 256 + 128 + ci] = pack_lo2(v10, v11);
                }
            }
        }
    } else {
        // MODE 2: fused 256->2 gemv with b2a bias + relu, partials into C (g_out2)
#pragma unroll
        for (int mi = 0; mi < 4; mi++) {
            int r0 = bm + wm * 64 + mi * 16 + (lane >> 2);
            int r1 = r0 + 8;
            float p00 = 0.f, p01 = 0.f, p10 = 0.f, p11 = 0.f;
#pragma unroll
            for (int ni = 0; ni < 4; ni++) {
                int col = bn + wn * 32 + ni * 8 + (lane & 3) * 2;
                float2 bv = *(const float2*)(bias + col);
                float h0 = fmaxf(acc[mi][ni][0] + bv.x, 0.f);
                float h1 = fmaxf(acc[mi][ni][1] + bv.y, 0.f);
                float h2 = fmaxf(acc[mi][ni][2] + bv.x, 0.f);
                float h3 = fmaxf(acc[mi][ni][3] + bv.y, 0.f);
                float2 wv0 = *(const float2*)(w2b + col * 2);
                float2 wv1 = *(const float2*)(w2b + (col + 1) * 2);
                p00 = fmaf(h0, wv0.x, fmaf(h1, wv1.x, p00));
                p01 = fmaf(h0, wv0.y, fmaf(h1, wv1.y, p01));
                p10 = fmaf(h2, wv0.x, fmaf(h3, wv1.x, p10));
                p11 = fmaf(h2, wv0.y, fmaf(h3, wv1.y, p11));
            }
#pragma unroll
            for (int off = 1; off <= 2; off <<= 1) {
                p00 += __shfl_xor_sync(0xffffffffu, p00, off);
                p01 += __shfl_xor_sync(0xffffffffu, p01, off);
                p10 += __shfl_xor_sync(0xffffffffu, p10, off);
                p11 += __shfl_xor_sync(0xffffffffu, p11, off);
            }
            if ((lane & 3) == 0) {
                if (r0 < M) {
                    atomicAdd(&C[(size_t)r0 * 2 + 0], p00);
                    atomicAdd(&C[(size_t)r0 * 2 + 1], p01);
                }
                if (r1 < M) {
                    atomicAdd(&C[(size_t)r1 * 2 + 0], p10);
                    atomicAdd(&C[(size_t)r1 * 2 + 1], p11);
                }
            }
        }
    }
#undef LOADCHUNK
}

// ---------------- BN1 ----------------
__global__ void __launch_bounds__(128) k_bn1_reduce(const float* __restrict__ pre) {
    int c = threadIdx.x;
    float s = 0.f, q = 0.f;
    for (int r = blockIdx.x; r < N_NODES; r += gridDim.x) {
        float v = pre[(size_t)r * DIM + c];
        s += v; q += v * v;
    }
    atomicAdd(&g_sum1[c], s);
    atomicAdd(&g_sq1[c], q);
}

__global__ void k_bn1_fin(const float* __restrict__ gamma, const float* __restrict__ beta) {
    int c = threadIdx.x;
    if (c >= DIM) return;
    const float invN = 1.0f / (float)N_NODES;
    float mean = g_sum1[c] * invN;
    float var  = g_sq1[c] * invN - mean * mean;
    float sc   = gamma[c] * rsqrtf(var + BN_EPS);
    g_scale1[c] = sc;
    g_shift1[c] = beta[c] - mean * sc;
}

// ---------------- BN2: bias+relu on atomic partials, then stats ----------------
__global__ void __launch_bounds__(256) k_bn2pre(const float* __restrict__ b2b) {
    __shared__ float red[8][4];
    int t = threadIdx.x;
    int lane = t & 31, wid = t >> 5;
    int r = blockIdx.x * 256 + t;
    float s0 = 0.f, s1 = 0.f, q0 = 0.f, q1 = 0.f;
    if (r < N_NODES) {
        float2 v = ((float2*)g_out2)[r];
        v.x = fmaxf(v.x + b2b[0], 0.f);
        v.y = fmaxf(v.y + b2b[1], 0.f);
        ((float2*)g_out2)[r] = v;
        s0 = v.x; s1 = v.y; q0 = v.x * v.x; q1 = v.y * v.y;
    }
#pragma unroll
    for (int off = 16; off; off >>= 1) {
        s0 += __shfl_xor_sync(0xffffffffu, s0, off);
        s1 += __shfl_xor_sync(0xffffffffu, s1, off);
        q0 += __shfl_xor_sync(0xffffffffu, q0, off);
        q1 += __shfl_xor_sync(0xffffffffu, q1, off);
    }
    if (lane == 0) { red[wid][0] = s0; red[wid][1] = s1; red[wid][2] = q0; red[wid][3] = q1; }
    __syncthreads();
    if (t < 4) {
        float acc = 0.f;
#pragma unroll
        for (int wI = 0; wI < 8; wI++) acc += red[wI][t];
        atomicAdd(&g_bn2[t], acc);
    }
}

__global__ void k_bn2_fin(const float* __restrict__ gamma2, const float* __restrict__ beta2) {
    int c = threadIdx.x;
    if (c >= 2) return;
    const float invN = 1.0f / (float)N_NODES;
    float mean = g_bn2[c] * invN;
    float var  = g_bn2[2 + c] * invN - mean * mean;
    float sc   = gamma2[c] * rsqrtf(var + BN_EPS);
    g_ss2[c]     = sc;
    g_ss2[2 + c] = beta2[c] - mean * sc;
}

__global__ void k_bn2_norm(float* __restrict__ out) {
    int r = blockIdx.x * blockDim.x + threadIdx.x;
    if (r >= N_NODES) return;
    float2 v = ((const float2*)g_out2)[r];
    float2 o;
    o.x = fmaf(v.x, g_ss2[0], g_ss2[2]);
    o.y = fmaf(v.y, g_ss2[1], g_ss2[3]);
    ((float2*)out)[r] = o;
}

// ---------------- launch ----------------
extern "C" void kernel_launch(void* const* d_in, const int* in_sizes, int n_in,
                              void* d_out, int out_size) {
    const float* x      = (const float*)d_in[0];
    const int*   eidx   = (const int*)d_in[1];
    const float* ew     = (const float*)d_in[3];
    const float* W1a    = (const float*)d_in[4];
    const float* b1a    = (const float*)d_in[5];
    const float* W1b    = (const float*)d_in[6];
    const float* b1b    = (const float*)d_in[7];
    const float* gamma1 = (const float*)d_in[8];
    const float* beta1  = (const float*)d_in[9];
    const float* W2a    = (const float*)d_in[10];
    const float* b2a    = (const float*)d_in[11];
    const float* W2b    = (const float*)d_in[12];
    const float* b2b    = (const float*)d_in[13];
    const float* gamma2 = (const float*)d_in[14];
    const float* beta2  = (const float*)d_in[15];

    const int nEdges = in_sizes[1] / 2;
    const int* src = eidx;
    const int* dst = eidx + nEdges;

    float *pre, *out2;
    __nv_bfloat16 *A2, *A3, *B2;
    cudaGetSymbolAddress((void**)&pre, g_pre);
    cudaGetSymbolAddress((void**)&out2, g_out2);
    cudaGetSymbolAddress((void**)&A2,  g_A2);
    cudaGetSymbolAddress((void**)&A3,  g_A3);
    cudaGetSymbolAddress((void**)&B2,  g_B2);

    cudaFuncSetAttribute(k_mma<0>, cudaFuncAttributeMaxDynamicSharedMemorySize, 65536);
    cudaFuncSetAttribute(k_mma<1>, cudaFuncAttributeMaxDynamicSharedMemorySize, 65536);
    cudaFuncSetAttribute(k_mma<2>, cudaFuncAttributeMaxDynamicSharedMemorySize, 65536);

    const int gatherBlocks = (MPAD * 32 + 255) / 256;
    const int edgeBlocks = (nEdges + 255) / 256;

    // ---- CSR build (reused by both layers) ----
    k_prep<<<(2 * N_NODES + 255) / 256, 256>>>();
    k_hist<<<edgeBlocks, 256>>>(dst, nEdges);
    k_scan<<<1, 1024>>>();
    k_fill<<<edgeBlocks, 256>>>(src, dst, ew, nEdges);

    // ---- layer 1 ----
    k_convB<<<(DIM * HID2 + 255) / 256, 256>>>(W1a, DIM, HID2);
    k_gather<false><<<gatherBlocks, 256>>>(x);
    {
        dim3 g(MTILES, 2);   // mma1: relu(A2@W1a + b1a) -> A3 (split-bf16)
        k_mma<1><<<g, 256, 65536>>>(A2, B2, b1a, (float*)A3, nullptr, N_NODES, HID2, DIM);
    }
    k_convB<<<(HID2 * DIM + 255) / 256, 256>>>(W1b, HID2, DIM);
    {
        dim3 g(MTILES, 1);   // mma2: relu(A3@W1b + b1b) -> pre (fp32)
        k_mma<0><<<g, 256, 65536>>>(A3, B2, b1b, pre, nullptr, N_NODES, DIM, HID2);
    }
    k_bn1_reduce<<<512, 128>>>(pre);
    k_bn1_fin<<<1, 128>>>(gamma1, beta1);

    // ---- layer 2 ----
    k_gather<true><<<gatherBlocks, 256>>>(pre);     // BN affine folded into gather
    k_convB<<<(DIM * HID2 + 255) / 256, 256>>>(W2a, DIM, HID2);
    {
        dim3 g(MTILES, 2);   // mma3: fused gemv -> out2 partials
        k_mma<2><<<g, 256, 65536>>>(A2, B2, b2a, out2, W2b, N_NODES, HID2, DIM);
    }
    k_bn2pre<<<(N_NODES + 255) / 256, 256>>>(b2b);
    k_bn2_fin<<<1, 32>>>(gamma2, beta2);
    k_bn2_norm<<<(N_NODES + 255) / 256, 256>>>((float*)d_out);
}

// round 12
// speedup vs baseline: 2.2100x; 1.0728x over previous
#include <cuda_runtime.h>
#include <cuda_bf16.h>
#include <cuda_fp16.h>
#include <cstdint>

#define N_NODES 50000
#define N_EDGES 1600000
#define DIM 128
#define HID2 256
#define BN_EPS 1e-5f

#define MPAD 50048          // 391 * 128
#define MTILES 391

// ---------------- scratch (static device globals; no runtime alloc) ----------------
__device__ __align__(16) float g_pre[(size_t)N_NODES * DIM];
__device__ __align__(16) float g_out2[(size_t)N_NODES * 2];
__device__ __align__(16) __half g_xh[(size_t)N_NODES * DIM];        // fp16 copy of x

__device__ __align__(16) __nv_bfloat16 g_A2[(size_t)MPAD * 256];    // gather out: [Mpad, 2*128] split-bf16
__device__ __align__(16) __nv_bfloat16 g_A3[(size_t)MPAD * 512];    // mma1 out:   [Mpad, 2*256] split-bf16
__device__ __align__(16) __nv_bfloat16 g_B2a[(size_t)256 * 256];    // W1a: [256, 2*128]
__device__ __align__(16) __nv_bfloat16 g_B2b[(size_t)128 * 512];    // W1b: [128, 2*256]
__device__ __align__(16) __nv_bfloat16 g_B2c[(size_t)256 * 256];    // W2a: [256, 2*128]

// CSR scratch
__device__ int   g_deg[N_NODES];
__device__ int   g_rowptr[N_NODES + 1];
__device__ int   g_cur[N_NODES];
__device__ uint2 g_edge[N_EDGES];

__device__ __align__(16) float g_sum1[DIM];
__device__ __align__(16) float g_sq1[DIM];
__device__ __align__(16) float g_scale1[DIM];
__device__ __align__(16) float g_shift1[DIM];
__device__ float g_bn2[4];
__device__ float g_ss2[4];

// ---------------- helpers ----------------
__device__ __forceinline__ uint32_t smem_u32(const void* p) {
    uint32_t a;
    asm("{ .reg .u64 t; cvta.to.shared.u64 t, %1; cvt.u32.u64 %0, t; }" : "=r"(a) : "l"(p));
    return a;
}
#define SWZ128(off) ((off) ^ (((off) >> 3) & 0x70))

__device__ __forceinline__ void mma16816(float* c, const uint32_t* a, const uint32_t* b) {
    asm volatile("mma.sync.aligned.m16n8k16.row.col.f32.bf16.bf16.f32 "
        "{%0,%1,%2,%3}, {%4,%5,%6,%7}, {%8,%9}, {%0,%1,%2,%3};"
        : "+f"(c[0]), "+f"(c[1]), "+f"(c[2]), "+f"(c[3])
        : "r"(a[0]), "r"(a[1]), "r"(a[2]), "r"(a[3]), "r"(b[0]), "r"(b[1]));
}
#define LDSM4(r, addr) asm volatile("ldmatrix.sync.aligned.m8n8.x4.shared.b16 {%0,%1,%2,%3}, [%4];" \
    : "=r"((r)[0]), "=r"((r)[1]), "=r"((r)[2]), "=r"((r)[3]) : "r"(addr))
#define LDSM2(r, addr) asm volatile("ldmatrix.sync.aligned.m8n8.x2.shared.b16 {%0,%1}, [%2];" \
    : "=r"((r)[0]), "=r"((r)[1]) : "r"(addr))
#define CPASYNC16(dst, src) asm volatile("cp.async.cg.shared.global [%0], [%1], 16;" :: "r"(dst), "l"(src))

__device__ __forceinline__ uint32_t pack_hi2(float x, float y) {
    __nv_bfloat16 h0 = __float2bfloat16(x);
    __nv_bfloat16 h1 = __float2bfloat16(y);
    uint32_t r;
    asm("mov.b32 %0, {%1, %2};" : "=r"(r) : "h"(*(unsigned short*)&h0), "h"(*(unsigned short*)&h1));
    return r;
}
__device__ __forceinline__ uint32_t pack_lo2(float x, float y) {
    __nv_bfloat16 h0 = __float2bfloat16(x);
    __nv_bfloat16 h1 = __float2bfloat16(y);
    __nv_bfloat16 l0 = __float2bfloat16(x - __bfloat162float(h0));
    __nv_bfloat16 l1 = __float2bfloat16(y - __bfloat162float(h1));
    uint32_t r;
    asm("mov.b32 %0, {%1, %2};" : "=r"(r) : "h"(*(unsigned short*)&l0), "h"(*(unsigned short*)&l1));
    return r;
}

// ---------------- fused setup: x->fp16, 3 weight splits, zeroing ----------------
__device__ __forceinline__ void convB_elem(const float* __restrict__ W, __nv_bfloat16* __restrict__ out,
                                           int j, int K, int N) {
    int n = j / K, k = j % K;
    float v = W[(size_t)k * N + n];
    __nv_bfloat16 h = __float2bfloat16(v);
    __nv_bfloat16 l = __float2bfloat16(v - __bfloat162float(h));
    size_t base = (size_t)n * 2 * K;
    out[base + k]     = h;
    out[base + K + k] = l;
}

#define CONVX_N (N_NODES * DIM / 4)   // 1,600,000 float4 quads

__global__ void __launch_bounds__(256) k_convAll(const float* __restrict__ x,
                                                 const float* __restrict__ W1a,
                                                 const float* __restrict__ W1b,
                                                 const float* __restrict__ W2a) {
    int i = blockIdx.x * blockDim.x + threadIdx.x;
    if (i < CONVX_N) {
        float4 v = ((const float4*)x)[i];
        __half2 h0 = __floats2half2_rn(v.x, v.y);
        __half2 h1 = __floats2half2_rn(v.z, v.w);
        uint2 o;
        o.x = *(uint32_t*)&h0;
        o.y = *(uint32_t*)&h1;
        ((uint2*)g_xh)[i] = o;
        return;
    }
    i -= CONVX_N;
    if (i < DIM * HID2) { convB_elem(W1a, g_B2a, i, DIM, HID2); return; }
    i -= DIM * HID2;
    if (i < HID2 * DIM) { convB_elem(W1b, g_B2b, i, HID2, DIM); return; }
    i -= HID2 * DIM;
    if (i < DIM * HID2) { convB_elem(W2a, g_B2c, i, DIM, HID2); return; }
    i -= DIM * HID2;
    if (i < N_NODES) { g_deg[i] = 0; return; }
    i -= N_NODES;
    if (i < N_NODES / 2) { ((float4*)g_out2)[i] = make_float4(0.f, 0.f, 0.f, 0.f); return; }
    i -= N_NODES / 2;
    if (i < DIM) { g_sum1[i] = 0.f; g_sq1[i] = 0.f; return; }
    i -= DIM;
    if (i < 4) g_bn2[i] = 0.f;
}
#define CONVALL_ITEMS (CONVX_N + 3 * DIM * HID2 + N_NODES + N_NODES / 2 + DIM + 4)

// ---------------- CSR build ----------------
__global__ void __launch_bounds__(256) k_hist(const int* __restrict__ dst, int nE4, int nEdges) {
    int i = blockIdx.x * blockDim.x + threadIdx.x;
    if (i < nE4) {
        int4 d = ((const int4*)dst)[i];
        atomicAdd(&g_deg[d.x], 1);
        atomicAdd(&g_deg[d.y], 1);
        atomicAdd(&g_deg[d.z], 1);
        atomicAdd(&g_deg[d.w], 1);
    } else if (i == nE4) {
        for (int e = nE4 * 4; e < nEdges; e++) atomicAdd(&g_deg[dst[e]], 1);
    }
}

__global__ void __launch_bounds__(1024) k_scan() {
    __shared__ int wsum[32];
    __shared__ int carry;
    int t = threadIdx.x, lane = t & 31, w = t >> 5;
    if (t == 0) { carry = 0; g_rowptr[0] = 0; }
    __syncthreads();
    for (int base = 0; base < N_NODES; base += 1024) {
        int i = base + t;
        int v = (i < N_NODES) ? g_deg[i] : 0;
        int s = v;
#pragma unroll
        for (int off = 1; off < 32; off <<= 1) {
            int u = __shfl_up_sync(0xffffffffu, s, off);
            if (lane >= off) s += u;
        }
        if (lane == 31) wsum[w] = s;
        __syncthreads();
        if (w == 0) {
            int ws = wsum[lane];
#pragma unroll
            for (int off = 1; off < 32; off <<= 1) {
                int u = __shfl_up_sync(0xffffffffu, ws, off);
                if (lane >= off) ws += u;
            }
            wsum[lane] = ws;
        }
        __syncthreads();
        int prefix = carry + (w > 0 ? wsum[w - 1] : 0);
        int inc = prefix + s;
        if (i < N_NODES) { g_rowptr[i + 1] = inc; g_cur[i] = inc - v; }
        int total = wsum[31];
        __syncthreads();
        if (t == 0) carry += total;
        __syncthreads();
    }
}

__global__ void __launch_bounds__(256) k_fill(const int* __restrict__ src,
                                              const int* __restrict__ dst,
                                              const float* __restrict__ wgt,
                                              int nE4, int nEdges) {
    int i = blockIdx.x * blockDim.x + threadIdx.x;
    if (i < nE4) {
        int4 s = ((const int4*)src)[i];
        int4 d = ((const int4*)dst)[i];
        float4 w = ((const float4*)wgt)[i];
        int p0 = atomicAdd(&g_cur[d.x], 1);
        int p1 = atomicAdd(&g_cur[d.y], 1);
        int p2 = atomicAdd(&g_cur[d.z], 1);
        int p3 = atomicAdd(&g_cur[d.w], 1);
        g_edge[p0] = make_uint2((uint32_t)s.x, __float_as_uint(w.x));
        g_edge[p1] = make_uint2((uint32_t)s.y, __float_as_uint(w.y));
        g_edge[p2] = make_uint2((uint32_t)s.z, __float_as_uint(w.z));
        g_edge[p3] = make_uint2((uint32_t)s.w, __float_as_uint(w.w));
    } else if (i == nE4) {
        for (int e = nE4 * 4; e < nEdges; e++) {
            int pos = atomicAdd(&g_cur[dst[e]], 1);
            g_edge[pos] = make_uint2((uint32_t)src[e], __float_as_uint(wgt[e]));
        }
    }
}

// ---------------- fused gather + (optional BN affine) + split-bf16 convert ----------------
// One warp per node row. Self term from f32; edge terms from fp16 (FP16E) or f32.
template<bool FP16E, bool BN_MODE>
__global__ void __launch_bounds__(256) k_gather(const float* __restrict__ f32,
                                                const __half* __restrict__ f16) {
    int lane = threadIdx.x & 31;
    int node = (blockIdx.x * blockDim.x + threadIdx.x) >> 5;
    if (node >= MPAD) return;
    uint32_t* o = (uint32_t*)g_A2;
    size_t base = (size_t)node * 128;
    if (node >= N_NODES) {
        ((uint2*)(o + base))[lane] = make_uint2(0u, 0u);
        ((uint2*)(o + base + 64))[lane] = make_uint2(0u, 0u);
        return;
    }
    const float4* f4 = (const float4*)f32;
    const uint2* h2 = (const uint2*)f16;    // fp16 row = 32 uint2
    float4 acc = f4[(size_t)node * 32 + lane];
    float sumw = 0.f;
    int j = g_rowptr[node];
    int end = g_rowptr[node + 1];

#define EDGE_TERM(E) do {                                                     \
        float w_ = __uint_as_float((E).y);                                    \
        if (BN_MODE) sumw += w_;                                              \
        if (FP16E) {                                                          \
            uint2 q_ = h2[(size_t)(E).x * 32 + lane];                         \
            float2 fa_ = __half22float2(*(__half2*)&q_.x);                    \
            float2 fb_ = __half22float2(*(__half2*)&q_.y);                    \
            acc.x = fmaf(w_, fa_.x, acc.x); acc.y = fmaf(w_, fa_.y, acc.y);   \
            acc.z = fmaf(w_, fb_.x, acc.z); acc.w = fmaf(w_, fb_.y, acc.w);   \
        } else {                                                              \
            float4 v_ = f4[(size_t)(E).x * 32 + lane];                        \
            acc.x = fmaf(w_, v_.x, acc.x); acc.y = fmaf(w_, v_.y, acc.y);     \
            acc.z = fmaf(w_, v_.z, acc.z); acc.w = fmaf(w_, v_.w, acc.w);     \
        }                                                                     \
    } while (0)

    for (; j + 4 <= end; j += 4) {
        uint2 e0 = g_edge[j + 0];
        uint2 e1 = g_edge[j + 1];
        uint2 e2 = g_edge[j + 2];
        uint2 e3 = g_edge[j + 3];
        EDGE_TERM(e0); EDGE_TERM(e1); EDGE_TERM(e2); EDGE_TERM(e3);
    }
    for (; j < end; j++) {
        uint2 e = g_edge[j];
        EDGE_TERM(e);
    }
#undef EDGE_TERM

    if (BN_MODE) {
        float4 sc = ((const float4*)g_scale1)[lane];
        float4 sh = ((const float4*)g_shift1)[lane];
        float m = 1.f + sumw;
        acc.x = fmaf(sc.x, acc.x, sh.x * m);
        acc.y = fmaf(sc.y, acc.y, sh.y * m);
        acc.z = fmaf(sc.z, acc.z, sh.z * m);
        acc.w = fmaf(sc.w, acc.w, sh.w * m);
    }
    uint2 hi = make_uint2(pack_hi2(acc.x, acc.y), pack_hi2(acc.z, acc.w));
    uint2 lo = make_uint2(pack_lo2(acc.x, acc.y), pack_lo2(acc.z, acc.w));
    *(uint2*)(o + base + 2 * lane) = hi;
    *(uint2*)(o + base + 64 + 2 * lane) = lo;
}

// ---------------- HMMA bf16 GEMM with fused epilogues ----------------
// MODE 0: C = relu(A@B^T + bias) fp32 (Ntot=128, grid.y=1) + fused BN1 stats atomics
// MODE 1: split-bf16 [hi|lo] write into C (row stride 256 u32)
// MODE 2: fused gemv: atomicAdd partials of relu(A@B^T + bias) @ w2b[256,2] into C
template<int MODE>
__global__ void __launch_bounds__(256, 2)
k_mma(const __nv_bfloat16* __restrict__ A2, const __nv_bfloat16* __restrict__ B2,
      const float* __restrict__ bias, float* __restrict__ C,
      const float* __restrict__ w2b, int M, int Ntot, int K) {
    extern __shared__ __align__(1024) uint8_t sm[];
    const int t = threadIdx.x;
    const int lane = t & 31;
    const int wid = t >> 5;
    const int wm = wid >> 2;
    const int wn = wid & 3;
    const int bm = blockIdx.x * 128;
    const int bn = blockIdx.y * 128;
    const int K2 = K * 2;
    const uint32_t smbase = smem_u32(sm);

    const int lrow = t >> 3;
    const int ls16 = t & 7;
    const int cps = K >> 6;
    const int total = 3 * cps;

#define LOADCHUNK(c, buf) do {                                                        \
        int s_ = (c) / cps, ck_ = (c) % cps;                                          \
        int aoff_ = (s_ == 1 ? K : 0) + ck_ * 64;                                     \
        int boff_ = (s_ == 2 ? K : 0) + ck_ * 64;                                     \
        uint32_t sA_ = smbase + (buf) * 32768;                                        \
        uint32_t sB_ = sA_ + 16384;                                                   \
        _Pragma("unroll")                                                             \
        for (int i_ = 0; i_ < 4; i_++) {                                              \
            int row_ = lrow + 32 * i_;                                                \
            uint32_t da_ = sA_ + SWZ128(row_ * 128 + ls16 * 16);                      \
            const void* ga_ = A2 + (size_t)(bm + row_) * K2 + aoff_ + ls16 * 8;       \
            CPASYNC16(da_, ga_);                                                      \
            uint32_t db_ = sB_ + SWZ128(row_ * 128 + ls16 * 16);                      \
            const void* gb_ = B2 + (size_t)(bn + row_) * K2 + boff_ + ls16 * 8;       \
            CPASYNC16(db_, gb_);                                                      \
        }                                                                             \
        asm volatile("cp.async.commit_group;");                                       \
    } while (0)

    float acc[4][4][4] = {};

    LOADCHUNK(0, 0);
    for (int c = 0; c < total; c++) {
        if (c + 1 < total) {
            LOADCHUNK(c + 1, (c + 1) & 1);
            asm volatile("cp.async.wait_group 1;");
        } else {
            asm volatile("cp.async.wait_group 0;");
        }
        __syncthreads();
        uint32_t sA = smbase + (c & 1) * 32768;
        uint32_t sB = sA + 16384;
        const int t16 = lane & 15;
#pragma unroll
        for (int ks = 0; ks < 4; ks++) {
            uint32_t afr[4][4];
            uint32_t bfr[4][2];
#pragma unroll
            for (int mi = 0; mi < 4; mi++) {
                int row = wm * 64 + mi * 16 + (lane & 15);
                uint32_t addr = sA + SWZ128(row * 128 + ks * 32 + ((lane >> 4) << 4));
                LDSM4(afr[mi], addr);
            }
#pragma unroll
            for (int ni = 0; ni < 4; ni++) {
                int row = wn * 32 + ni * 8 + (t16 & 7);
                uint32_t addr = sB + SWZ128(row * 128 + ks * 32 + ((t16 >> 3) << 4));
                LDSM2(bfr[ni], addr);
            }
#pragma unroll
            for (int mi = 0; mi < 4; mi++)
#pragma unroll
                for (int ni = 0; ni < 4; ni++)
                    mma16816(acc[mi][ni], afr[mi], bfr[ni]);
        }
        __syncthreads();
    }

    if (MODE == 0) {
        float bs[4][2] = {}, bq[4][2] = {};
#pragma unroll
        for (int mi = 0; mi < 4; mi++) {
            int r0 = bm + wm * 64 + mi * 16 + (lane >> 2);
            int r1 = r0 + 8;
#pragma unroll
            for (int ni = 0; ni < 4; ni++) {
                int col = bn + wn * 32 + ni * 8 + (lane & 3) * 2;
                float2 bv = *(const float2*)(bias + col);
                float v00 = fmaxf(acc[mi][ni][0] + bv.x, 0.f);
                float v01 = fmaxf(acc[mi][ni][1] + bv.y, 0.f);
                float v10 = fmaxf(acc[mi][ni][2] + bv.x, 0.f);
                float v11 = fmaxf(acc[mi][ni][3] + bv.y, 0.f);
                if (r0 < M) {
                    *(float2*)(C + (size_t)r0 * Ntot + col) = make_float2(v00, v01);
                    bs[ni][0] += v00; bs[ni][1] += v01;
                    bq[ni][0] += v00 * v00; bq[ni][1] += v01 * v01;
                }
                if (r1 < M) {
                    *(float2*)(C + (size_t)r1 * Ntot + col) = make_float2(v10, v11);
                    bs[ni][0] += v10; bs[ni][1] += v11;
                    bq[ni][0] += v10 * v10; bq[ni][1] += v11 * v11;
                }
            }
        }
        // fused BN1 stats: reduce over 8 row-lanes, atomics from lanes 0-3
#pragma unroll
        for (int ni = 0; ni < 4; ni++) {
            float s0 = bs[ni][0], s1 = bs[ni][1], q0 = bq[ni][0], q1 = bq[ni][1];
#pragma unroll
            for (int off = 4; off <= 16; off <<= 1) {
                s0 += __shfl_xor_sync(0xffffffffu, s0, off);
                s1 += __shfl_xor_sync(0xffffffffu, s1, off);
                q0 += __shfl_xor_sync(0xffffffffu, q0, off);
                q1 += __shfl_xor_sync(0xffffffffu, q1, off);
            }
            if (lane < 4) {
                int c0 = bn + wn * 32 + ni * 8 + lane * 2;
                atomicAdd(&g_sum1[c0], s0);
                atomicAdd(&g_sum1[c0 + 1], s1);
                atomicAdd(&g_sq1[c0], q0);
                atomicAdd(&g_sq1[c0 + 1], q1);
            }
        }
    } else if (MODE == 1) {
#pragma unroll
        for (int mi = 0; mi < 4; mi++) {
            int r0 = bm + wm * 64 + mi * 16 + (lane >> 2);
            int r1 = r0 + 8;
#pragma unroll
            for (int ni = 0; ni < 4; ni++) {
                int col = bn + wn * 32 + ni * 8 + (lane & 3) * 2;
                float2 bv = *(const float2*)(bias + col);
                float v00 = fmaxf(acc[mi][ni][0] + bv.x, 0.f);
                float v01 = fmaxf(acc[mi][ni][1] + bv.y, 0.f);
                float v10 = fmaxf(acc[mi][ni][2] + bv.x, 0.f);
                float v11 = fmaxf(acc[mi][ni][3] + bv.y, 0.f);
                uint32_t* o = (uint32_t*)C;
                int ci = col >> 1;
                o[(size_t)r0 * 256 + ci]       = pack_hi2(v00, v01);
                o[(size_t)r0 * 256 + 128 + ci] = pack_lo2(v00, v01);
                o[(size_t)r1 * 256 + ci]       = pack_hi2(v10, v11);
                o[(size_t)r1 * 256 + 128 + ci] = pack_lo2(v10, v11);
            }
        }
    } else {
#pragma unroll
        for (int mi = 0; mi < 4; mi++) {
            int r0 = bm + wm * 64 + mi * 16 + (lane >> 2);
            int r1 = r0 + 8;
            float p00 = 0.f, p01 = 0.f, p10 = 0.f, p11 = 0.f;
#pragma unroll
            for (int ni = 0; ni < 4; ni++) {
                int col = bn + wn * 32 + ni * 8 + (lane & 3) * 2;
                float2 bv = *(const float2*)(bias + col);
                float h0 = fmaxf(acc[mi][ni][0] + bv.x, 0.f);
                float h1 = fmaxf(acc[mi][ni][1] + bv.y, 0.f);
                float h2 = fmaxf(acc[mi][ni][2] + bv.x, 0.f);
                float h3 = fmaxf(acc[mi][ni][3] + bv.y, 0.f);
                float2 wv0 = *(const float2*)(w2b + col * 2);
                float2 wv1 = *(const float2*)(w2b + (col + 1) * 2);
                p00 = fmaf(h0, wv0.x, fmaf(h1, wv1.x, p00));
                p01 = fmaf(h0, wv0.y, fmaf(h1, wv1.y, p01));
                p10 = fmaf(h2, wv0.x, fmaf(h3, wv1.x, p10));
                p11 = fmaf(h2, wv0.y, fmaf(h3, wv1.y, p11));
            }
#pragma unroll
            for (int off = 1; off <= 2; off <<= 1) {
                p00 += __shfl_xor_sync(0xffffffffu, p00, off);
                p01 += __shfl_xor_sync(0xffffffffu, p01, off);
                p10 += __shfl_xor_sync(0xffffffffu, p10, off);
                p11 += __shfl_xor_sync(0xffffffffu, p11, off);
            }
            if ((lane & 3) == 0) {
                if (r0 < M) {
                    atomicAdd(&C[(size_t)r0 * 2 + 0], p00);
                    atomicAdd(&C[(size_t)r0 * 2 + 1], p01);
                }
                if (r1 < M) {
                    atomicAdd(&C[(size_t)r1 * 2 + 0], p10);
                    atomicAdd(&C[(size_t)r1 * 2 + 1], p11);
                }
            }
        }
    }
#undef LOADCHUNK
}

// ---------------- BN finalize kernels ----------------
__global__ void k_bn1_fin(const float* __restrict__ gamma, const float* __restrict__ beta) {
    int c = threadIdx.x;
    if (c >= DIM) return;
    const float invN = 1.0f / (float)N_NODES;
    float mean = g_sum1[c] * invN;
    float var  = g_sq1[c] * invN - mean * mean;
    float sc   = gamma[c] * rsqrtf(var + BN_EPS);
    g_scale1[c] = sc;
    g_shift1[c] = beta[c] - mean * sc;
}

__global__ void __launch_bounds__(256) k_bn2pre(const float* __restrict__ b2b) {
    __shared__ float red[8][4];
    int t = threadIdx.x;
    int lane = t & 31, wid = t >> 5;
    int r = blockIdx.x * 256 + t;
    float s0 = 0.f, s1 = 0.f, q0 = 0.f, q1 = 0.f;
    if (r < N_NODES) {
        float2 v = ((float2*)g_out2)[r];
        v.x = fmaxf(v.x + b2b[0], 0.f);
        v.y = fmaxf(v.y + b2b[1], 0.f);
        ((float2*)g_out2)[r] = v;
        s0 = v.x; s1 = v.y; q0 = v.x * v.x; q1 = v.y * v.y;
    }
#pragma unroll
    for (int off = 16; off; off >>= 1) {
        s0 += __shfl_xor_sync(0xffffffffu, s0, off);
        s1 += __shfl_xor_sync(0xffffffffu, s1, off);
        q0 += __shfl_xor_sync(0xffffffffu, q0, off);
        q1 += __shfl_xor_sync(0xffffffffu, q1, off);
    }
    if (lane == 0) { red[wid][0] = s0; red[wid][1] = s1; red[wid][2] = q0; red[wid][3] = q1; }
    __syncthreads();
    if (t < 4) {
        float acc = 0.f;
#pragma unroll
        for (int wI = 0; wI < 8; wI++) acc += red[wI][t];
        atomicAdd(&g_bn2[t], acc);
    }
}

__global__ void k_bn2_fin(const float* __restrict__ gamma2, const float* __restrict__ beta2) {
    int c = threadIdx.x;
    if (c >= 2) return;
    const float invN = 1.0f / (float)N_NODES;
    float mean = g_bn2[c] * invN;
    float var  = g_bn2[2 + c] * invN - mean * mean;
    float sc   = gamma2[c] * rsqrtf(var + BN_EPS);
    g_ss2[c]     = sc;
    g_ss2[2 + c] = beta2[c] - mean * sc;
}

__global__ void k_bn2_norm(float* __restrict__ out) {
    int r = blockIdx.x * blockDim.x + threadIdx.x;
    if (r >= N_NODES) return;
    float2 v = ((const float2*)g_out2)[r];
    float2 o;
    o.x = fmaf(v.x, g_ss2[0], g_ss2[2]);
    o.y = fmaf(v.y, g_ss2[1], g_ss2[3]);
    ((float2*)out)[r] = o;
}

// ---------------- launch ----------------
extern "C" void kernel_launch(void* const* d_in, const int* in_sizes, int n_in,
                              void* d_out, int out_size) {
    const float* x      = (const float*)d_in[0];
    const int*   eidx   = (const int*)d_in[1];
    const float* ew     = (const float*)d_in[3];
    const float* W1a    = (const float*)d_in[4];
    const float* b1a    = (const float*)d_in[5];
    const float* W1b    = (const float*)d_in[6];
    const float* b1b    = (const float*)d_in[7];
    const float* gamma1 = (const float*)d_in[8];
    const float* beta1  = (const float*)d_in[9];
    const float* W2a    = (const float*)d_in[10];
    const float* b2a    = (const float*)d_in[11];
    const float* W2b    = (const float*)d_in[12];
    const float* b2b    = (const float*)d_in[13];
    const float* gamma2 = (const float*)d_in[14];
    const float* beta2  = (const float*)d_in[15];

    const int nEdges = in_sizes[1] / 2;
    const int* src = eidx;
    const int* dst = eidx + nEdges;
    const int nE4 = nEdges / 4;

    float *pre, *out2;
    __half* xh;
    __nv_bfloat16 *A2, *A3, *B2a, *B2b, *B2c;
    cudaGetSymbolAddress((void**)&pre, g_pre);
    cudaGetSymbolAddress((void**)&out2, g_out2);
    cudaGetSymbolAddress((void**)&xh,  g_xh);
    cudaGetSymbolAddress((void**)&A2,  g_A2);
    cudaGetSymbolAddress((void**)&A3,  g_A3);
    cudaGetSymbolAddress((void**)&B2a, g_B2a);
    cudaGetSymbolAddress((void**)&B2b, g_B2b);
    cudaGetSymbolAddress((void**)&B2c, g_B2c);

    cudaFuncSetAttribute(k_mma<0>, cudaFuncAttributeMaxDynamicSharedMemorySize, 65536);
    cudaFuncSetAttribute(k_mma<1>, cudaFuncAttributeMaxDynamicSharedMemorySize, 65536);
    cudaFuncSetAttribute(k_mma<2>, cudaFuncAttributeMaxDynamicSharedMemorySize, 65536);

    const int gatherBlocks = (MPAD * 32 + 255) / 256;
    const int edgeBlocks4 = (nE4 + 1 + 255) / 256;

    // ---- setup + CSR build ----
    k_convAll<<<(CONVALL_ITEMS + 255) / 256, 256>>>(x, W1a, W1b, W2a);
    k_hist<<<edgeBlocks4, 256>>>(dst, nE4, nEdges);
    k_scan<<<1, 1024>>>();
    k_fill<<<edgeBlocks4, 256>>>(src, dst, ew, nE4, nEdges);

    // ---- layer 1 ----
    k_gather<true, false><<<gatherBlocks, 256>>>(x, xh);      // fp16 edge gather
    {
        dim3 g(MTILES, 2);   // mma1: relu(A2@W1a + b1a) -> A3 (split-bf16)
        k_mma<1><<<g, 256, 65536>>>(A2, B2a, b1a, (float*)A3, nullptr, N_NODES, HID2, DIM);
    }
    {
        dim3 g(MTILES, 1);   // mma2: relu(A3@W1b + b1b) -> pre (fp32) + BN1 stats
        k_mma<0><<<g, 256, 65536>>>(A3, B2b, b1b, pre, nullptr, N_NODES, DIM, HID2);
    }
    k_bn1_fin<<<1, 128>>>(gamma1, beta1);

    // ---- layer 2 ----
    k_gather<false, true><<<gatherBlocks, 256>>>(pre, nullptr);   // BN affine folded
    {
        dim3 g(MTILES, 2);   // mma3: fused gemv -> out2 partials
        k_mma<2><<<g, 256, 65536>>>(A2, B2c, b2a, out2, W2b, N_NODES, HID2, DIM);
    }
    k_bn2pre<<<(N_NODES + 255) / 256, 256>>>(b2b);
    k_bn2_fin<<<1, 32>>>(gamma2, beta2);
    k_bn2_norm<<<(N_NODES + 255) / 256, 256>>>((float*)d_out);
}

// round 13
// speedup vs baseline: 2.2972x; 1.0395x over previous
#include <cuda_runtime.h>
#include <cuda_bf16.h>
#include <cuda_fp16.h>
#include <cstdint>

#define N_NODES 50000
#define N_EDGES 1600000
#define DIM 128
#define HID2 256
#define BN_EPS 1e-5f

#define MPAD 50048          // 391 * 128
#define MTILES 391

// ---------------- scratch (static device globals; no runtime alloc) ----------------
__device__ __align__(16) float g_pre[(size_t)N_NODES * DIM];
__device__ __align__(16) float g_out2[(size_t)N_NODES * 2];
__device__ __align__(16) __half g_xh[(size_t)N_NODES * DIM];        // fp16 copy of x
__device__ __align__(16) __half g_preh[(size_t)N_NODES * DIM];      // fp16 shadow of pre

__device__ __align__(16) __nv_bfloat16 g_A2[(size_t)MPAD * 256];    // gather out: [Mpad, 2*128] split-bf16
__device__ __align__(16) __nv_bfloat16 g_A3[(size_t)MPAD * 512];    // mma1 out:   [Mpad, 2*256] split-bf16
__device__ __align__(16) __nv_bfloat16 g_B2a[(size_t)256 * 256];    // W1a: [256, 2*128]
__device__ __align__(16) __nv_bfloat16 g_B2b[(size_t)128 * 512];    // W1b: [128, 2*256]
__device__ __align__(16) __nv_bfloat16 g_B2c[(size_t)256 * 256];    // W2a: [256, 2*128]

// CSR scratch
__device__ int   g_deg[N_NODES];
__device__ int   g_rowptr[N_NODES + 1];
__device__ int   g_cur[N_NODES];
__device__ uint2 g_edge[N_EDGES];

__device__ __align__(16) float g_sum1[DIM];
__device__ __align__(16) float g_sq1[DIM];
__device__ float g_bn2[4];

// ---------------- helpers ----------------
__device__ __forceinline__ uint32_t smem_u32(const void* p) {
    uint32_t a;
    asm("{ .reg .u64 t; cvta.to.shared.u64 t, %1; cvt.u32.u64 %0, t; }" : "=r"(a) : "l"(p));
    return a;
}
#define SWZ128(off) ((off) ^ (((off) >> 3) & 0x70))

__device__ __forceinline__ void mma16816(float* c, const uint32_t* a, const uint32_t* b) {
    asm volatile("mma.sync.aligned.m16n8k16.row.col.f32.bf16.bf16.f32 "
        "{%0,%1,%2,%3}, {%4,%5,%6,%7}, {%8,%9}, {%0,%1,%2,%3};"
        : "+f"(c[0]), "+f"(c[1]), "+f"(c[2]), "+f"(c[3])
        : "r"(a[0]), "r"(a[1]), "r"(a[2]), "r"(a[3]), "r"(b[0]), "r"(b[1]));
}
#define LDSM4(r, addr) asm volatile("ldmatrix.sync.aligned.m8n8.x4.shared.b16 {%0,%1,%2,%3}, [%4];" \
    : "=r"((r)[0]), "=r"((r)[1]), "=r"((r)[2]), "=r"((r)[3]) : "r"(addr))
#define LDSM2(r, addr) asm volatile("ldmatrix.sync.aligned.m8n8.x2.shared.b16 {%0,%1}, [%2];" \
    : "=r"((r)[0]), "=r"((r)[1]) : "r"(addr))
#define CPASYNC16(dst, src) asm volatile("cp.async.cg.shared.global [%0], [%1], 16;" :: "r"(dst), "l"(src))

__device__ __forceinline__ uint32_t pack_hi2(float x, float y) {
    __nv_bfloat16 h0 = __float2bfloat16(x);
    __nv_bfloat16 h1 = __float2bfloat16(y);
    uint32_t r;
    asm("mov.b32 %0, {%1, %2};" : "=r"(r) : "h"(*(unsigned short*)&h0), "h"(*(unsigned short*)&h1));
    return r;
}
__device__ __forceinline__ uint32_t pack_lo2(float x, float y) {
    __nv_bfloat16 h0 = __float2bfloat16(x);
    __nv_bfloat16 h1 = __float2bfloat16(y);
    __nv_bfloat16 l0 = __float2bfloat16(x - __bfloat162float(h0));
    __nv_bfloat16 l1 = __float2bfloat16(y - __bfloat162float(h1));
    uint32_t r;
    asm("mov.b32 %0, {%1, %2};" : "=r"(r) : "h"(*(unsigned short*)&l0), "h"(*(unsigned short*)&l1));
    return r;
}

// ---------------- zeroing ----------------
__global__ void __launch_bounds__(256) k_zero() {
    int i = blockIdx.x * blockDim.x + threadIdx.x;
    if (i < N_NODES) g_deg[i] = 0;
    if (i < N_NODES / 2) ((float4*)g_out2)[i] = make_float4(0.f, 0.f, 0.f, 0.f);
    if (i < DIM) { g_sum1[i] = 0.f; g_sq1[i] = 0.f; }
    if (i < 4) g_bn2[i] = 0.f;
}

// ---------------- fused: histogram + x->fp16 + 3 weight splits ----------------
__device__ __forceinline__ void convB_elem(const float* __restrict__ W, __nv_bfloat16* __restrict__ out,
                                           int j, int K, int N) {
    int n = j / K, k = j % K;
    float v = W[(size_t)k * N + n];
    __nv_bfloat16 h = __float2bfloat16(v);
    __nv_bfloat16 l = __float2bfloat16(v - __bfloat162float(h));
    size_t base = (size_t)n * 2 * K;
    out[base + k]     = h;
    out[base + K + k] = l;
}

#define CONVX_N (N_NODES * DIM / 4)   // 1,600,000 float4 quads

__global__ void __launch_bounds__(256) k_histconv(const int* __restrict__ dst, int nE4, int nEdges,
                                                  const float* __restrict__ x,
                                                  const float* __restrict__ W1a,
                                                  const float* __restrict__ W1b,
                                                  const float* __restrict__ W2a) {
    int i = blockIdx.x * blockDim.x + threadIdx.x;
    if (i < nE4) {
        int4 d = ((const int4*)dst)[i];
        atomicAdd(&g_deg[d.x], 1);
        atomicAdd(&g_deg[d.y], 1);
        atomicAdd(&g_deg[d.z], 1);
        atomicAdd(&g_deg[d.w], 1);
        return;
    }
    if (i == nE4) {
        for (int e = nE4 * 4; e < nEdges; e++) atomicAdd(&g_deg[dst[e]], 1);
        return;
    }
    i -= nE4 + 1;
    if (i < CONVX_N) {
        float4 v = ((const float4*)x)[i];
        __half2 h0 = __floats2half2_rn(v.x, v.y);
        __half2 h1 = __floats2half2_rn(v.z, v.w);
        uint2 o;
        o.x = *(uint32_t*)&h0;
        o.y = *(uint32_t*)&h1;
        ((uint2*)g_xh)[i] = o;
        return;
    }
    i -= CONVX_N;
    if (i < DIM * HID2) { convB_elem(W1a, g_B2a, i, DIM, HID2); return; }
    i -= DIM * HID2;
    if (i < HID2 * DIM) { convB_elem(W1b, g_B2b, i, HID2, DIM); return; }
    i -= HID2 * DIM;
    if (i < DIM * HID2) { convB_elem(W2a, g_B2c, i, DIM, HID2); return; }
}

// ---------------- CSR scan + fill ----------------
__global__ void __launch_bounds__(1024) k_scan() {
    __shared__ int wsum[32];
    __shared__ int carry;
    int t = threadIdx.x, lane = t & 31, w = t >> 5;
    if (t == 0) { carry = 0; g_rowptr[0] = 0; }
    __syncthreads();
    for (int base = 0; base < N_NODES; base += 1024) {
        int i = base + t;
        int v = (i < N_NODES) ? g_deg[i] : 0;
        int s = v;
#pragma unroll
        for (int off = 1; off < 32; off <<= 1) {
            int u = __shfl_up_sync(0xffffffffu, s, off);
            if (lane >= off) s += u;
        }
        if (lane == 31) wsum[w] = s;
        __syncthreads();
        if (w == 0) {
            int ws = wsum[lane];
#pragma unroll
            for (int off = 1; off < 32; off <<= 1) {
                int u = __shfl_up_sync(0xffffffffu, ws, off);
                if (lane >= off) ws += u;
            }
            wsum[lane] = ws;
        }
        __syncthreads();
        int prefix = carry + (w > 0 ? wsum[w - 1] : 0);
        int inc = prefix + s;
        if (i < N_NODES) { g_rowptr[i + 1] = inc; g_cur[i] = inc - v; }
        int total = wsum[31];
        __syncthreads();
        if (t == 0) carry += total;
        __syncthreads();
    }
}

__global__ void __launch_bounds__(256) k_fill(const int* __restrict__ src,
                                              const int* __restrict__ dst,
                                              const float* __restrict__ wgt,
                                              int nE4, int nEdges) {
    int i = blockIdx.x * blockDim.x + threadIdx.x;
    if (i < nE4) {
        int4 s = ((const int4*)src)[i];
        int4 d = ((const int4*)dst)[i];
        float4 w = ((const float4*)wgt)[i];
        int p0 = atomicAdd(&g_cur[d.x], 1);
        int p1 = atomicAdd(&g_cur[d.y], 1);
        int p2 = atomicAdd(&g_cur[d.z], 1);
        int p3 = atomicAdd(&g_cur[d.w], 1);
        g_edge[p0] = make_uint2((uint32_t)s.x, __float_as_uint(w.x));
        g_edge[p1] = make_uint2((uint32_t)s.y, __float_as_uint(w.y));
        g_edge[p2] = make_uint2((uint32_t)s.z, __float_as_uint(w.z));
        g_edge[p3] = make_uint2((uint32_t)s.w, __float_as_uint(w.w));
    } else if (i == nE4) {
        for (int e = nE4 * 4; e < nEdges; e++) {
            int pos = atomicAdd(&g_cur[dst[e]], 1);
            g_edge[pos] = make_uint2((uint32_t)src[e], __float_as_uint(wgt[e]));
        }
    }
}

// ---------------- fused gather + (optional BN affine) + split-bf16 convert ----------------
// One warp per node row. Self term from f32; edge terms from fp16.
// BN_MODE additionally computes per-block BN1 scale/shift from raw stats (replaces k_bn1_fin)
// and applies: acc = sc * raw + sh * (1 + sum_w).
template<bool BN_MODE>
__global__ void __launch_bounds__(256) k_gather(const float* __restrict__ f32,
                                                const __half* __restrict__ f16,
                                                const float* __restrict__ gamma,
                                                const float* __restrict__ beta) {
    __shared__ __align__(16) float s_sc[DIM];
    __shared__ __align__(16) float s_sh[DIM];
    int t = threadIdx.x;
    if (BN_MODE) {
        if (t < DIM) {
            const float invN = 1.0f / (float)N_NODES;
            float mean = g_sum1[t] * invN;
            float var  = g_sq1[t] * invN - mean * mean;
            float sc   = gamma[t] * rsqrtf(var + BN_EPS);
            s_sc[t] = sc;
            s_sh[t] = beta[t] - mean * sc;
        }
        __syncthreads();
    }
    int lane = t & 31;
    int node = (blockIdx.x * blockDim.x + t) >> 5;
    if (node >= MPAD) return;
    uint32_t* o = (uint32_t*)g_A2;
    size_t base = (size_t)node * 128;
    if (node >= N_NODES) {
        ((uint2*)(o + base))[lane] = make_uint2(0u, 0u);
        ((uint2*)(o + base + 64))[lane] = make_uint2(0u, 0u);
        return;
    }
    const float4* f4 = (const float4*)f32;
    const uint2* h2 = (const uint2*)f16;
    float4 acc = f4[(size_t)node * 32 + lane];
    float sumw = 0.f;
    int j = g_rowptr[node];
    int end = g_rowptr[node + 1];

#define EDGE_TERM(E) do {                                                     \
        float w_ = __uint_as_float((E).y);                                    \
        if (BN_MODE) sumw += w_;                                              \
        uint2 q_ = h2[(size_t)(E).x * 32 + lane];                             \
        float2 fa_ = __half22float2(*(__half2*)&q_.x);                        \
        float2 fb_ = __half22float2(*(__half2*)&q_.y);                        \
        acc.x = fmaf(w_, fa_.x, acc.x); acc.y = fmaf(w_, fa_.y, acc.y);       \
        acc.z = fmaf(w_, fb_.x, acc.z); acc.w = fmaf(w_, fb_.y, acc.w);       \
    } while (0)

    for (; j + 4 <= end; j += 4) {
        uint2 e0 = g_edge[j + 0];
        uint2 e1 = g_edge[j + 1];
        uint2 e2 = g_edge[j + 2];
        uint2 e3 = g_edge[j + 3];
        EDGE_TERM(e0); EDGE_TERM(e1); EDGE_TERM(e2); EDGE_TERM(e3);
    }
    for (; j < end; j++) {
        uint2 e = g_edge[j];
        EDGE_TERM(e);
    }
#undef EDGE_TERM

    if (BN_MODE) {
        float4 sc = *(const float4*)&s_sc[lane * 4];
        float4 sh = *(const float4*)&s_sh[lane * 4];
        float m = 1.f + sumw;
        acc.x = fmaf(sc.x, acc.x, sh.x * m);
        acc.y = fmaf(sc.y, acc.y, sh.y * m);
        acc.z = fmaf(sc.z, acc.z, sh.z * m);
        acc.w = fmaf(sc.w, acc.w, sh.w * m);
    }
    uint2 hi = make_uint2(pack_hi2(acc.x, acc.y), pack_hi2(acc.z, acc.w));
    uint2 lo = make_uint2(pack_lo2(acc.x, acc.y), pack_lo2(acc.z, acc.w));
    *(uint2*)(o + base + 2 * lane) = hi;
    *(uint2*)(o + base + 64 + 2 * lane) = lo;
}

// ---------------- HMMA bf16 GEMM with fused epilogues ----------------
// MODE 0: C = relu(A@B^T + bias) fp32 + fp16 shadow (g_preh) + fused BN1 stats atomics
// MODE 1: split-bf16 [hi|lo] write into C (row stride 256 u32)
// MODE 2: fused gemv: atomicAdd partials of relu(A@B^T + bias) @ w2b[256,2] into C
template<int MODE>
__global__ void __launch_bounds__(256, 2)
k_mma(const __nv_bfloat16* __restrict__ A2, const __nv_bfloat16* __restrict__ B2,
      const float* __restrict__ bias, float* __restrict__ C,
      const float* __restrict__ w2b, int M, int Ntot, int K) {
    extern __shared__ __align__(1024) uint8_t sm[];
    const int t = threadIdx.x;
    const int lane = t & 31;
    const int wid = t >> 5;
    const int wm = wid >> 2;
    const int wn = wid & 3;
    const int bm = blockIdx.x * 128;
    const int bn = blockIdx.y * 128;
    const int K2 = K * 2;
    const uint32_t smbase = smem_u32(sm);

    const int lrow = t >> 3;
    const int ls16 = t & 7;
    const int cps = K >> 6;
    const int total = 3 * cps;

#define LOADCHUNK(c, buf) do {                                                        \
        int s_ = (c) / cps, ck_ = (c) % cps;                                          \
        int aoff_ = (s_ == 1 ? K : 0) + ck_ * 64;                                     \
        int boff_ = (s_ == 2 ? K : 0) + ck_ * 64;                                     \
        uint32_t sA_ = smbase + (buf) * 32768;                                        \
        uint32_t sB_ = sA_ + 16384;                                                   \
        _Pragma("unroll")                                                             \
        for (int i_ = 0; i_ < 4; i_++) {                                              \
            int row_ = lrow + 32 * i_;                                                \
            uint32_t da_ = sA_ + SWZ128(row_ * 128 + ls16 * 16);                      \
            const void* ga_ = A2 + (size_t)(bm + row_) * K2 + aoff_ + ls16 * 8;       \
            CPASYNC16(da_, ga_);                                                      \
            uint32_t db_ = sB_ + SWZ128(row_ * 128 + ls16 * 16);                      \
            const void* gb_ = B2 + (size_t)(bn + row_) * K2 + boff_ + ls16 * 8;       \
            CPASYNC16(db_, gb_);                                                      \
        }                                                                             \
        asm volatile("cp.async.commit_group;");                                       \
    } while (0)

    float acc[4][4][4] = {};

    LOADCHUNK(0, 0);
    for (int c = 0; c < total; c++) {
        if (c + 1 < total) {
            LOADCHUNK(c + 1, (c + 1) & 1);
            asm volatile("cp.async.wait_group 1;");
        } else {
            asm volatile("cp.async.wait_group 0;");
        }
        __syncthreads();
        uint32_t sA = smbase + (c & 1) * 32768;
        uint32_t sB = sA + 16384;
        const int t16 = lane & 15;
#pragma unroll
        for (int ks = 0; ks < 4; ks++) {
            uint32_t afr[4][4];
            uint32_t bfr[4][2];
#pragma unroll
            for (int mi = 0; mi < 4; mi++) {
                int row = wm * 64 + mi * 16 + (lane & 15);
                uint32_t addr = sA + SWZ128(row * 128 + ks * 32 + ((lane >> 4) << 4));
                LDSM4(afr[mi], addr);
            }
#pragma unroll
            for (int ni = 0; ni < 4; ni++) {
                int row = wn * 32 + ni * 8 + (t16 & 7);
                uint32_t addr = sB + SWZ128(row * 128 + ks * 32 + ((t16 >> 3) << 4));
                LDSM2(bfr[ni], addr);
            }
#pragma unroll
            for (int mi = 0; mi < 4; mi++)
#pragma unroll
                for (int ni = 0; ni < 4; ni++)
                    mma16816(acc[mi][ni], afr[mi], bfr[ni]);
        }
        __syncthreads();
    }

    if (MODE == 0) {
        __half2* preh = (__half2*)g_preh;
        float bs[4][2] = {}, bq[4][2] = {};
#pragma unroll
        for (int mi = 0; mi < 4; mi++) {
            int r0 = bm + wm * 64 + mi * 16 + (lane >> 2);
            int r1 = r0 + 8;
#pragma unroll
            for (int ni = 0; ni < 4; ni++) {
                int col = bn + wn * 32 + ni * 8 + (lane & 3) * 2;
                float2 bv = *(const float2*)(bias + col);
                float v00 = fmaxf(acc[mi][ni][0] + bv.x, 0.f);
                float v01 = fmaxf(acc[mi][ni][1] + bv.y, 0.f);
                float v10 = fmaxf(acc[mi][ni][2] + bv.x, 0.f);
                float v11 = fmaxf(acc[mi][ni][3] + bv.y, 0.f);
                if (r0 < M) {
                    *(float2*)(C + (size_t)r0 * Ntot + col) = make_float2(v00, v01);
                    preh[(size_t)r0 * 64 + (col >> 1)] = __floats2half2_rn(v00, v01);
                    bs[ni][0] += v00; bs[ni][1] += v01;
                    bq[ni][0] += v00 * v00; bq[ni][1] += v01 * v01;
                }
                if (r1 < M) {
                    *(float2*)(C + (size_t)r1 * Ntot + col) = make_float2(v10, v11);
                    preh[(size_t)r1 * 64 + (col >> 1)] = __floats2half2_rn(v10, v11);
                    bs[ni][0] += v10; bs[ni][1] += v11;
                    bq[ni][0] += v10 * v10; bq[ni][1] += v11 * v11;
                }
            }
        }
#pragma unroll
        for (int ni = 0; ni < 4; ni++) {
            float s0 = bs[ni][0], s1 = bs[ni][1], q0 = bq[ni][0], q1 = bq[ni][1];
#pragma unroll
            for (int off = 4; off <= 16; off <<= 1) {
                s0 += __shfl_xor_sync(0xffffffffu, s0, off);
                s1 += __shfl_xor_sync(0xffffffffu, s1, off);
                q0 += __shfl_xor_sync(0xffffffffu, q0, off);
                q1 += __shfl_xor_sync(0xffffffffu, q1, off);
            }
            if (lane < 4) {
                int c0 = bn + wn * 32 + ni * 8 + lane * 2;
                atomicAdd(&g_sum1[c0], s0);
                atomicAdd(&g_sum1[c0 + 1], s1);
                atomicAdd(&g_sq1[c0], q0);
                atomicAdd(&g_sq1[c0 + 1], q1);
            }
        }
    } else if (MODE == 1) {
#pragma unroll
        for (int mi = 0; mi < 4; mi++) {
            int r0 = bm + wm * 64 + mi * 16 + (lane >> 2);
            int r1 = r0 + 8;
#pragma unroll
            for (int ni = 0; ni < 4; ni++) {
                int col = bn + wn * 32 + ni * 8 + (lane & 3) * 2;
                float2 bv = *(const float2*)(bias + col);
                float v00 = fmaxf(acc[mi][ni][0] + bv.x, 0.f);
                float v01 = fmaxf(acc[mi][ni][1] + bv.y, 0.f);
                float v10 = fmaxf(acc[mi][ni][2] + bv.x, 0.f);
                float v11 = fmaxf(acc[mi][ni][3] + bv.y, 0.f);
                uint32_t* o = (uint32_t*)C;
                int ci = col >> 1;
                o[(size_t)r0 * 256 + ci]       = pack_hi2(v00, v01);
                o[(size_t)r0 * 256 + 128 + ci] = pack_lo2(v00, v01);
                o[(size_t)r1 * 256 + ci]       = pack_hi2(v10, v11);
                o[(size_t)r1 * 256 + 128 + ci] = pack_lo2(v10, v11);
            }
        }
    } else {
#pragma unroll
        for (int mi = 0; mi < 4; mi++) {
            int r0 = bm + wm * 64 + mi * 16 + (lane >> 2);
            int r1 = r0 + 8;
            float p00 = 0.f, p01 = 0.f, p10 = 0.f, p11 = 0.f;
#pragma unroll
            for (int ni = 0; ni < 4; ni++) {
                int col = bn + wn * 32 + ni * 8 + (lane & 3) * 2;
                float2 bv = *(const float2*)(bias + col);
                float h0 = fmaxf(acc[mi][ni][0] + bv.x, 0.f);
                float h1 = fmaxf(acc[mi][ni][1] + bv.y, 0.f);
                float h2 = fmaxf(acc[mi][ni][2] + bv.x, 0.f);
                float h3 = fmaxf(acc[mi][ni][3] + bv.y, 0.f);
                float2 wv0 = *(const float2*)(w2b + col * 2);
                float2 wv1 = *(const float2*)(w2b + (col + 1) * 2);
                p00 = fmaf(h0, wv0.x, fmaf(h1, wv1.x, p00));
                p01 = fmaf(h0, wv0.y, fmaf(h1, wv1.y, p01));
                p10 = fmaf(h2, wv0.x, fmaf(h3, wv1.x, p10));
                p11 = fmaf(h2, wv0.y, fmaf(h3, wv1.y, p11));
            }
#pragma unroll
            for (int off = 1; off <= 2; off <<= 1) {
                p00 += __shfl_xor_sync(0xffffffffu, p00, off);
                p01 += __shfl_xor_sync(0xffffffffu, p01, off);
                p10 += __shfl_xor_sync(0xffffffffu, p10, off);
                p11 += __shfl_xor_sync(0xffffffffu, p11, off);
            }
            if ((lane & 3) == 0) {
                if (r0 < M) {
                    atomicAdd(&C[(size_t)r0 * 2 + 0], p00);
                    atomicAdd(&C[(size_t)r0 * 2 + 1], p01);
                }
                if (r1 < M) {
                    atomicAdd(&C[(size_t)r1 * 2 + 0], p10);
                    atomicAdd(&C[(size_t)r1 * 2 + 1], p11);
                }
            }
        }
    }
#undef LOADCHUNK
}

// ---------------- BN2 ----------------
__global__ void __launch_bounds__(256) k_bn2pre(const float* __restrict__ b2b) {
    __shared__ float red[8][4];
    int t = threadIdx.x;
    int lane = t & 31, wid = t >> 5;
    int r = blockIdx.x * 256 + t;
    float s0 = 0.f, s1 = 0.f, q0 = 0.f, q1 = 0.f;
    if (r < N_NODES) {
        float2 v = ((float2*)g_out2)[r];
        v.x = fmaxf(v.x + b2b[0], 0.f);
        v.y = fmaxf(v.y + b2b[1], 0.f);
        ((float2*)g_out2)[r] = v;
        s0 = v.x; s1 = v.y; q0 = v.x * v.x; q1 = v.y * v.y;
    }
#pragma unroll
    for (int off = 16; off; off >>= 1) {
        s0 += __shfl_xor_sync(0xffffffffu, s0, off);
        s1 += __shfl_xor_sync(0xffffffffu, s1, off);
        q0 += __shfl_xor_sync(0xffffffffu, q0, off);
        q1 += __shfl_xor_sync(0xffffffffu, q1, off);
    }
    if (lane == 0) { red[wid][0] = s0; red[wid][1] = s1; red[wid][2] = q0; red[wid][3] = q1; }
    __syncthreads();
    if (t < 4) {
        float acc = 0.f;
#pragma unroll
        for (int wI = 0; wI < 8; wI++) acc += red[wI][t];
        atomicAdd(&g_bn2[t], acc);
    }
}

// fused finalize + normalize
__global__ void __launch_bounds__(256) k_bn2norm(const float* __restrict__ gamma2,
                                                 const float* __restrict__ beta2,
                                                 float* __restrict__ out) {
    __shared__ float ss[4];   // sc0, sc1, sh0, sh1
    int t = threadIdx.x;
    if (t < 2) {
        const float invN = 1.0f / (float)N_NODES;
        float mean = g_bn2[t] * invN;
        float var  = g_bn2[2 + t] * invN - mean * mean;
        float sc   = gamma2[t] * rsqrtf(var + BN_EPS);
        ss[t]     = sc;
        ss[2 + t] = beta2[t] - mean * sc;
    }
    __syncthreads();
    int r = blockIdx.x * blockDim.x + t;
    if (r >= N_NODES) return;
    float2 v = ((const float2*)g_out2)[r];
    float2 o;
    o.x = fmaf(v.x, ss[0], ss[2]);
    o.y = fmaf(v.y, ss[1], ss[3]);
    ((float2*)out)[r] = o;
}

// ---------------- launch ----------------
extern "C" void kernel_launch(void* const* d_in, const int* in_sizes, int n_in,
                              void* d_out, int out_size) {
    const float* x      = (const float*)d_in[0];
    const int*   eidx   = (const int*)d_in[1];
    const float* ew     = (const float*)d_in[3];
    const float* W1a    = (const float*)d_in[4];
    const float* b1a    = (const float*)d_in[5];
    const float* W1b    = (const float*)d_in[6];
    const float* b1b    = (const float*)d_in[7];
    const float* gamma1 = (const float*)d_in[8];
    const float* beta1  = (const float*)d_in[9];
    const float* W2a    = (const float*)d_in[10];
    const float* b2a    = (const float*)d_in[11];
    const float* W2b    = (const float*)d_in[12];
    const float* b2b    = (const float*)d_in[13];
    const float* gamma2 = (const float*)d_in[14];
    const float* beta2  = (const float*)d_in[15];

    const int nEdges = in_sizes[1] / 2;
    const int* src = eidx;
    const int* dst = eidx + nEdges;
    const int nE4 = nEdges / 4;

    float *pre, *out2;
    __half *xh, *preh;
    __nv_bfloat16 *A2, *A3, *B2a, *B2b, *B2c;
    cudaGetSymbolAddress((void**)&pre, g_pre);
    cudaGetSymbolAddress((void**)&out2, g_out2);
    cudaGetSymbolAddress((void**)&xh,   g_xh);
    cudaGetSymbolAddress((void**)&preh, g_preh);
    cudaGetSymbolAddress((void**)&A2,  g_A2);
    cudaGetSymbolAddress((void**)&A3,  g_A3);
    cudaGetSymbolAddress((void**)&B2a, g_B2a);
    cudaGetSymbolAddress((void**)&B2b, g_B2b);
    cudaGetSymbolAddress((void**)&B2c, g_B2c);

    cudaFuncSetAttribute(k_mma<0>, cudaFuncAttributeMaxDynamicSharedMemorySize, 65536);
    cudaFuncSetAttribute(k_mma<1>, cudaFuncAttributeMaxDynamicSharedMemorySize, 65536);
    cudaFuncSetAttribute(k_mma<2>, cudaFuncAttributeMaxDynamicSharedMemorySize, 65536);

    const int gatherBlocks = (MPAD * 32 + 255) / 256;
    const int edgeBlocks4 = (nE4 + 1 + 255) / 256;
    const int histconvItems = (nE4 + 1) + CONVX_N + 3 * DIM * HID2;

    // ---- setup + CSR build ----
    k_zero<<<(N_NODES + 255) / 256, 256>>>();
    k_histconv<<<(histconvItems + 255) / 256, 256>>>(dst, nE4, nEdges, x, W1a, W1b, W2a);
    k_scan<<<1, 1024>>>();
    k_fill<<<edgeBlocks4, 256>>>(src, dst, ew, nE4, nEdges);

    // ---- layer 1 ----
    k_gather<false><<<gatherBlocks, 256>>>(x, xh, nullptr, nullptr);
    {
        dim3 g(MTILES, 2);   // mma1: relu(A2@W1a + b1a) -> A3 (split-bf16)
        k_mma<1><<<g, 256, 65536>>>(A2, B2a, b1a, (float*)A3, nullptr, N_NODES, HID2, DIM);
    }
    {
        dim3 g(MTILES, 1);   // mma2: relu(A3@W1b + b1b) -> pre (fp32 + fp16 shadow) + BN1 stats
        k_mma<0><<<g, 256, 65536>>>(A3, B2b, b1b, pre, nullptr, N_NODES, DIM, HID2);
    }

    // ---- layer 2 ----
    k_gather<true><<<gatherBlocks, 256>>>(pre, preh, gamma1, beta1);   // BN1 finalize+affine folded
    {
        dim3 g(MTILES, 2);   // mma3: fused gemv -> out2 partials
        k_mma<2><<<g, 256, 65536>>>(A2, B2c, b2a, out2, W2b, N_NODES, HID2, DIM);
    }
    k_bn2pre<<<(N_NODES + 255) / 256, 256>>>(b2b);
    k_bn2norm<<<(N_NODES + 255) / 256, 256>>>(gamma2, beta2, (float*)d_out);
}

// round 15
// speedup vs baseline: 2.3821x; 1.0370x over previous
#include <cuda_runtime.h>
#include <cuda_fp16.h>
#include <cstdint>

#define N_NODES 50000
#define N_EDGES 1600000
#define DIM 128
#define HID2 256
#define BN_EPS 1e-5f

#define MPAD 50048          // 391 * 128
#define MTILES 391

// ---------------- scratch (static device globals; no runtime alloc) ----------------
__device__ __align__(16) float g_pre[(size_t)N_NODES * DIM];        // fp32 pre (BN1 input, self term)
__device__ __align__(16) float g_out2[(size_t)N_NODES * 2];
__device__ __align__(16) __half g_xh[(size_t)N_NODES * DIM];        // fp16 copy of x
__device__ __align__(16) __half g_preh[(size_t)N_NODES * DIM];      // fp16 shadow of pre

__device__ __align__(16) __half g_A2[(size_t)MPAD * 256];           // gather1 out: [Mpad, 2*128] split-fp16
__device__ __align__(16) __half g_A3[(size_t)MPAD * 512];           // mma1 out:   [Mpad, 2*256] split-fp16
__device__ __align__(16) __half g_A2h[(size_t)MPAD * 128];          // gather2 out: fp16 [Mpad,128]
__device__ __align__(16) __half g_B2a[(size_t)256 * 256];           // W1a: [256, 2*128] fp16 [hi|lo]
__device__ __align__(16) __half g_B2b[(size_t)128 * 512];           // W1b: [128, 2*256]
__device__ __align__(16) __half g_B2c[(size_t)256 * 256];           // W2a: [256, 2*128]

// CSR scratch
__device__ int   g_deg[N_NODES];
__device__ int   g_rowptr[N_NODES + 1];
__device__ int   g_cur[N_NODES];
__device__ uint2 g_edge[N_EDGES];

__device__ __align__(16) float g_sum1[DIM];
__device__ __align__(16) float g_sq1[DIM];
__device__ float g_bn2[4];

// ---------------- helpers ----------------
__device__ __forceinline__ uint32_t smem_u32(const void* p) {
    uint32_t a;
    asm("{ .reg .u64 t; cvta.to.shared.u64 t, %1; cvt.u32.u64 %0, t; }" : "=r"(a) : "l"(p));
    return a;
}
#define SWZ128(off) ((off) ^ (((off) >> 3) & 0x70))

__device__ __forceinline__ void mma16816h(float* c, const uint32_t* a, const uint32_t* b) {
    asm volatile("mma.sync.aligned.m16n8k16.row.col.f32.f16.f16.f32 "
        "{%0,%1,%2,%3}, {%4,%5,%6,%7}, {%8,%9}, {%0,%1,%2,%3};"
        : "+f"(c[0]), "+f"(c[1]), "+f"(c[2]), "+f"(c[3])
        : "r"(a[0]), "r"(a[1]), "r"(a[2]), "r"(a[3]), "r"(b[0]), "r"(b[1]));
}
#define LDSM4(r, addr) asm volatile("ldmatrix.sync.aligned.m8n8.x4.shared.b16 {%0,%1,%2,%3}, [%4];" \
    : "=r"((r)[0]), "=r"((r)[1]), "=r"((r)[2]), "=r"((r)[3]) : "r"(addr))
#define LDSM2(r, addr) asm volatile("ldmatrix.sync.aligned.m8n8.x2.shared.b16 {%0,%1}, [%2];" \
    : "=r"((r)[0]), "=r"((r)[1]) : "r"(addr))
#define CPASYNC16(dst, src) asm volatile("cp.async.cg.shared.global [%0], [%1], 16;" :: "r"(dst), "l"(src))

__device__ __forceinline__ uint32_t pack_hi2h(float x, float y) {
    __half2 h = __floats2half2_rn(x, y);
    return *(uint32_t*)&h;
}
__device__ __forceinline__ uint32_t pack_lo2h(float x, float y) {
    __half2 h = __floats2half2_rn(x, y);
    float2 hf = __half22float2(h);
    __half2 l = __floats2half2_rn(x - hf.x, y - hf.y);
    return *(uint32_t*)&l;
}

// ---------------- zeroing ----------------
__global__ void __launch_bounds__(256) k_zero() {
    int i = blockIdx.x * blockDim.x + threadIdx.x;
    if (i < N_NODES) g_deg[i] = 0;
    if (i < N_NODES / 2) ((float4*)g_out2)[i] = make_float4(0.f, 0.f, 0.f, 0.f);
    if (i < DIM) { g_sum1[i] = 0.f; g_sq1[i] = 0.f; }
    if (i < 4) g_bn2[i] = 0.f;
}

// ---------------- fused: histogram(ILP8) + x->fp16 + 3 weight splits ----------------
__device__ __forceinline__ void convB_elem(const float* __restrict__ W, __half* __restrict__ out,
                                           int j, int K, int N) {
    int n = j / K, k = j % K;
    float v = W[(size_t)k * N + n];
    __half h = __float2half_rn(v);
    __half l = __float2half_rn(v - __half2float(h));
    size_t base = (size_t)n * 2 * K;
    out[base + k]     = h;
    out[base + K + k] = l;
}

#define CONVX_N (N_NODES * DIM / 4)   // 1,600,000 float4 quads

__global__ void __launch_bounds__(256) k_histconv(const int* __restrict__ dst, int nE8, int nEdges,
                                                  const float* __restrict__ x,
                                                  const float* __restrict__ W1a,
                                                  const float* __restrict__ W1b,
                                                  const float* __restrict__ W2a) {
    int i = blockIdx.x * blockDim.x + threadIdx.x;
    if (i < nE8) {
        int4 d0 = ((const int4*)dst)[2 * i];
        int4 d1 = ((const int4*)dst)[2 * i + 1];
        atomicAdd(&g_deg[d0.x], 1); atomicAdd(&g_deg[d0.y], 1);
        atomicAdd(&g_deg[d0.z], 1); atomicAdd(&g_deg[d0.w], 1);
        atomicAdd(&g_deg[d1.x], 1); atomicAdd(&g_deg[d1.y], 1);
        atomicAdd(&g_deg[d1.z], 1); atomicAdd(&g_deg[d1.w], 1);
        return;
    }
    if (i == nE8) {
        for (int e = nE8 * 8; e < nEdges; e++) atomicAdd(&g_deg[dst[e]], 1);
        return;
    }
    i -= nE8 + 1;
    if (i < CONVX_N) {
        float4 v = ((const float4*)x)[i];
        __half2 h0 = __floats2half2_rn(v.x, v.y);
        __half2 h1 = __floats2half2_rn(v.z, v.w);
        uint2 o;
        o.x = *(uint32_t*)&h0;
        o.y = *(uint32_t*)&h1;
        ((uint2*)g_xh)[i] = o;
        return;
    }
    i -= CONVX_N;
    if (i < DIM * HID2) { convB_elem(W1a, g_B2a, i, DIM, HID2); return; }
    i -= DIM * HID2;
    if (i < HID2 * DIM) { convB_elem(W1b, g_B2b, i, HID2, DIM); return; }
    i -= HID2 * DIM;
    if (i < DIM * HID2) { convB_elem(W2a, g_B2c, i, DIM, HID2); return; }
}

// ---------------- CSR scan + fill ----------------
__global__ void __launch_bounds__(1024) k_scan() {
    __shared__ int wsum[32];
    __shared__ int carry;
    int t = threadIdx.x, lane = t & 31, w = t >> 5;
    if (t == 0) { carry = 0; g_rowptr[0] = 0; }
    __syncthreads();
    for (int base = 0; base < N_NODES; base += 1024) {
        int i = base + t;
        int v = (i < N_NODES) ? g_deg[i] : 0;
        int s = v;
#pragma unroll
        for (int off = 1; off < 32; off <<= 1) {
            int u = __shfl_up_sync(0xffffffffu, s, off);
            if (lane >= off) s += u;
        }
        if (lane == 31) wsum[w] = s;
        __syncthreads();
        if (w == 0) {
            int ws = wsum[lane];
#pragma unroll
            for (int off = 1; off < 32; off <<= 1) {
                int u = __shfl_up_sync(0xffffffffu, ws, off);
                if (lane >= off) ws += u;
            }
            wsum[lane] = ws;
        }
        __syncthreads();
        int prefix = carry + (w > 0 ? wsum[w - 1] : 0);
        int inc = prefix + s;
        if (i < N_NODES) { g_rowptr[i + 1] = inc; g_cur[i] = inc - v; }
        int total = wsum[31];
        __syncthreads();
        if (t == 0) carry += total;
        __syncthreads();
    }
}

__global__ void __launch_bounds__(256) k_fill(const int* __restrict__ src,
                                              const int* __restrict__ dst,
                                              const float* __restrict__ wgt,
                                              int nE8, int nEdges) {
    int i = blockIdx.x * blockDim.x + threadIdx.x;
    if (i < nE8) {
        int4 s0 = ((const int4*)src)[2 * i];
        int4 s1 = ((const int4*)src)[2 * i + 1];
        int4 d0 = ((const int4*)dst)[2 * i];
        int4 d1 = ((const int4*)dst)[2 * i + 1];
        float4 w0 = ((const float4*)wgt)[2 * i];
        float4 w1 = ((const float4*)wgt)[2 * i + 1];
        int p0 = atomicAdd(&g_cur[d0.x], 1);
        int p1 = atomicAdd(&g_cur[d0.y], 1);
        int p2 = atomicAdd(&g_cur[d0.z], 1);
        int p3 = atomicAdd(&g_cur[d0.w], 1);
        int p4 = atomicAdd(&g_cur[d1.x], 1);
        int p5 = atomicAdd(&g_cur[d1.y], 1);
        int p6 = atomicAdd(&g_cur[d1.z], 1);
        int p7 = atomicAdd(&g_cur[d1.w], 1);
        g_edge[p0] = make_uint2((uint32_t)s0.x, __float_as_uint(w0.x));
        g_edge[p1] = make_uint2((uint32_t)s0.y, __float_as_uint(w0.y));
        g_edge[p2] = make_uint2((uint32_t)s0.z, __float_as_uint(w0.z));
        g_edge[p3] = make_uint2((uint32_t)s0.w, __float_as_uint(w0.w));
        g_edge[p4] = make_uint2((uint32_t)s1.x, __float_as_uint(w1.x));
        g_edge[p5] = make_uint2((uint32_t)s1.y, __float_as_uint(w1.y));
        g_edge[p6] = make_uint2((uint32_t)s1.z, __float_as_uint(w1.z));
        g_edge[p7] = make_uint2((uint32_t)s1.w, __float_as_uint(w1.w));
    } else if (i == nE8) {
        for (int e = nE8 * 8; e < nEdges; e++) {
            int pos = atomicAdd(&g_cur[dst[e]], 1);
            g_edge[pos] = make_uint2((uint32_t)src[e], __float_as_uint(wgt[e]));
        }
    }
}

// ---------------- fused gather: self fp32 + edges fp16, out split-fp16 or fp16 ----------------
// raw = f32self[n] + sum_e w_e * f16[src_e]  (fp32 accumulate).
// BN_MODE: per-block computes BN1 scale/shift from raw stats, applies sc*raw + sh*(1+sum_w).
// OUT_SPLIT: write [hi|lo] split-fp16 row (g_A2, 256 fp16); else plain fp16 row (g_A2h, 128 fp16).
template<bool BN_MODE, bool OUT_SPLIT>
__global__ void __launch_bounds__(256) k_gather(const float* __restrict__ f32self,
                                                const __half* __restrict__ f16,
                                                const float* __restrict__ gamma,
                                                const float* __restrict__ beta) {
    __shared__ __align__(16) float s_sc[DIM];
    __shared__ __align__(16) float s_sh[DIM];
    int t = threadIdx.x;
    if (BN_MODE) {
        if (t < DIM) {
            const float invN = 1.0f / (float)N_NODES;
            float mean = g_sum1[t] * invN;
            float var  = g_sq1[t] * invN - mean * mean;
            float sc   = gamma[t] * rsqrtf(var + BN_EPS);
            s_sc[t] = sc;
            s_sh[t] = beta[t] - mean * sc;
        }
        __syncthreads();
    }
    int lane = t & 31;
    int node = (blockIdx.x * blockDim.x + t) >> 5;
    if (node >= MPAD) return;
    if (node >= N_NODES) {
        if (OUT_SPLIT) {
            uint32_t* o = (uint32_t*)g_A2;
            size_t base = (size_t)node * 128;
            ((uint2*)(o + base))[lane] = make_uint2(0u, 0u);
            ((uint2*)(o + base + 64))[lane] = make_uint2(0u, 0u);
        } else {
            ((uint2*)g_A2h)[(size_t)node * 32 + lane] = make_uint2(0u, 0u);
        }
        return;
    }
    const uint2* h2 = (const uint2*)f16;
    float4 acc = ((const float4*)f32self)[(size_t)node * 32 + lane];
    float sumw = 0.f;
    int j = g_rowptr[node];
    int end = g_rowptr[node + 1];

#define EDGE_TERM(E) do {                                                     \
        float w_ = __uint_as_float((E).y);                                    \
        if (BN_MODE) sumw += w_;                                              \
        uint2 q_ = h2[(size_t)(E).x * 32 + lane];                             \
        float2 fa_ = __half22float2(*(__half2*)&q_.x);                        \
        float2 fb_ = __half22float2(*(__half2*)&q_.y);                        \
        acc.x = fmaf(w_, fa_.x, acc.x); acc.y = fmaf(w_, fa_.y, acc.y);       \
        acc.z = fmaf(w_, fb_.x, acc.z); acc.w = fmaf(w_, fb_.y, acc.w);       \
    } while (0)

    for (; j + 4 <= end; j += 4) {
        uint2 e0 = g_edge[j + 0];
        uint2 e1 = g_edge[j + 1];
        uint2 e2 = g_edge[j + 2];
        uint2 e3 = g_edge[j + 3];
        EDGE_TERM(e0); EDGE_TERM(e1); EDGE_TERM(e2); EDGE_TERM(e3);
    }
    for (; j < end; j++) {
        uint2 e = g_edge[j];
        EDGE_TERM(e);
    }
#undef EDGE_TERM

    if (BN_MODE) {
        float4 sc = *(const float4*)&s_sc[lane * 4];
        float4 sh = *(const float4*)&s_sh[lane * 4];
        float m = 1.f + sumw;
        acc.x = fmaf(sc.x, acc.x, sh.x * m);
        acc.y = fmaf(sc.y, acc.y, sh.y * m);
        acc.z = fmaf(sc.z, acc.z, sh.z * m);
        acc.w = fmaf(sc.w, acc.w, sh.w * m);
    }
    if (OUT_SPLIT) {
        uint32_t* o = (uint32_t*)g_A2;
        size_t base = (size_t)node * 128;
        uint2 hi = make_uint2(pack_hi2h(acc.x, acc.y), pack_hi2h(acc.z, acc.w));
        uint2 lo = make_uint2(pack_lo2h(acc.x, acc.y), pack_lo2h(acc.z, acc.w));
        *(uint2*)(o + base + 2 * lane) = hi;
        *(uint2*)(o + base + 64 + 2 * lane) = lo;
    } else {
        uint2 ov = make_uint2(pack_hi2h(acc.x, acc.y), pack_hi2h(acc.z, acc.w));
        ((uint2*)g_A2h)[(size_t)node * 32 + lane] = ov;
    }
}

// ---------------- HMMA fp16 GEMM ----------------
// MODE 0: split-A 3-term (A [Mpad,2K], B [N,2K]); out: pre fp32 + preh fp16 + BN1 stats (Ntot=128)
// MODE 1: split-A 3-term; out: split-fp16 write into C (row = [hi 256|lo 256] fp16)
// MODE 2: fp16-A 2-term (A [Mpad,K], per chunk A x B_hi then A x B_lo); fused gemv into C
template<int MODE>
__global__ void __launch_bounds__(256, 2)
k_mma(const __half* __restrict__ A, const __half* __restrict__ B,
      const float* __restrict__ bias, float* __restrict__ C,
      const float* __restrict__ w2b, int M, int Ntot, int K) {
    extern __shared__ __align__(1024) uint8_t sm[];
    const int t = threadIdx.x;
    const int lane = t & 31;
    const int wid = t >> 5;
    const int wm = wid >> 2;
    const int wn = wid & 3;
    const int bm = blockIdx.x * 128;
    const int bn = blockIdx.y * 128;
    const int K2 = K * 2;
    const uint32_t smbase = smem_u32(sm);

    const int lrow = t >> 3;
    const int ls16 = t & 7;
    const bool SPLIT_A = (MODE != 2);
    const int cps = K >> 6;
    const int total = SPLIT_A ? 3 * cps : cps;
    const int BUFSZ = SPLIT_A ? 32768 : 49152;

#define LOADCHUNK(c, buf) do {                                                          \
        uint32_t sA_ = smbase + (buf) * BUFSZ;                                          \
        if (SPLIT_A) {                                                                  \
            int s_ = (c) / cps, ck_ = (c) % cps;                                        \
            int aoff_ = (s_ == 1 ? K : 0) + ck_ * 64;                                   \
            int boff_ = (s_ == 2 ? K : 0) + ck_ * 64;                                   \
            uint32_t sB_ = sA_ + 16384;                                                 \
            _Pragma("unroll")                                                           \
            for (int i_ = 0; i_ < 4; i_++) {                                            \
                int row_ = lrow + 32 * i_;                                              \
                uint32_t so_ = SWZ128(row_ * 128 + ls16 * 16);                          \
                CPASYNC16(sA_ + so_, A + (size_t)(bm + row_) * K2 + aoff_ + ls16 * 8);  \
                CPASYNC16(sB_ + so_, B + (size_t)(bn + row_) * K2 + boff_ + ls16 * 8);  \
            }                                                                           \
        } else {                                                                        \
            int koff_ = (c) * 64;                                                       \
            uint32_t sBh_ = sA_ + 16384;                                                \
            uint32_t sBl_ = sA_ + 32768;                                                \
            _Pragma("unroll")                                                           \
            for (int i_ = 0; i_ < 4; i_++) {                                            \
                int row_ = lrow + 32 * i_;                                              \
                uint32_t so_ = SWZ128(row_ * 128 + ls16 * 16);                          \
                CPASYNC16(sA_ + so_, A + (size_t)(bm + row_) * K + koff_ + ls16 * 8);   \
                CPASYNC16(sBh_ + so_, B + (size_t)(bn + row_) * K2 + koff_ + ls16 * 8); \
                CPASYNC16(sBl_ + so_, B + (size_t)(bn + row_) * K2 + K + koff_ + ls16 * 8); \
            }                                                                           \
        }                                                                               \
        asm volatile("cp.async.commit_group;");                                         \
    } while (0)

    float acc[4][4][4] = {};

    LOADCHUNK(0, 0);
    for (int c = 0; c < total; c++) {
        if (c + 1 < total) {
            LOADCHUNK(c + 1, (c + 1) & 1);
            asm volatile("cp.async.wait_group 1;");
        } else {
            asm volatile("cp.async.wait_group 0;");
        }
        __syncthreads();
        uint32_t sA = smbase + (c & 1) * BUFSZ;
        const int t16 = lane & 15;
#pragma unroll
        for (int ks = 0; ks < 4; ks++) {
            uint32_t afr[4][4];
            uint32_t bfr[4][2];
#pragma unroll
            for (int mi = 0; mi < 4; mi++) {
                int row = wm * 64 + mi * 16 + (lane & 15);
                uint32_t addr = sA + SWZ128(row * 128 + ks * 32 + ((lane >> 4) << 4));
                LDSM4(afr[mi], addr);
            }
            if (SPLIT_A) {
                uint32_t sB = sA + 16384;
#pragma unroll
                for (int ni = 0; ni < 4; ni++) {
                    int row = wn * 32 + ni * 8 + (t16 & 7);
                    uint32_t addr = sB + SWZ128(row * 128 + ks * 32 + ((t16 >> 3) << 4));
                    LDSM2(bfr[ni], addr);
                }
#pragma unroll
                for (int mi = 0; mi < 4; mi++)
#pragma unroll
                    for (int ni = 0; ni < 4; ni++)
                        mma16816h(acc[mi][ni], afr[mi], bfr[ni]);
            } else {
                uint32_t sBh = sA + 16384;
                uint32_t sBl = sA + 32768;
#pragma unroll
                for (int ni = 0; ni < 4; ni++) {
                    int row = wn * 32 + ni * 8 + (t16 & 7);
                    uint32_t addr = sBh + SWZ128(row * 128 + ks * 32 + ((t16 >> 3) << 4));
                    LDSM2(bfr[ni], addr);
                }
#pragma unroll
                for (int mi = 0; mi < 4; mi++)
#pragma unroll
                    for (int ni = 0; ni < 4; ni++)
                        mma16816h(acc[mi][ni], afr[mi], bfr[ni]);
#pragma unroll
                for (int ni = 0; ni < 4; ni++) {
                    int row = wn * 32 + ni * 8 + (t16 & 7);
                    uint32_t addr = sBl + SWZ128(row * 128 + ks * 32 + ((t16 >> 3) << 4));
                    LDSM2(bfr[ni], addr);
                }
#pragma unroll
                for (int mi = 0; mi < 4; mi++)
#pragma unroll
                    for (int ni = 0; ni < 4; ni++)
                        mma16816h(acc[mi][ni], afr[mi], bfr[ni]);
            }
        }
        __syncthreads();
    }

    if (MODE == 0) {
        __half2* preh = (__half2*)g_preh;
        float bs[4][2] = {}, bq[4][2] = {};
#pragma unroll
        for (int mi = 0; mi < 4; mi++) {
            int r0 = bm + wm * 64 + mi * 16 + (lane >> 2);
            int r1 = r0 + 8;
#pragma unroll
            for (int ni = 0; ni < 4; ni++) {
                int col = bn + wn * 32 + ni * 8 + (lane & 3) * 2;
                float2 bv = *(const float2*)(bias + col);
                float v00 = fmaxf(acc[mi][ni][0] + bv.x, 0.f);
                float v01 = fmaxf(acc[mi][ni][1] + bv.y, 0.f);
                float v10 = fmaxf(acc[mi][ni][2] + bv.x, 0.f);
                float v11 = fmaxf(acc[mi][ni][3] + bv.y, 0.f);
                if (r0 < M) {
                    *(float2*)(C + (size_t)r0 * Ntot + col) = make_float2(v00, v01);
                    preh[(size_t)r0 * 64 + (col >> 1)] = __floats2half2_rn(v00, v01);
                    bs[ni][0] += v00; bs[ni][1] += v01;
                    bq[ni][0] += v00 * v00; bq[ni][1] += v01 * v01;
                }
                if (r1 < M) {
                    *(float2*)(C + (size_t)r1 * Ntot + col) = make_float2(v10, v11);
                    preh[(size_t)r1 * 64 + (col >> 1)] = __floats2half2_rn(v10, v11);
                    bs[ni][0] += v10; bs[ni][1] += v11;
                    bq[ni][0] += v10 * v10; bq[ni][1] += v11 * v11;
                }
            }
        }
#pragma unroll
        for (int ni = 0; ni < 4; ni++) {
            float s0 = bs[ni][0], s1 = bs[ni][1], q0 = bq[ni][0], q1 = bq[ni][1];
#pragma unroll
            for (int off = 4; off <= 16; off <<= 1) {
                s0 += __shfl_xor_sync(0xffffffffu, s0, off);
                s1 += __shfl_xor_sync(0xffffffffu, s1, off);
                q0 += __shfl_xor_sync(0xffffffffu, q0, off);
                q1 += __shfl_xor_sync(0xffffffffu, q1, off);
            }
            if (lane < 4) {
                int c0 = bn + wn * 32 + ni * 8 + lane * 2;
                atomicAdd(&g_sum1[c0], s0);
                atomicAdd(&g_sum1[c0 + 1], s1);
                atomicAdd(&g_sq1[c0], q0);
                atomicAdd(&g_sq1[c0 + 1], q1);
            }
        }
    } else if (MODE == 1) {
        // split-fp16 write: row = [hi 256 | lo 256] fp16, as half2 with row stride 256 half2
        uint32_t* o = (uint32_t*)C;
#pragma unroll
        for (int mi = 0; mi < 4; mi++) {
            int r0 = bm + wm * 64 + mi * 16 + (lane >> 2);
            int r1 = r0 + 8;
#pragma unroll
            for (int ni = 0; ni < 4; ni++) {
                int col = bn + wn * 32 + ni * 8 + (lane & 3) * 2;
                float2 bv = *(const float2*)(bias + col);
                float v00 = fmaxf(acc[mi][ni][0] + bv.x, 0.f);
                float v01 = fmaxf(acc[mi][ni][1] + bv.y, 0.f);
                float v10 = fmaxf(acc[mi][ni][2] + bv.x, 0.f);
                float v11 = fmaxf(acc[mi][ni][3] + bv.y, 0.f);
                int ci = col >> 1;
                o[(size_t)r0 * 256 + ci]       = pack_hi2h(v00, v01);
                o[(size_t)r0 * 256 + 128 + ci] = pack_lo2h(v00, v01);
                o[(size_t)r1 * 256 + ci]       = pack_hi2h(v10, v11);
                o[(size_t)r1 * 256 + 128 + ci] = pack_lo2h(v10, v11);
            }
        }
    } else {
#pragma unroll
        for (int mi = 0; mi < 4; mi++) {
            int r0 = bm + wm * 64 + mi * 16 + (lane >> 2);
            int r1 = r0 + 8;
            float p00 = 0.f, p01 = 0.f, p10 = 0.f, p11 = 0.f;
#pragma unroll
            for (int ni = 0; ni < 4; ni++) {
                int col = bn + wn * 32 + ni * 8 + (lane & 3) * 2;
                float2 bv = *(const float2*)(bias + col);
                float h0 = fmaxf(acc[mi][ni][0] + bv.x, 0.f);
                float h1 = fmaxf(acc[mi][ni][1] + bv.y, 0.f);
                float h2 = fmaxf(acc[mi][ni][2] + bv.x, 0.f);
                float h3 = fmaxf(acc[mi][ni][3] + bv.y, 0.f);
                float2 wv0 = *(const float2*)(w2b + col * 2);
                float2 wv1 = *(const float2*)(w2b + (col + 1) * 2);
                p00 = fmaf(h0, wv0.x, fmaf(h1, wv1.x, p00));
                p01 = fmaf(h0, wv0.y, fmaf(h1, wv1.y, p01));
                p10 = fmaf(h2, wv0.x, fmaf(h3, wv1.x, p10));
                p11 = fmaf(h2, wv0.y, fmaf(h3, wv1.y, p11));
            }
#pragma unroll
            for (int off = 1; off <= 2; off <<= 1) {
                p00 += __shfl_xor_sync(0xffffffffu, p00, off);
                p01 += __shfl_xor_sync(0xffffffffu, p01, off);
                p10 += __shfl_xor_sync(0xffffffffu, p10, off);
                p11 += __shfl_xor_sync(0xffffffffu, p11, off);
            }
            if ((lane & 3) == 0) {
                if (r0 < M) {
                    atomicAdd(&C[(size_t)r0 * 2 + 0], p00);
                    atomicAdd(&C[(size_t)r0 * 2 + 1], p01);
                }
                if (r1 < M) {
                    atomicAdd(&C[(size_t)r1 * 2 + 0], p10);
                    atomicAdd(&C[(size_t)r1 * 2 + 1], p11);
                }
            }
        }
    }
#undef LOADCHUNK
}

// ---------------- BN2 ----------------
__global__ void __launch_bounds__(256) k_bn2pre(const float* __restrict__ b2b) {
    __shared__ float red[8][4];
    int t = threadIdx.x;
    int lane = t & 31, wid = t >> 5;
    int r = blockIdx.x * 256 + t;
    float s0 = 0.f, s1 = 0.f, q0 = 0.f, q1 = 0.f;
    if (r < N_NODES) {
        float2 v = ((float2*)g_out2)[r];
        v.x = fmaxf(v.x + b2b[0], 0.f);
        v.y = fmaxf(v.y + b2b[1], 0.f);
        ((float2*)g_out2)[r] = v;
        s0 = v.x; s1 = v.y; q0 = v.x * v.x; q1 = v.y * v.y;
    }
#pragma unroll
    for (int off = 16; off; off >>= 1) {
        s0 += __shfl_xor_sync(0xffffffffu, s0, off);
        s1 += __shfl_xor_sync(0xffffffffu, s1, off);
        q0 += __shfl_xor_sync(0xffffffffu, q0, off);
        q1 += __shfl_xor_sync(0xffffffffu, q1, off);
    }
    if (lane == 0) { red[wid][0] = s0; red[wid][1] = s1; red[wid][2] = q0; red[wid][3] = q1; }
    __syncthreads();
    if (t < 4) {
        float acc = 0.f;
#pragma unroll
        for (int wI = 0; wI < 8; wI++) acc += red[wI][t];
        atomicAdd(&g_bn2[t], acc);
    }
}

__global__ void __launch_bounds__(256) k_bn2norm(const float* __restrict__ gamma2,
                                                 const float* __restrict__ beta2,
                                                 float* __restrict__ out) {
    __shared__ float ss[4];
    int t = threadIdx.x;
    if (t < 2) {
        const float invN = 1.0f / (float)N_NODES;
        float mean = g_bn2[t] * invN;
        float var  = g_bn2[2 + t] * invN - mean * mean;
        float sc   = gamma2[t] * rsqrtf(var + BN_EPS);
        ss[t]     = sc;
        ss[2 + t] = beta2[t] - mean * sc;
    }
    __syncthreads();
    int r = blockIdx.x * blockDim.x + t;
    if (r >= N_NODES) return;
    float2 v = ((const float2*)g_out2)[r];
    float2 o;
    o.x = fmaf(v.x, ss[0], ss[2]);
    o.y = fmaf(v.y, ss[1], ss[3]);
    ((float2*)out)[r] = o;
}

// ---------------- launch ----------------
extern "C" void kernel_launch(void* const* d_in, const int* in_sizes, int n_in,
                              void* d_out, int out_size) {
    const float* x      = (const float*)d_in[0];
    const int*   eidx   = (const int*)d_in[1];
    const float* ew     = (const float*)d_in[3];
    const float* W1a    = (const float*)d_in[4];
    const float* b1a    = (const float*)d_in[5];
    const float* W1b    = (const float*)d_in[6];
    const float* b1b    = (const float*)d_in[7];
    const float* gamma1 = (const float*)d_in[8];
    const float* beta1  = (const float*)d_in[9];
    const float* W2a    = (const float*)d_in[10];
    const float* b2a    = (const float*)d_in[11];
    const float* W2b    = (const float*)d_in[12];
    const float* b2b    = (const float*)d_in[13];
    const float* gamma2 = (const float*)d_in[14];
    const float* beta2  = (const float*)d_in[15];

    const int nEdges = in_sizes[1] / 2;
    const int* src = eidx;
    const int* dst = eidx + nEdges;
    const int nE8 = nEdges / 8;

    float *pre, *out2;
    __half *xh, *preh, *A2, *A3, *A2h, *B2a, *B2b, *B2c;
    cudaGetSymbolAddress((void**)&pre,  g_pre);
    cudaGetSymbolAddress((void**)&out2, g_out2);
    cudaGetSymbolAddress((void**)&xh,   g_xh);
    cudaGetSymbolAddress((void**)&preh, g_preh);
    cudaGetSymbolAddress((void**)&A2,   g_A2);
    cudaGetSymbolAddress((void**)&A3,   g_A3);
    cudaGetSymbolAddress((void**)&A2h,  g_A2h);
    cudaGetSymbolAddress((void**)&B2a,  g_B2a);
    cudaGetSymbolAddress((void**)&B2b,  g_B2b);
    cudaGetSymbolAddress((void**)&B2c,  g_B2c);

    cudaFuncSetAttribute(k_mma<0>, cudaFuncAttributeMaxDynamicSharedMemorySize, 65536);
    cudaFuncSetAttribute(k_mma<1>, cudaFuncAttributeMaxDynamicSharedMemorySize, 65536);
    cudaFuncSetAttribute(k_mma<2>, cudaFuncAttributeMaxDynamicSharedMemorySize, 98304);

    const int gatherBlocks = (MPAD * 32 + 255) / 256;
    const int edgeBlocks8 = (nE8 + 1 + 255) / 256;
    const int histconvItems = (nE8 + 1) + CONVX_N + 3 * DIM * HID2;

    // ---- setup + CSR build ----
    k_zero<<<(N_NODES + 255) / 256, 256>>>();
    k_histconv<<<(histconvItems + 255) / 256, 256>>>(dst, nE8, nEdges, x, W1a, W1b, W2a);
    k_scan<<<1, 1024>>>();
    k_fill<<<edgeBlocks8, 256>>>(src, dst, ew, nE8, nEdges);

    // ---- layer 1 (split-fp16 3-term precision) ----
    k_gather<false, true><<<gatherBlocks, 256>>>(x, xh, nullptr, nullptr);
    {
        dim3 g(MTILES, 2);   // mma1: relu(A2@W1a + b1a) -> A3 (split-fp16)
        k_mma<1><<<g, 256, 65536>>>(A2, B2a, b1a, (float*)A3, nullptr, N_NODES, HID2, DIM);
    }
    {
        dim3 g(MTILES, 1);   // mma2: relu(A3@W1b + b1b) -> pre fp32 + preh fp16 + BN1 stats
        k_mma<0><<<g, 256, 65536>>>(A3, B2b, b1b, pre, nullptr, N_NODES, DIM, HID2);
    }

    // ---- layer 2 (fp16-A 2-term) ----
    k_gather<true, false><<<gatherBlocks, 256>>>(pre, preh, gamma1, beta1);  // BN1 finalize+affine folded
    {
        dim3 g(MTILES, 2);   // mma3: fused gemv -> out2 partials
        k_mma<2><<<g, 256, 98304>>>(A2h, B2c, b2a, out2, W2b, N_NODES, HID2, DIM);
    }
    k_bn2pre<<<(N_NODES + 255) / 256, 256>>>(b2b);
    k_bn2norm<<<(N_NODES + 255) / 256, 256>>>(gamma2, beta2, (float*)d_out);
}

// round 17
// speedup vs baseline: 2.5455x; 1.0686x over previous
#include <cuda_runtime.h>
#include <cuda_fp16.h>
#include <cstdint>

#define N_NODES 50000
#define N_EDGES 1600000
#define DIM 128
#define HID2 256
#define BN_EPS 1e-5f

#define MPAD 50048          // 391 * 128
#define MTILES 391

// ---------------- scratch (static device globals; no runtime alloc) ----------------
__device__ __align__(16) float g_pre[(size_t)N_NODES * DIM];        // fp32 pre (BN1 input, self term)
__device__ __align__(16) float g_out2[(size_t)N_NODES * 2];
__device__ __align__(16) __half g_xh[(size_t)N_NODES * DIM];        // fp16 copy of x
__device__ __align__(16) __half g_preh[(size_t)N_NODES * DIM];      // fp16 shadow of pre

__device__ __align__(16) __half g_A2h[(size_t)MPAD * 128];          // gather out: fp16 [Mpad,128]
__device__ __align__(16) __half g_A3[(size_t)MPAD * 512];           // mma1 out: [Mpad, 2*256] split-fp16
__device__ __align__(16) __half g_B2a[(size_t)256 * 256];           // W1a: [256, 2*128] fp16 [hi|lo]
__device__ __align__(16) __half g_B2b[(size_t)128 * 512];           // W1b: [128, 2*256]
__device__ __align__(16) __half g_B2c[(size_t)256 * 256];           // W2a: [256, 2*128]

// CSR scratch
__device__ int   g_deg[N_NODES];
__device__ int   g_rowptr[N_NODES + 1];
__device__ int   g_cur[N_NODES];
__device__ uint2 g_edge[N_EDGES];

__device__ __align__(16) float g_sum1[DIM];
__device__ __align__(16) float g_sq1[DIM];
__device__ float g_bn2[4];

// ---------------- helpers ----------------
__device__ __forceinline__ uint32_t smem_u32(const void* p) {
    uint32_t a;
    asm("{ .reg .u64 t; cvta.to.shared.u64 t, %1; cvt.u32.u64 %0, t; }" : "=r"(a) : "l"(p));
    return a;
}
#define SWZ128(off) ((off) ^ (((off) >> 3) & 0x70))

__device__ __forceinline__ void mma16816h(float* c, const uint32_t* a, const uint32_t* b) {
    asm volatile("mma.sync.aligned.m16n8k16.row.col.f32.f16.f16.f32 "
        "{%0,%1,%2,%3}, {%4,%5,%6,%7}, {%8,%9}, {%0,%1,%2,%3};"
        : "+f"(c[0]), "+f"(c[1]), "+f"(c[2]), "+f"(c[3])
        : "r"(a[0]), "r"(a[1]), "r"(a[2]), "r"(a[3]), "r"(b[0]), "r"(b[1]));
}
#define LDSM4(r, addr) asm volatile("ldmatrix.sync.aligned.m8n8.x4.shared.b16 {%0,%1,%2,%3}, [%4];" \
    : "=r"((r)[0]), "=r"((r)[1]), "=r"((r)[2]), "=r"((r)[3]) : "r"(addr))
#define LDSM2(r, addr) asm volatile("ldmatrix.sync.aligned.m8n8.x2.shared.b16 {%0,%1}, [%2];" \
    : "=r"((r)[0]), "=r"((r)[1]) : "r"(addr))
#define CPASYNC16(dst, src) asm volatile("cp.async.cg.shared.global [%0], [%1], 16;" :: "r"(dst), "l"(src))

__device__ __forceinline__ uint32_t pack_hi2h(float x, float y) {
    __half2 h = __floats2half2_rn(x, y);
    return *(uint32_t*)&h;
}
__device__ __forceinline__ uint32_t pack_lo2h(float x, float y) {
    __half2 h = __floats2half2_rn(x, y);
    float2 hf = __half22float2(h);
    __half2 l = __floats2half2_rn(x - hf.x, y - hf.y);
    return *(uint32_t*)&l;
}

// ---------------- zeroing ----------------
__global__ void __launch_bounds__(256) k_zero() {
    int i = blockIdx.x * blockDim.x + threadIdx.x;
    if (i < N_NODES) g_deg[i] = 0;
    if (i < N_NODES / 2) ((float4*)g_out2)[i] = make_float4(0.f, 0.f, 0.f, 0.f);
    if (i < DIM) { g_sum1[i] = 0.f; g_sq1[i] = 0.f; }
    if (i < 4) g_bn2[i] = 0.f;
}

// ---------------- fused: histogram(ILP8) + x->fp16 + 3 weight splits ----------------
__device__ __forceinline__ void convB_elem(const float* __restrict__ W, __half* __restrict__ out,
                                           int j, int K, int N) {
    int n = j / K, k = j % K;
    float v = W[(size_t)k * N + n];
    __half h = __float2half_rn(v);
    __half l = __float2half_rn(v - __half2float(h));
    size_t base = (size_t)n * 2 * K;
    out[base + k]     = h;
    out[base + K + k] = l;
}

#define CONVX_N (N_NODES * DIM / 4)   // 1,600,000 float4 quads

__global__ void __launch_bounds__(256) k_histconv(const int* __restrict__ dst, int nE8, int nEdges,
                                                  const float* __restrict__ x,
                                                  const float* __restrict__ W1a,
                                                  const float* __restrict__ W1b,
                                                  const float* __restrict__ W2a) {
    int i = blockIdx.x * blockDim.x + threadIdx.x;
    if (i < nE8) {
        int4 d0 = ((const int4*)dst)[2 * i];
        int4 d1 = ((const int4*)dst)[2 * i + 1];
        atomicAdd(&g_deg[d0.x], 1); atomicAdd(&g_deg[d0.y], 1);
        atomicAdd(&g_deg[d0.z], 1); atomicAdd(&g_deg[d0.w], 1);
        atomicAdd(&g_deg[d1.x], 1); atomicAdd(&g_deg[d1.y], 1);
        atomicAdd(&g_deg[d1.z], 1); atomicAdd(&g_deg[d1.w], 1);
        return;
    }
    if (i == nE8) {
        for (int e = nE8 * 8; e < nEdges; e++) atomicAdd(&g_deg[dst[e]], 1);
        return;
    }
    i -= nE8 + 1;
    if (i < CONVX_N) {
        float4 v = ((const float4*)x)[i];
        __half2 h0 = __floats2half2_rn(v.x, v.y);
        __half2 h1 = __floats2half2_rn(v.z, v.w);
        uint2 o;
        o.x = *(uint32_t*)&h0;
        o.y = *(uint32_t*)&h1;
        ((uint2*)g_xh)[i] = o;
        return;
    }
    i -= CONVX_N;
    if (i < DIM * HID2) { convB_elem(W1a, g_B2a, i, DIM, HID2); return; }
    i -= DIM * HID2;
    if (i < HID2 * DIM) { convB_elem(W1b, g_B2b, i, HID2, DIM); return; }
    i -= HID2 * DIM;
    if (i < DIM * HID2) { convB_elem(W2a, g_B2c, i, DIM, HID2); return; }
}

// ---------------- CSR scan + fill ----------------
__global__ void __launch_bounds__(1024) k_scan() {
    __shared__ int wsum[32];
    __shared__ int carry;
    int t = threadIdx.x, lane = t & 31, w = t >> 5;
    if (t == 0) { carry = 0; g_rowptr[0] = 0; }
    __syncthreads();
    for (int base = 0; base < N_NODES; base += 1024) {
        int i = base + t;
        int v = (i < N_NODES) ? g_deg[i] : 0;
        int s = v;
#pragma unroll
        for (int off = 1; off < 32; off <<= 1) {
            int u = __shfl_up_sync(0xffffffffu, s, off);
            if (lane >= off) s += u;
        }
        if (lane == 31) wsum[w] = s;
        __syncthreads();
        if (w == 0) {
            int ws = wsum[lane];
#pragma unroll
            for (int off = 1; off < 32; off <<= 1) {
                int u = __shfl_up_sync(0xffffffffu, ws, off);
                if (lane >= off) ws += u;
            }
            wsum[lane] = ws;
        }
        __syncthreads();
        int prefix = carry + (w > 0 ? wsum[w - 1] : 0);
        int inc = prefix + s;
        if (i < N_NODES) { g_rowptr[i + 1] = inc; g_cur[i] = inc - v; }
        int total = wsum[31];
        __syncthreads();
        if (t == 0) carry += total;
        __syncthreads();
    }
}

__global__ void __launch_bounds__(256) k_fill(const int* __restrict__ src,
                                              const int* __restrict__ dst,
                                              const float* __restrict__ wgt,
                                              int nEdges) {
    int e = blockIdx.x * blockDim.x + threadIdx.x;
    if (e >= nEdges) return;
    int d = dst[e];
    int pos = atomicAdd(&g_cur[d], 1);
    g_edge[pos] = make_uint2((uint32_t)src[e], __float_as_uint(wgt[e]));
}

// ---------------- fused gather: self fp32 + edges fp16 -> plain fp16 row ----------------
// raw = f32self[n] + sum_e w_e * f16[src_e]  (fp32 accumulate); out g_A2h.
// BN_MODE: per-block computes BN1 scale/shift from raw stats, applies sc*raw + sh*(1+sum_w).
template<bool BN_MODE>
__global__ void __launch_bounds__(256) k_gather(const float* __restrict__ f32self,
                                                const __half* __restrict__ f16,
                                                const float* __restrict__ gamma,
                                                const float* __restrict__ beta) {
    __shared__ __align__(16) float s_sc[DIM];
    __shared__ __align__(16) float s_sh[DIM];
    int t = threadIdx.x;
    if (BN_MODE) {
        if (t < DIM) {
            const float invN = 1.0f / (float)N_NODES;
            float mean = g_sum1[t] * invN;
            float var  = g_sq1[t] * invN - mean * mean;
            float sc   = gamma[t] * rsqrtf(var + BN_EPS);
            s_sc[t] = sc;
            s_sh[t] = beta[t] - mean * sc;
        }
        __syncthreads();
    }
    int lane = t & 31;
    int node = (blockIdx.x * blockDim.x + t) >> 5;
    if (node >= MPAD) return;
    if (node >= N_NODES) {
        ((uint2*)g_A2h)[(size_t)node * 32 + lane] = make_uint2(0u, 0u);
        return;
    }
    const uint2* h2 = (const uint2*)f16;
    float4 acc = ((const float4*)f32self)[(size_t)node * 32 + lane];
    float sumw = 0.f;
    int j = g_rowptr[node];
    int end = g_rowptr[node + 1];

#define EDGE_TERM(E) do {                                                     \
        float w_ = __uint_as_float((E).y);                                    \
        if (BN_MODE) sumw += w_;                                              \
        uint2 q_ = h2[(size_t)(E).x * 32 + lane];                             \
        float2 fa_ = __half22float2(*(__half2*)&q_.x);                        \
        float2 fb_ = __half22float2(*(__half2*)&q_.y);                        \
        acc.x = fmaf(w_, fa_.x, acc.x); acc.y = fmaf(w_, fa_.y, acc.y);       \
        acc.z = fmaf(w_, fb_.x, acc.z); acc.w = fmaf(w_, fb_.y, acc.w);       \
    } while (0)

    for (; j + 8 <= end; j += 8) {
        uint2 e0 = g_edge[j + 0];
        uint2 e1 = g_edge[j + 1];
        uint2 e2 = g_edge[j + 2];
        uint2 e3 = g_edge[j + 3];
        uint2 e4 = g_edge[j + 4];
        uint2 e5 = g_edge[j + 5];
        uint2 e6 = g_edge[j + 6];
        uint2 e7 = g_edge[j + 7];
        EDGE_TERM(e0); EDGE_TERM(e1); EDGE_TERM(e2); EDGE_TERM(e3);
        EDGE_TERM(e4); EDGE_TERM(e5); EDGE_TERM(e6); EDGE_TERM(e7);
    }
    for (; j < end; j++) {
        uint2 e = g_edge[j];
        EDGE_TERM(e);
    }
#undef EDGE_TERM

    if (BN_MODE) {
        float4 sc = *(const float4*)&s_sc[lane * 4];
        float4 sh = *(const float4*)&s_sh[lane * 4];
        float m = 1.f + sumw;
        acc.x = fmaf(sc.x, acc.x, sh.x * m);
        acc.y = fmaf(sc.y, acc.y, sh.y * m);
        acc.z = fmaf(sc.z, acc.z, sh.z * m);
        acc.w = fmaf(sc.w, acc.w, sh.w * m);
    }
    uint2 ov = make_uint2(pack_hi2h(acc.x, acc.y), pack_hi2h(acc.z, acc.w));
    ((uint2*)g_A2h)[(size_t)node * 32 + lane] = ov;
}

// ---------------- HMMA fp16 GEMM ----------------
// MODE 0 (mma2): split-A 3-term (A [Mpad,2K]); out: pre fp32 + preh fp16 + BN1 stats (Ntot=128)
// MODE 1 (mma1): fp16-A 2-term; out: split-fp16 write into C (row = [hi 256|lo 256] fp16)
// MODE 2 (mma3): fp16-A 2-term; fused gemv: atomicAdd partials of relu(.) @ w2b[256,2] into C
template<int MODE>
__global__ void __launch_bounds__(256, 2)
k_mma(const __half* __restrict__ A, const __half* __restrict__ B,
      const float* __restrict__ bias, float* __restrict__ C,
      const float* __restrict__ w2b, int M, int Ntot, int K) {
    extern __shared__ __align__(1024) uint8_t sm[];
    const int t = threadIdx.x;
    const int lane = t & 31;
    const int wid = t >> 5;
    const int wm = wid >> 2;
    const int wn = wid & 3;
    const int bm = blockIdx.x * 128;
    const int bn = blockIdx.y * 128;
    const int K2 = K * 2;
    const uint32_t smbase = smem_u32(sm);

    const int lrow = t >> 3;
    const int ls16 = t & 7;
    const bool SPLIT_A = (MODE == 0);
    const int cps = K >> 6;
    const int total = SPLIT_A ? 3 * cps : cps;
    const int BUFSZ = SPLIT_A ? 32768 : 49152;

#define LOADCHUNK(c, buf) do {                                                          \
        uint32_t sA_ = smbase + (buf) * BUFSZ;                                          \
        if (SPLIT_A) {                                                                  \
            int s_ = (c) / cps, ck_ = (c) % cps;                                        \
            int aoff_ = (s_ == 1 ? K : 0) + ck_ * 64;                                   \
            int boff_ = (s_ == 2 ? K : 0) + ck_ * 64;                                   \
            uint32_t sB_ = sA_ + 16384;                                                 \
            _Pragma("unroll")                                                           \
            for (int i_ = 0; i_ < 4; i_++) {                                            \
                int row_ = lrow + 32 * i_;                                              \
                uint32_t so_ = SWZ128(row_ * 128 + ls16 * 16);                          \
                CPASYNC16(sA_ + so_, A + (size_t)(bm + row_) * K2 + aoff_ + ls16 * 8);  \
                CPASYNC16(sB_ + so_, B + (size_t)(bn + row_) * K2 + boff_ + ls16 * 8);  \
            }                                                                           \
        } else {                                                                        \
            int koff_ = (c) * 64;                                                       \
            uint32_t sBh_ = sA_ + 16384;                                                \
            uint32_t sBl_ = sA_ + 32768;                                                \
            _Pragma("unroll")                                                           \
            for (int i_ = 0; i_ < 4; i_++) {                                            \
                int row_ = lrow + 32 * i_;                                              \
                uint32_t so_ = SWZ128(row_ * 128 + ls16 * 16);                          \
                CPASYNC16(sA_ + so_, A + (size_t)(bm + row_) * K + koff_ + ls16 * 8);   \
                CPASYNC16(sBh_ + so_, B + (size_t)(bn + row_) * K2 + koff_ + ls16 * 8); \
                CPASYNC16(sBl_ + so_, B + (size_t)(bn + row_) * K2 + K + koff_ + ls16 * 8); \
            }                                                                           \
        }                                                                               \
        asm volatile("cp.async.commit_group;");                                         \
    } while (0)

    float acc[4][4][4] = {};

    LOADCHUNK(0, 0);
    for (int c = 0; c < total; c++) {
        if (c + 1 < total) {
            LOADCHUNK(c + 1, (c + 1) & 1);
            asm volatile("cp.async.wait_group 1;");
        } else {
            asm volatile("cp.async.wait_group 0;");
        }
        __syncthreads();
        uint32_t sA = smbase + (c & 1) * BUFSZ;
        const int t16 = lane & 15;
#pragma unroll
        for (int ks = 0; ks < 4; ks++) {
            uint32_t afr[4][4];
            uint32_t bfr[4][2];
#pragma unroll
            for (int mi = 0; mi < 4; mi++) {
                int row = wm * 64 + mi * 16 + (lane & 15);
                uint32_t addr = sA + SWZ128(row * 128 + ks * 32 + ((lane >> 4) << 4));
                LDSM4(afr[mi], addr);
            }
            if (SPLIT_A) {
                uint32_t sB = sA + 16384;
#pragma unroll
                for (int ni = 0; ni < 4; ni++) {
                    int row = wn * 32 + ni * 8 + (t16 & 7);
                    uint32_t addr = sB + SWZ128(row * 128 + ks * 32 + ((t16 >> 3) << 4));
                    LDSM2(bfr[ni], addr);
                }
#pragma unroll
                for (int mi = 0; mi < 4; mi++)
#pragma unroll
                    for (int ni = 0; ni < 4; ni++)
                        mma16816h(acc[mi][ni], afr[mi], bfr[ni]);
            } else {
                uint32_t sBh = sA + 16384;
                uint32_t sBl = sA + 32768;
#pragma unroll
                for (int ni = 0; ni < 4; ni++) {
                    int row = wn * 32 + ni * 8 + (t16 & 7);
                    uint32_t addr = sBh + SWZ128(row * 128 + ks * 32 + ((t16 >> 3) << 4));
                    LDSM2(bfr[ni], addr);
                }
#pragma unroll
                for (int mi = 0; mi < 4; mi++)
#pragma unroll
                    for (int ni = 0; ni < 4; ni++)
                        mma16816h(acc[mi][ni], afr[mi], bfr[ni]);
#pragma unroll
                for (int ni = 0; ni < 4; ni++) {
                    int row = wn * 32 + ni * 8 + (t16 & 7);
                    uint32_t addr = sBl + SWZ128(row * 128 + ks * 32 + ((t16 >> 3) << 4));
                    LDSM2(bfr[ni], addr);
                }
#pragma unroll
                for (int mi = 0; mi < 4; mi++)
#pragma unroll
                    for (int ni = 0; ni < 4; ni++)
                        mma16816h(acc[mi][ni], afr[mi], bfr[ni]);
            }
        }
        __syncthreads();
    }

    if (MODE == 0) {
        __half2* preh = (__half2*)g_preh;
        float bs[4][2] = {}, bq[4][2] = {};
#pragma unroll
        for (int mi = 0; mi < 4; mi++) {
            int r0 = bm + wm * 64 + mi * 16 + (lane >> 2);
            int r1 = r0 + 8;
#pragma unroll
            for (int ni = 0; ni < 4; ni++) {
                int col = bn + wn * 32 + ni * 8 + (lane & 3) * 2;
                float2 bv = *(const float2*)(bias + col);
                float v00 = fmaxf(acc[mi][ni][0] + bv.x, 0.f);
                float v01 = fmaxf(acc[mi][ni][1] + bv.y, 0.f);
                float v10 = fmaxf(acc[mi][ni][2] + bv.x, 0.f);
                float v11 = fmaxf(acc[mi][ni][3] + bv.y, 0.f);
                if (r0 < M) {
                    *(float2*)(C + (size_t)r0 * Ntot + col) = make_float2(v00, v01);
                    preh[(size_t)r0 * 64 + (col >> 1)] = __floats2half2_rn(v00, v01);
                    bs[ni][0] += v00; bs[ni][1] += v01;
                    bq[ni][0] += v00 * v00; bq[ni][1] += v01 * v01;
                }
                if (r1 < M) {
                    *(float2*)(C + (size_t)r1 * Ntot + col) = make_float2(v10, v11);
                    preh[(size_t)r1 * 64 + (col >> 1)] = __floats2half2_rn(v10, v11);
                    bs[ni][0] += v10; bs[ni][1] += v11;
                    bq[ni][0] += v10 * v10; bq[ni][1] += v11 * v11;
                }
            }
        }
#pragma unroll
        for (int ni = 0; ni < 4; ni++) {
            float s0 = bs[ni][0], s1 = bs[ni][1], q0 = bq[ni][0], q1 = bq[ni][1];
#pragma unroll
            for (int off = 4; off <= 16; off <<= 1) {
                s0 += __shfl_xor_sync(0xffffffffu, s0, off);
                s1 += __shfl_xor_sync(0xffffffffu, s1, off);
                q0 += __shfl_xor_sync(0xffffffffu, q0, off);
                q1 += __shfl_xor_sync(0xffffffffu, q1, off);
            }
            if (lane < 4) {
                int c0 = bn + wn * 32 + ni * 8 + lane * 2;
                atomicAdd(&g_sum1[c0], s0);
                atomicAdd(&g_sum1[c0 + 1], s1);
                atomicAdd(&g_sq1[c0], q0);
                atomicAdd(&g_sq1[c0 + 1], q1);
            }
        }
    } else if (MODE == 1) {
        // split-fp16 write: row = [hi 256 | lo 256] fp16, row stride 256 u32
        uint32_t* o = (uint32_t*)C;
#pragma unroll
        for (int mi = 0; mi < 4; mi++) {
            int r0 = bm + wm * 64 + mi * 16 + (lane >> 2);
            int r1 = r0 + 8;
#pragma unroll
            for (int ni = 0; ni < 4; ni++) {
                int col = bn + wn * 32 + ni * 8 + (lane & 3) * 2;
                float2 bv = *(const float2*)(bias + col);
                float v00 = fmaxf(acc[mi][ni][0] + bv.x, 0.f);
                float v01 = fmaxf(acc[mi][ni][1] + bv.y, 0.f);
                float v10 = fmaxf(acc[mi][ni][2] + bv.x, 0.f);
                float v11 = fmaxf(acc[mi][ni][3] + bv.y, 0.f);
                int ci = col >> 1;
                o[(size_t)r0 * 256 + ci]       = pack_hi2h(v00, v01);
                o[(size_t)r0 * 256 + 128 + ci] = pack_lo2h(v00, v01);
                o[(size_t)r1 * 256 + ci]       = pack_hi2h(v10, v11);
                o[(size_t)r1 * 256 + 128 + ci] = pack_lo2h(v10, v11);
            }
        }
    } else {
#pragma unroll
        for (int mi = 0; mi < 4; mi++) {
            int r0 = bm + wm * 64 + mi * 16 + (lane >> 2);
            int r1 = r0 + 8;
            float p00 = 0.f, p01 = 0.f, p10 = 0.f, p11 = 0.f;
#pragma unroll
            for (int ni = 0; ni < 4; ni++) {
                int col = bn + wn * 32 + ni * 8 + (lane & 3) * 2;
                float2 bv = *(const float2*)(bias + col);
                float h0 = fmaxf(acc[mi][ni][0] + bv.x, 0.f);
                float h1 = fmaxf(acc[mi][ni][1] + bv.y, 0.f);
                float h2 = fmaxf(acc[mi][ni][2] + bv.x, 0.f);
                float h3 = fmaxf(acc[mi][ni][3] + bv.y, 0.f);
                float2 wv0 = *(const float2*)(w2b + col * 2);
                float2 wv1 = *(const float2*)(w2b + (col + 1) * 2);
                p00 = fmaf(h0, wv0.x, fmaf(h1, wv1.x, p00));
                p01 = fmaf(h0, wv0.y, fmaf(h1, wv1.y, p01));
                p10 = fmaf(h2, wv0.x, fmaf(h3, wv1.x, p10));
                p11 = fmaf(h2, wv0.y, fmaf(h3, wv1.y, p11));
            }
#pragma unroll
            for (int off = 1; off <= 2; off <<= 1) {
                p00 += __shfl_xor_sync(0xffffffffu, p00, off);
                p01 += __shfl_xor_sync(0xffffffffu, p01, off);
                p10 += __shfl_xor_sync(0xffffffffu, p10, off);
                p11 += __shfl_xor_sync(0xffffffffu, p11, off);
            }
            if ((lane & 3) == 0) {
                if (r0 < M) {
                    atomicAdd(&C[(size_t)r0 * 2 + 0], p00);
                    atomicAdd(&C[(size_t)r0 * 2 + 1], p01);
                }
                if (r1 < M) {
                    atomicAdd(&C[(size_t)r1 * 2 + 0], p10);
                    atomicAdd(&C[(size_t)r1 * 2 + 1], p11);
                }
            }
        }
    }
#undef LOADCHUNK
}

// ---------------- BN2 ----------------
__global__ void __launch_bounds__(256) k_bn2pre(const float* __restrict__ b2b) {
    __shared__ float red[8][4];
    int t = threadIdx.x;
    int lane = t & 31, wid = t >> 5;
    int r = blockIdx.x * 256 + t;
    float s0 = 0.f, s1 = 0.f, q0 = 0.f, q1 = 0.f;
    if (r < N_NODES) {
        float2 v = ((float2*)g_out2)[r];
        v.x = fmaxf(v.x + b2b[0], 0.f);
        v.y = fmaxf(v.y + b2b[1], 0.f);
        ((float2*)g_out2)[r] = v;
        s0 = v.x; s1 = v.y; q0 = v.x * v.x; q1 = v.y * v.y;
    }
#pragma unroll
    for (int off = 16; off; off >>= 1) {
        s0 += __shfl_xor_sync(0xffffffffu, s0, off);
        s1 += __shfl_xor_sync(0xffffffffu, s1, off);
        q0 += __shfl_xor_sync(0xffffffffu, q0, off);
        q1 += __shfl_xor_sync(0xffffffffu, q1, off);
    }
    if (lane == 0) { red[wid][0] = s0; red[wid][1] = s1; red[wid][2] = q0; red[wid][3] = q1; }
    __syncthreads();
    if (t < 4) {
        float acc = 0.f;
#pragma unroll
        for (int wI = 0; wI < 8; wI++) acc += red[wI][t];
        atomicAdd(&g_bn2[t], acc);
    }
}

__global__ void __launch_bounds__(256) k_bn2norm(const float* __restrict__ gamma2,
                                                 const float* __restrict__ beta2,
                                                 float* __restrict__ out) {
    __shared__ float ss[4];
    int t = threadIdx.x;
    if (t < 2) {
        const float invN = 1.0f / (float)N_NODES;
        float mean = g_bn2[t] * invN;
        float var  = g_bn2[2 + t] * invN - mean * mean;
        float sc   = gamma2[t] * rsqrtf(var + BN_EPS);
        ss[t]     = sc;
        ss[2 + t] = beta2[t] - mean * sc;
    }
    __syncthreads();
    int r = blockIdx.x * blockDim.x + t;
    if (r >= N_NODES) return;
    float2 v = ((const float2*)g_out2)[r];
    float2 o;
    o.x = fmaf(v.x, ss[0], ss[2]);
    o.y = fmaf(v.y, ss[1], ss[3]);
    ((float2*)out)[r] = o;
}

// ---------------- launch ----------------
extern "C" void kernel_launch(void* const* d_in, const int* in_sizes, int n_in,
                              void* d_out, int out_size) {
    const float* x      = (const float*)d_in[0];
    const int*   eidx   = (const int*)d_in[1];
    const float* ew     = (const float*)d_in[3];
    const float* W1a    = (const float*)d_in[4];
    const float* b1a    = (const float*)d_in[5];
    const float* W1b    = (const float*)d_in[6];
    const float* b1b    = (const float*)d_in[7];
    const float* gamma1 = (const float*)d_in[8];
    const float* beta1  = (const float*)d_in[9];
    const float* W2a    = (const float*)d_in[10];
    const float* b2a    = (const float*)d_in[11];
    const float* W2b    = (const float*)d_in[12];
    const float* b2b    = (const float*)d_in[13];
    const float* gamma2 = (const float*)d_in[14];
    const float* beta2  = (const float*)d_in[15];

    const int nEdges = in_sizes[1] / 2;
    const int* src = eidx;
    const int* dst = eidx + nEdges;
    const int nE8 = nEdges / 8;

    float *pre, *out2;
    __half *xh, *preh, *A2h, *A3, *B2a, *B2b, *B2c;
    cudaGetSymbolAddress((void**)&pre,  g_pre);
    cudaGetSymbolAddress((void**)&out2, g_out2);
    cudaGetSymbolAddress((void**)&xh,   g_xh);
    cudaGetSymbolAddress((void**)&preh, g_preh);
    cudaGetSymbolAddress((void**)&A2h,  g_A2h);
    cudaGetSymbolAddress((void**)&A3,   g_A3);
    cudaGetSymbolAddress((void**)&B2a,  g_B2a);
    cudaGetSymbolAddress((void**)&B2b,  g_B2b);
    cudaGetSymbolAddress((void**)&B2c,  g_B2c);

    cudaFuncSetAttribute(k_mma<0>, cudaFuncAttributeMaxDynamicSharedMemorySize, 65536);
    cudaFuncSetAttribute(k_mma<1>, cudaFuncAttributeMaxDynamicSharedMemorySize, 98304);
    cudaFuncSetAttribute(k_mma<2>, cudaFuncAttributeMaxDynamicSharedMemorySize, 98304);

    const int gatherBlocks = (MPAD * 32 + 255) / 256;
    const int histconvItems = (nE8 + 1) + CONVX_N + 3 * DIM * HID2;

    // ---- setup + CSR build ----
    k_zero<<<(N_NODES + 255) / 256, 256>>>();
    k_histconv<<<(histconvItems + 255) / 256, 256>>>(dst, nE8, nEdges, x, W1a, W1b, W2a);
    k_scan<<<1, 1024>>>();
    k_fill<<<(nEdges + 255) / 256, 256>>>(src, dst, ew, nEdges);

    // ---- layer 1 ----
    k_gather<false><<<gatherBlocks, 256>>>(x, xh, nullptr, nullptr);
    {
        dim3 g(MTILES, 2);   // mma1 (2-term): relu(A2h@W1a + b1a) -> A3 (split-fp16)
        k_mma<1><<<g, 256, 98304>>>(A2h, B2a, b1a, (float*)A3, nullptr, N_NODES, HID2, DIM);
    }
    {
        dim3 g(MTILES, 1);   // mma2 (3-term): relu(A3@W1b + b1b) -> pre fp32 + preh fp16 + BN1 stats
        k_mma<0><<<g, 256, 65536>>>(A3, B2b, b1b, pre, nullptr, N_NODES, DIM, HID2);
    }

    // ---- layer 2 ----
    k_gather<true><<<gatherBlocks, 256>>>(pre, preh, gamma1, beta1);  // BN1 finalize+affine folded
    {
        dim3 g(MTILES, 2);   // mma3 (2-term): fused gemv -> out2 partials
        k_mma<2><<<g, 256, 98304>>>(A2h, B2c, b2a, out2, W2b, N_NODES, HID2, DIM);
    }
    k_bn2pre<<<(N_NODES + 255) / 256, 256>>>(b2b);
    k_bn2norm<<<(N_NODES + 255) / 256, 256>>>(gamma2, beta2, (float*)d_out);
}